// round 11
// baseline (speedup 1.0000x reference)
#include <cuda_runtime.h>
#include <cuda_bf16.h>
#include <math.h>
#include <cstdint>

// Problem constants
#define Bsz   2
#define Sseq  2048
#define Dmod  2048
#define Hh    16
#define DKk   128
#define Ll    64
#define Mrows (Bsz * Sseq)   // 4096

// ---------------------------------------------------------------------------
// Device scratch
// ---------------------------------------------------------------------------
__device__ float    g_Q   [(size_t)Mrows * Dmod];
__device__ uint32_t g_Xhi [(size_t)3 * Mrows * 1024];  // split activations q/k/v
__device__ uint32_t g_Xlo [(size_t)3 * Mrows * 1024];
__device__ uint32_t g_Ohi [(size_t)Mrows * 1024];      // FA output planes
__device__ uint32_t g_Olo [(size_t)Mrows * 1024];
__device__ uint32_t g_Khi[(size_t)Mrows * 1024];       // [b,h,s][64 words]
__device__ uint32_t g_Klo[(size_t)Mrows * 1024];
__device__ uint32_t g_Vhi[(size_t)Mrows * 1024];       // [b,h,d][1024 words]
__device__ uint32_t g_Vlo[(size_t)Mrows * 1024];
__device__ uint32_t g_WqThi[(size_t)Dmod * 1024];
__device__ uint32_t g_WqTlo[(size_t)Dmod * 1024];
__device__ uint32_t g_WkThi[(size_t)Dmod * 1024];
__device__ uint32_t g_WkTlo[(size_t)Dmod * 1024];
__device__ uint32_t g_WvThi[(size_t)Dmod * 1024];
__device__ uint32_t g_WvTlo[(size_t)Dmod * 1024];
__device__ uint32_t g_WoThi[(size_t)Dmod * 1024];
__device__ uint32_t g_WoTlo[(size_t)Dmod * 1024];
__device__ float    g_bk[Dmod];
__device__ float    g_bv[Dmod];

// ---------------------------------------------------------------------------
// Helpers
// ---------------------------------------------------------------------------
__device__ __forceinline__ uint32_t smem_u32(const void* p) {
    uint32_t a;
    asm("{ .reg .u64 t; cvta.to.shared.u64 t, %1; cvt.u32.u64 %0, t; }"
        : "=r"(a) : "l"(p));
    return a;
}

#define CP_ASYNC16(dst, src) \
    asm volatile("cp.async.cg.shared.global [%0], [%1], 16;" \
        :: "r"((uint32_t)(dst)), "l"(src) : "memory")
#define CP_COMMIT() asm volatile("cp.async.commit_group;" ::: "memory")
#define CP_WAIT(n)  asm volatile("cp.async.wait_group %0;" :: "n"(n) : "memory")

__device__ __forceinline__ void mma_bf16(float* c, const uint32_t* a,
                                         uint32_t b0, uint32_t b1) {
    asm volatile(
        "mma.sync.aligned.m16n8k16.row.col.f32.bf16.bf16.f32 "
        "{%0,%1,%2,%3}, {%4,%5,%6,%7}, {%8,%9}, {%0,%1,%2,%3};"
        : "+f"(c[0]), "+f"(c[1]), "+f"(c[2]), "+f"(c[3])
        : "r"(a[0]), "r"(a[1]), "r"(a[2]), "r"(a[3]), "r"(b0), "r"(b1));
}

__device__ __forceinline__ uint32_t packbf(float e0, float e1) {
    uint32_t r;
    asm("cvt.rn.bf16x2.f32 %0, %1, %2;" : "=r"(r) : "f"(e1), "f"(e0));
    return r;
}

__device__ __forceinline__ void split2(float e0, float e1,
                                       uint32_t& hi, uint32_t& lo) {
    hi = packbf(e0, e1);
    float r0 = e0 - __uint_as_float(hi << 16);
    float r1 = e1 - __uint_as_float(hi & 0xFFFF0000u);
    lo = packbf(r0, r1);
}

__device__ __forceinline__ float ex2(float x) {
    float y;
    asm("ex2.approx.ftz.f32 %0, %1;" : "=f"(y) : "f"(x));
    return y;
}

// ---------------------------------------------------------------------------
// Split activations into bf16 hi/lo word planes with pair permutation.
// Word-group perm: phys order {w0,w4,w1,w5,w2,w6,w3,w7} so fragment word
// pairs (t4, t4+4) are adjacent -> uint2 loads (FA's proven convention).
// Each thread handles one 8-word group (16 elements). grid.z = input select.
// ---------------------------------------------------------------------------
__global__ __launch_bounds__(256) void split_act_kernel(
    const float* __restrict__ in0, const float* __restrict__ in1,
    const float* __restrict__ in2,
    uint32_t* __restrict__ hi_out, uint32_t* __restrict__ lo_out)
{
    const int z = blockIdx.z;
    const float* in = (z == 0) ? in0 : (z == 1) ? in1 : in2;
    uint32_t* Oh = hi_out + (size_t)z * Mrows * 1024;
    uint32_t* Ol = lo_out + (size_t)z * Mrows * 1024;

    const size_t idx = (size_t)blockIdx.x * 256 + threadIdx.x;
    const size_t ebase = idx * 16;
    const float4 a = *(const float4*)(in + ebase);
    const float4 b = *(const float4*)(in + ebase + 4);
    const float4 c = *(const float4*)(in + ebase + 8);
    const float4 d = *(const float4*)(in + ebase + 12);

    uint32_t h[8], l[8];
    split2(a.x, a.y, h[0], l[0]);
    split2(a.z, a.w, h[1], l[1]);
    split2(b.x, b.y, h[2], l[2]);
    split2(b.z, b.w, h[3], l[3]);
    split2(c.x, c.y, h[4], l[4]);
    split2(c.z, c.w, h[5], l[5]);
    split2(d.x, d.y, h[6], l[6]);
    split2(d.z, d.w, h[7], l[7]);

    const size_t wbase = idx * 8;
    *(uint4*)(Oh + wbase)     = make_uint4(h[0], h[4], h[1], h[5]);
    *(uint4*)(Oh + wbase + 4) = make_uint4(h[2], h[6], h[3], h[7]);
    *(uint4*)(Ol + wbase)     = make_uint4(l[0], l[4], l[1], l[5]);
    *(uint4*)(Ol + wbase + 4) = make_uint4(l[2], l[6], l[3], l[7]);
}

// ---------------------------------------------------------------------------
// Fused fold + transpose -> bf16 hi/lo planes (merged z over K/V weights):
// WT[h*128+c][k-words of d], pair-permuted.
// ---------------------------------------------------------------------------
#define FT_SMEM_BYTES ((64 * 132 + 64 * 128) * 4)

__global__ __launch_bounds__(256) void foldT_kernel(
    const float* __restrict__ Wl0, const float* __restrict__ Wr0,
    uint32_t* __restrict__ WThi0, uint32_t* __restrict__ WTlo0,
    const float* __restrict__ Wl1, const float* __restrict__ Wr1,
    uint32_t* __restrict__ WThi1, uint32_t* __restrict__ WTlo1)
{
    const float* Wl = blockIdx.z ? Wl1 : Wl0;
    const float* Wr = blockIdx.z ? Wr1 : Wr0;
    uint32_t* WThi = blockIdx.z ? WThi1 : WThi0;
    uint32_t* WTlo = blockIdx.z ? WTlo1 : WTlo0;

    extern __shared__ float fsm[];
    float* sWl = fsm;             // [l][132]
    float* sWr = fsm + 64 * 132;  // [l][128]

    const int dblk = blockIdx.x;
    const int h    = blockIdx.y;
    const int t    = threadIdx.x;

    #pragma unroll
    for (int i = 0; i < 8; i++) {
        int u = t + i * 256;
        int l = u >> 5, c4 = u & 31;
        *(float4*)&sWr[l * 128 + c4 * 4] = *(const float4*)(Wr + l * DKk + c4 * 4);
    }
    #pragma unroll
    for (int i = 0; i < 8; i++) {
        int u = t + i * 256;
        int d = u >> 4, l4 = u & 15;
        float4 x = *(const float4*)(Wl + (size_t)(dblk * 128 + d) * (Hh * Ll)
                                    + h * Ll + l4 * 4);
        sWl[(l4 * 4 + 0) * 132 + d] = x.x;
        sWl[(l4 * 4 + 1) * 132 + d] = x.y;
        sWl[(l4 * 4 + 2) * 132 + d] = x.z;
        sWl[(l4 * 4 + 3) * 132 + d] = x.w;
    }
    __syncthreads();

    const int d8 = (t & 15) * 8;
    const int cg = t >> 4;
    float acc[8][8];
    #pragma unroll
    for (int dd = 0; dd < 8; dd++)
        #pragma unroll
        for (int j = 0; j < 8; j++) acc[dd][j] = 0.f;

    for (int l = 0; l < Ll; l++) {
        float4 a0 = *(float4*)&sWl[l * 132 + d8];
        float4 a1 = *(float4*)&sWl[l * 132 + d8 + 4];
        const float* wr = &sWr[l * 128 + cg * 8];
        #pragma unroll
        for (int j = 0; j < 8; j++) {
            float wv = wr[j];
            acc[0][j] += a0.x * wv;
            acc[1][j] += a0.y * wv;
            acc[2][j] += a0.z * wv;
            acc[3][j] += a0.w * wv;
            acc[4][j] += a1.x * wv;
            acc[5][j] += a1.y * wv;
            acc[6][j] += a1.z * wv;
            acc[7][j] += a1.w * wv;
        }
    }

    // store word pairs, pair-permuted: phys = wb + 2*i + (t&1)
    const int wb  = dblk * 64 + ((d8 >> 1) & ~7);
    const int off = t & 1;
    #pragma unroll
    for (int j = 0; j < 8; j++) {
        const int n = h * 128 + cg * 8 + j;
        #pragma unroll
        for (int i2 = 0; i2 < 4; i2++) {
            uint32_t hi, lo;
            split2(acc[2 * i2][j], acc[2 * i2 + 1][j], hi, lo);
            WThi[(size_t)n * 1024 + wb + 2 * i2 + off] = hi;
            WTlo[(size_t)n * 1024 + wb + 2 * i2 + off] = lo;
        }
    }
}

__global__ __launch_bounds__(128) void fold_b_kernel(
    const float* __restrict__ bl0, const float* __restrict__ Wr0,
    const float* __restrict__ br0, float* __restrict__ be0,
    const float* __restrict__ bl1, const float* __restrict__ Wr1,
    const float* __restrict__ br1, float* __restrict__ be1)
{
    const float* bl = blockIdx.y ? bl1 : bl0;
    const float* Wr = blockIdx.y ? Wr1 : Wr0;
    const float* br = blockIdx.y ? br1 : br0;
    float* beff = blockIdx.y ? be1 : be0;
    const int h = blockIdx.x;
    const int c = threadIdx.x;
    float acc = br[c];
    #pragma unroll 16
    for (int l = 0; l < Ll; l++)
        acc += bl[h * Ll + l] * Wr[l * DKk + c];
    beff[h * DKk + c] = acc;
}

// ---------------------------------------------------------------------------
// 32x32 tiled transpose -> bf16 hi/lo planes (merged z over Wq/Wo)
// ---------------------------------------------------------------------------
__global__ __launch_bounds__(256) void transposeW_kernel(
    const float* __restrict__ in0,
    uint32_t* __restrict__ hi0, uint32_t* __restrict__ lo0,
    const float* __restrict__ in1,
    uint32_t* __restrict__ hi1, uint32_t* __restrict__ lo1)
{
    const float* in = blockIdx.z ? in1 : in0;
    uint32_t* Oh = blockIdx.z ? hi1 : hi0;
    uint32_t* Ol = blockIdx.z ? lo1 : lo0;
    __shared__ float tile[32][33];
    const int bx = blockIdx.x * 32;   // n block (output rows)
    const int by = blockIdx.y * 32;   // k block (output words)
    const int tx = threadIdx.x & 31;
    const int ty = threadIdx.x >> 5;
    #pragma unroll
    for (int i = 0; i < 32; i += 8)
        tile[ty + i][tx] = in[(size_t)(by + ty + i) * Dmod + bx + tx];
    __syncthreads();

    // tile[d_off][n_off]; thread: c = n_off, u..u+8 word indices
    const int c = tx;
    const int u = ty;   // 0..7
    #pragma unroll
    for (int ii = 0; ii < 2; ii++) {
        const int uf = u + 8 * ii;          // 0..15 word within 32-elem block
        const int r  = uf & 7;
        const int phys = (by >> 1) + (uf & 8) + (((r & 3) << 1) | (r >> 2));
        uint32_t hi, lo;
        split2(tile[2 * uf][c], tile[2 * uf + 1][c], hi, lo);
        Oh[(size_t)(bx + c) * 1024 + phys] = hi;
        Ol[(size_t)(bx + c) * 1024 + phys] = lo;
    }
}

// ---------------------------------------------------------------------------
// bf16 hi/lo x3 tensor-core GEMM body: C = A @ WT^T + bias.
// All operands pre-split bf16 word planes (pair-permuted).
// CTA 128x128, BK=32 (2 x k16), 2-stage cp.async, 256 thr, occupancy 2.
// smem/stage: 4 planes x 128 rows x 20 words = 40KB; 2 stages = 80KB.
// MODE 0: fp32 out. MODE 1: K split planes. MODE 2: V split planes transposed.
// ---------------------------------------------------------------------------
#define G_BK 32
#define G_NK (Dmod / G_BK)            // 64
#define G_ST 20                       // words per row per plane
#define G_PLANE_WORDS (128 * G_ST)    // 2560
#define G_STAGE_WORDS (4 * G_PLANE_WORDS)  // 10240
#define G_SMEM_BYTES (2 * G_STAGE_WORDS * 4)  // 81920

template<int MODE>
__device__ __forceinline__ void gemm_body(
    uint32_t* smw, uint32_t smem_base,
    const uint32_t* __restrict__ AhiG, const uint32_t* __restrict__ AloG,
    const uint32_t* __restrict__ WhiG, const uint32_t* __restrict__ WloG,
    const float* __restrict__ bias, float* __restrict__ C,
    uint32_t* __restrict__ Chi, uint32_t* __restrict__ Clo,
    int m0, int n0)
{
    const int t    = threadIdx.x;
    const int wid  = t >> 5;
    const int lane = t & 31;
    const int g    = lane >> 2;
    const int tid4 = lane & 3;
    const int wm   = wid >> 2;
    const int wn   = wid & 3;

    float acc[4][4][4];
    #pragma unroll
    for (int mf = 0; mf < 4; mf++)
        #pragma unroll
        for (int nf = 0; nf < 4; nf++)
            #pragma unroll
            for (int r = 0; r < 4; r++) acc[mf][nf][r] = 0.f;

    auto load_stage = [&](int s, int k0) {
        const uint32_t base = smem_base + (uint32_t)s * G_STAGE_WORDS * 4;
        const int w0 = k0 >> 1;   // global word offset
        #pragma unroll
        for (int i = 0; i < 2; i++) {
            int u = t + i * 256;
            int row = u >> 2, c4 = u & 3;
            uint32_t doff = (uint32_t)(row * G_ST + c4 * 4) * 4;
            size_t asrc = (size_t)(m0 + row) * 1024 + w0 + c4 * 4;
            size_t bsrc = (size_t)(n0 + row) * 1024 + w0 + c4 * 4;
            CP_ASYNC16(base + doff,                          AhiG + asrc);
            CP_ASYNC16(base + G_PLANE_WORDS * 4 + doff,      AloG + asrc);
            CP_ASYNC16(base + 2 * G_PLANE_WORDS * 4 + doff,  WhiG + bsrc);
            CP_ASYNC16(base + 3 * G_PLANE_WORDS * 4 + doff,  WloG + bsrc);
        }
    };

    load_stage(0, 0);
    CP_COMMIT();
    load_stage(1, G_BK);
    CP_COMMIT();

    for (int k = 0; k < G_NK; k++) {
        const int s = k & 1;
        CP_WAIT(1);
        __syncthreads();

        const uint32_t* Ah = smw + (size_t)s * G_STAGE_WORDS;
        const uint32_t* Al = Ah + G_PLANE_WORDS;
        const uint32_t* Bh = Al + G_PLANE_WORDS;
        const uint32_t* Bl = Bh + G_PLANE_WORDS;

        #pragma unroll
        for (int ks = 0; ks < 2; ks++) {
            const int wk = 8 * ks + 2 * tid4;
            uint2 bh[4], bl[4];
            #pragma unroll
            for (int nf = 0; nf < 4; nf++) {
                const int rr = (wn * 32 + nf * 8 + g) * G_ST + wk;
                bh[nf] = *(const uint2*)&Bh[rr];
                bl[nf] = *(const uint2*)&Bl[rr];
            }
            #pragma unroll
            for (int mf = 0; mf < 4; mf++) {
                const int ra = (wm * 64 + mf * 16 + g) * G_ST + wk;
                const int rb = ra + 8 * G_ST;
                uint2 hg  = *(const uint2*)&Ah[ra];
                uint2 hg8 = *(const uint2*)&Ah[rb];
                uint2 lg  = *(const uint2*)&Al[ra];
                uint2 lg8 = *(const uint2*)&Al[rb];
                uint32_t ahi[4] = {hg.x, hg8.x, hg.y, hg8.y};
                uint32_t alo[4] = {lg.x, lg8.x, lg.y, lg8.y};
                #pragma unroll
                for (int nf = 0; nf < 4; nf++) {
                    mma_bf16(acc[mf][nf], ahi, bh[nf].x, bh[nf].y);
                    mma_bf16(acc[mf][nf], ahi, bl[nf].x, bl[nf].y);
                    mma_bf16(acc[mf][nf], alo, bh[nf].x, bh[nf].y);
                }
            }
        }

        __syncthreads();
        if (k + 2 < G_NK) load_stage(s, (k + 2) * G_BK);
        CP_COMMIT();
    }

    #pragma unroll
    for (int mf = 0; mf < 4; mf++) {
        const int r0 = m0 + wm * 64 + mf * 16 + g;
        #pragma unroll
        for (int nf = 0; nf < 4; nf++) {
            const int c0 = n0 + wn * 32 + nf * 8 + 2 * tid4;
            const float b0 = bias[c0], b1 = bias[c0 + 1];
            float v0 = acc[mf][nf][0] + b0, v1 = acc[mf][nf][1] + b1;
            float v2 = acc[mf][nf][2] + b0, v3 = acc[mf][nf][3] + b1;
            if (MODE == 0) {
                *(float2*)(C + (size_t)r0 * Dmod + c0)       = make_float2(v0, v1);
                *(float2*)(C + (size_t)(r0 + 8) * Dmod + c0) = make_float2(v2, v3);
            } else if (MODE == 1) {
                const int bb = r0 >> 11, s2 = r0 & 2047, hh = c0 >> 7;
                const int j = (c0 & 127) >> 1;
                const int p = (j & ~7) | (2 * tid4 + (nf & 1));
                const size_t base = ((size_t)(bb * Hh + hh) * Sseq + s2) * 64 + p;
                uint32_t hi, lo;
                split2(v0, v1, hi, lo);
                Chi[base] = hi; Clo[base] = lo;
                split2(v2, v3, hi, lo);
                Chi[base + 512] = hi; Clo[base + 512] = lo;
            } else {
                float u0 = __shfl_xor_sync(0xFFFFFFFFu, v0, 4);
                float u1 = __shfl_xor_sync(0xFFFFFFFFu, v1, 4);
                float u2 = __shfl_xor_sync(0xFFFFFFFFu, v2, 4);
                float u3 = __shfl_xor_sync(0xFFFFFFFFu, v3, 4);
                if ((g & 1) == 0) {
                    const int bb = r0 >> 11, s2 = r0 & 2047, hh = c0 >> 7;
                    const int d = c0 & 127;
                    const size_t base0 =
                        ((size_t)(bb * Hh + hh) * DKk + d) * 1024 + ((s2 & ~15) >> 1);
                    uint32_t hi, lo;
                    split2(v0, u0, hi, lo);
                    Chi[base0 + g] = hi;            Clo[base0 + g] = lo;
                    split2(v2, u2, hi, lo);
                    Chi[base0 + g + 1] = hi;        Clo[base0 + g + 1] = lo;
                    split2(v1, u1, hi, lo);
                    Chi[base0 + 1024 + g] = hi;     Clo[base0 + 1024 + g] = lo;
                    split2(v3, u3, hi, lo);
                    Chi[base0 + 1024 + g + 1] = hi; Clo[base0 + 1024 + g + 1] = lo;
                }
            }
        }
    }
}

// Merged Q/K/V projection (grid.z selects input/weight/epilogue)
__global__ __launch_bounds__(256, 2) void qkv_gemm_kernel(
    const uint32_t* __restrict__ Xhi, const uint32_t* __restrict__ Xlo,
    const uint32_t* __restrict__ WqThi, const uint32_t* __restrict__ WqTlo,
    const uint32_t* __restrict__ WkThi, const uint32_t* __restrict__ WkTlo,
    const uint32_t* __restrict__ WvThi, const uint32_t* __restrict__ WvTlo,
    const float* __restrict__ bq, const float* __restrict__ bk,
    const float* __restrict__ bv,
    float* __restrict__ Q,
    uint32_t* __restrict__ Khi, uint32_t* __restrict__ Klo,
    uint32_t* __restrict__ Vhi, uint32_t* __restrict__ Vlo)
{
    extern __shared__ uint32_t smw[];
    const uint32_t smem_base = smem_u32(smw);
    const int m0 = blockIdx.y * 128;
    const int n0 = blockIdx.x * 128;
    const int z = blockIdx.z;
    const uint32_t* Ah = Xhi + (size_t)z * Mrows * 1024;
    const uint32_t* Al = Xlo + (size_t)z * Mrows * 1024;
    if (z == 0)
        gemm_body<0>(smw, smem_base, Ah, Al, WqThi, WqTlo, bq, Q,
                     nullptr, nullptr, m0, n0);
    else if (z == 1)
        gemm_body<1>(smw, smem_base, Ah, Al, WkThi, WkTlo, bk, nullptr,
                     Khi, Klo, m0, n0);
    else
        gemm_body<2>(smw, smem_base, Ah, Al, WvThi, WvTlo, bv, nullptr,
                     Vhi, Vlo, m0, n0);
}

__global__ __launch_bounds__(256, 2) void o_gemm_kernel(
    const uint32_t* __restrict__ Ahi, const uint32_t* __restrict__ Alo,
    const uint32_t* __restrict__ WThi, const uint32_t* __restrict__ WTlo,
    const float* __restrict__ bias, float* __restrict__ C)
{
    extern __shared__ uint32_t smw[];
    const uint32_t smem_base = smem_u32(smw);
    gemm_body<0>(smw, smem_base, Ahi, Alo, WThi, WTlo, bias, C,
                 nullptr, nullptr, blockIdx.y * 128, blockIdx.x * 128);
}

// ---------------------------------------------------------------------------
// Tensor-core causal FA (mainloop unchanged; epilogue writes split O planes)
// ---------------------------------------------------------------------------
#define KROWW 72
#define VROWW 40
#define FA_STAGE_WORDS (2 * 64 * KROWW + 2 * 128 * VROWW)
#define FA_SMEM_BYTES (2 * FA_STAGE_WORDS * 4)

__global__ __launch_bounds__(256, 1) void fa_tc_kernel(
    const float* __restrict__ Q,
    const uint32_t* __restrict__ KhiG, const uint32_t* __restrict__ KloG,
    const uint32_t* __restrict__ VhiG, const uint32_t* __restrict__ VloG,
    uint32_t* __restrict__ OhiG, uint32_t* __restrict__ OloG)
{
    extern __shared__ uint32_t su[];
    const uint32_t smem_base = smem_u32(su);

    const int qb = (int)gridDim.x - 1 - (int)blockIdx.x;
    const int h  = blockIdx.y;
    const int b  = blockIdx.z;
    const int t  = threadIdx.x;
    const int w  = t >> 5;
    const int lane = t & 31;
    const int g  = lane >> 2;
    const int t4 = lane & 3;
    const int q0 = qb * 128;

    const size_t bh_off = (size_t)b * Sseq * Dmod + (size_t)h * DKk;
    const size_t bhS = (size_t)(b * Hh + h) * Sseq;
    const size_t bhD = (size_t)(b * Hh + h) * DKk;

    const float qscale = 0.088388347648318447f * 1.4426950408889634f;
    uint32_t qhi[8][4], qlo[8][4];
    {
        const float* Qw = Q + bh_off + (size_t)(q0 + w * 16) * Dmod;
        #pragma unroll
        for (int ks = 0; ks < 8; ks++) {
            const int d0 = ks * 16 + 2 * t4;
            float2 x0 = *(const float2*)(Qw + (size_t)g * Dmod + d0);
            float2 x1 = *(const float2*)(Qw + (size_t)(g + 8) * Dmod + d0);
            float2 x2 = *(const float2*)(Qw + (size_t)g * Dmod + d0 + 8);
            float2 x3 = *(const float2*)(Qw + (size_t)(g + 8) * Dmod + d0 + 8);
            split2(x0.x * qscale, x0.y * qscale, qhi[ks][0], qlo[ks][0]);
            split2(x1.x * qscale, x1.y * qscale, qhi[ks][1], qlo[ks][1]);
            split2(x2.x * qscale, x2.y * qscale, qhi[ks][2], qlo[ks][2]);
            split2(x3.x * qscale, x3.y * qscale, qhi[ks][3], qlo[ks][3]);
        }
    }

    auto load_tile = [&](int stage, int kt) {
        const int kv0 = kt * 64;
        const uint32_t sb = smem_base + (uint32_t)stage * FA_STAGE_WORDS * 4;
        const uint32_t kh = sb;
        const uint32_t kl = sb + 64 * KROWW * 4;
        const uint32_t vh = sb + 2 * 64 * KROWW * 4;
        const uint32_t vl = vh + 128 * VROWW * 4;
        #pragma unroll
        for (int i = 0; i < 4; i++) {
            int u = t + i * 256;
            int row = u >> 4, w4 = (u & 15) * 4;
            size_t src = (bhS + kv0 + row) * 64 + w4;
            uint32_t doff = (uint32_t)(row * KROWW + w4) * 4;
            CP_ASYNC16(kh + doff, KhiG + src);
            CP_ASYNC16(kl + doff, KloG + src);
        }
        #pragma unroll
        for (int i = 0; i < 4; i++) {
            int u = t + i * 256;
            int row = u >> 3, w4 = (u & 7) * 4;
            size_t src = (bhD + row) * 1024 + (kv0 >> 1) + w4;
            uint32_t doff = (uint32_t)(row * VROWW + w4) * 4;
            CP_ASYNC16(vh + doff, VhiG + src);
            CP_ASYNC16(vl + doff, VloG + src);
        }
    };

    float oacc[16][4];
    #pragma unroll
    for (int nf = 0; nf < 16; nf++)
        #pragma unroll
        for (int r = 0; r < 4; r++) oacc[nf][r] = 0.f;

    float m0 = -1e30f, m1 = -1e30f, l0 = 0.f, l1 = 0.f;
    const int row0 = q0 + w * 16 + g;
    const int row1 = row0 + 8;

    const int ntiles = 2 * qb + 2;
    load_tile(0, 0);
    CP_COMMIT();

    for (int kt = 0; kt < ntiles; kt++) {
        const int st = kt & 1;
        const int kv0 = kt * 64;
        if (kt + 1 < ntiles) {
            load_tile(st ^ 1, kt + 1);
            CP_COMMIT();
            CP_WAIT(1);
        } else {
            CP_WAIT(0);
        }
        __syncthreads();

        const uint32_t* Khi = su + (size_t)st * FA_STAGE_WORDS;
        const uint32_t* Klo = Khi + 64 * KROWW;
        const uint32_t* Vhi = Khi + 2 * 64 * KROWW;
        const uint32_t* Vlo = Vhi + 128 * VROWW;

        float acc[8][4];
        #pragma unroll
        for (int nf = 0; nf < 8; nf++)
            #pragma unroll
            for (int r = 0; r < 4; r++) acc[nf][r] = 0.f;

        #pragma unroll
        for (int ks = 0; ks < 8; ks++) {
            #pragma unroll
            for (int nf = 0; nf < 8; nf++) {
                const int r = (nf * 8 + g) * KROWW + 8 * ks + 2 * t4;
                uint2 bh = *(const uint2*)&Khi[r];
                uint2 bl = *(const uint2*)&Klo[r];
                mma_bf16(acc[nf], qhi[ks], bh.x, bh.y);
                mma_bf16(acc[nf], qhi[ks], bl.x, bl.y);
                mma_bf16(acc[nf], qlo[ks], bh.x, bh.y);
            }
        }

        if (kv0 + 63 > q0) {
            #pragma unroll
            for (int nf = 0; nf < 8; nf++) {
                const int c = kv0 + nf * 8 + 2 * t4;
                if (c     > row0) acc[nf][0] = -1e30f;
                if (c + 1 > row0) acc[nf][1] = -1e30f;
                if (c     > row1) acc[nf][2] = -1e30f;
                if (c + 1 > row1) acc[nf][3] = -1e30f;
            }
        }

        float mx0 = -1e30f, mx1 = -1e30f;
        #pragma unroll
        for (int nf = 0; nf < 8; nf++) {
            mx0 = fmaxf(mx0, fmaxf(acc[nf][0], acc[nf][1]));
            mx1 = fmaxf(mx1, fmaxf(acc[nf][2], acc[nf][3]));
        }
        mx0 = fmaxf(mx0, __shfl_xor_sync(0xFFFFFFFFu, mx0, 1));
        mx0 = fmaxf(mx0, __shfl_xor_sync(0xFFFFFFFFu, mx0, 2));
        mx1 = fmaxf(mx1, __shfl_xor_sync(0xFFFFFFFFu, mx1, 1));
        mx1 = fmaxf(mx1, __shfl_xor_sync(0xFFFFFFFFu, mx1, 2));

        const float mn0 = fmaxf(m0, mx0);
        const float mn1 = fmaxf(m1, mx1);
        const float cr0 = ex2(m0 - mn0);
        const float cr1 = ex2(m1 - mn1);

        float ps0 = 0.f, ps1 = 0.f;
        #pragma unroll
        for (int nf = 0; nf < 8; nf++) {
            acc[nf][0] = ex2(acc[nf][0] - mn0);
            acc[nf][1] = ex2(acc[nf][1] - mn0);
            acc[nf][2] = ex2(acc[nf][2] - mn1);
            acc[nf][3] = ex2(acc[nf][3] - mn1);
            ps0 += acc[nf][0] + acc[nf][1];
            ps1 += acc[nf][2] + acc[nf][3];
        }
        ps0 += __shfl_xor_sync(0xFFFFFFFFu, ps0, 1);
        ps0 += __shfl_xor_sync(0xFFFFFFFFu, ps0, 2);
        ps1 += __shfl_xor_sync(0xFFFFFFFFu, ps1, 1);
        ps1 += __shfl_xor_sync(0xFFFFFFFFu, ps1, 2);

        l0 = l0 * cr0 + ps0;
        l1 = l1 * cr1 + ps1;
        m0 = mn0;
        m1 = mn1;

        #pragma unroll
        for (int nf = 0; nf < 16; nf++) {
            oacc[nf][0] *= cr0;
            oacc[nf][1] *= cr0;
            oacc[nf][2] *= cr1;
            oacc[nf][3] *= cr1;
        }

        #pragma unroll
        for (int ks2 = 0; ks2 < 4; ks2++) {
            uint32_t ahi[4], alo[4];
            split2(acc[2 * ks2][0],     acc[2 * ks2][1],     ahi[0], alo[0]);
            split2(acc[2 * ks2][2],     acc[2 * ks2][3],     ahi[1], alo[1]);
            split2(acc[2 * ks2 + 1][0], acc[2 * ks2 + 1][1], ahi[2], alo[2]);
            split2(acc[2 * ks2 + 1][2], acc[2 * ks2 + 1][3], ahi[3], alo[3]);
            #pragma unroll
            for (int nf = 0; nf < 16; nf++) {
                const int r = (nf * 8 + g) * VROWW + 8 * ks2 + 2 * t4;
                uint2 bh = *(const uint2*)&Vhi[r];
                uint2 bl = *(const uint2*)&Vlo[r];
                mma_bf16(oacc[nf], ahi, bh.x, bh.y);
                mma_bf16(oacc[nf], ahi, bl.x, bl.y);
                mma_bf16(oacc[nf], alo, bh.x, bh.y);
            }
        }
        __syncthreads();
    }

    // epilogue: normalize, split into bf16 hi/lo planes (pair-permuted words)
    const float inv0 = 1.0f / l0;
    const float inv1 = 1.0f / l1;
    const size_t rowg  = (size_t)(b * Sseq + q0 + w * 16 + g) * 1024 + h * 64;
    const size_t rowg8 = rowg + 8 * 1024;
    #pragma unroll
    for (int nf = 0; nf < 16; nf++) {
        const int w_log = nf * 4 + t4;
        const int phys  = (w_log & ~7) + 2 * t4 + (nf & 1);
        uint32_t hi, lo;
        split2(oacc[nf][0] * inv0, oacc[nf][1] * inv0, hi, lo);
        OhiG[rowg + phys] = hi;
        OloG[rowg + phys] = lo;
        split2(oacc[nf][2] * inv1, oacc[nf][3] * inv1, hi, lo);
        OhiG[rowg8 + phys] = hi;
        OloG[rowg8 + phys] = lo;
    }
}

// ---------------------------------------------------------------------------
// kernel_launch
// ---------------------------------------------------------------------------
extern "C" void kernel_launch(void* const* d_in, const int* in_sizes, int n_in,
                              void* d_out, int out_size)
{
    const float* queries = (const float*)d_in[0];
    const float* keys    = (const float*)d_in[1];
    const float* values  = (const float*)d_in[2];
    const float* Wq      = (const float*)d_in[3];
    const float* bq      = (const float*)d_in[4];
    const float* Wlk     = (const float*)d_in[5];
    const float* blk     = (const float*)d_in[6];
    const float* Wlv     = (const float*)d_in[7];
    const float* blv     = (const float*)d_in[8];
    const float* Wkr     = (const float*)d_in[9];
    const float* bkr     = (const float*)d_in[10];
    const float* Wvr     = (const float*)d_in[11];
    const float* bvr     = (const float*)d_in[12];
    const float* Wo      = (const float*)d_in[13];
    const float* bo      = (const float*)d_in[14];
    float* out = (float*)d_out;

    float *Q, *bk, *bv;
    uint32_t *Xhi, *Xlo, *Ohi, *Olo, *Khi, *Klo, *Vhi, *Vlo;
    uint32_t *WqThi, *WqTlo, *WkThi, *WkTlo, *WvThi, *WvTlo, *WoThi, *WoTlo;
    cudaGetSymbolAddress((void**)&Q,     g_Q);
    cudaGetSymbolAddress((void**)&Xhi,   g_Xhi);
    cudaGetSymbolAddress((void**)&Xlo,   g_Xlo);
    cudaGetSymbolAddress((void**)&Ohi,   g_Ohi);
    cudaGetSymbolAddress((void**)&Olo,   g_Olo);
    cudaGetSymbolAddress((void**)&Khi,   g_Khi);
    cudaGetSymbolAddress((void**)&Klo,   g_Klo);
    cudaGetSymbolAddress((void**)&Vhi,   g_Vhi);
    cudaGetSymbolAddress((void**)&Vlo,   g_Vlo);
    cudaGetSymbolAddress((void**)&WqThi, g_WqThi);
    cudaGetSymbolAddress((void**)&WqTlo, g_WqTlo);
    cudaGetSymbolAddress((void**)&WkThi, g_WkThi);
    cudaGetSymbolAddress((void**)&WkTlo, g_WkTlo);
    cudaGetSymbolAddress((void**)&WvThi, g_WvThi);
    cudaGetSymbolAddress((void**)&WvTlo, g_WvTlo);
    cudaGetSymbolAddress((void**)&WoThi, g_WoThi);
    cudaGetSymbolAddress((void**)&WoTlo, g_WoTlo);
    cudaGetSymbolAddress((void**)&bk,    g_bk);
    cudaGetSymbolAddress((void**)&bv,    g_bv);

    cudaFuncSetAttribute(qkv_gemm_kernel,
                         cudaFuncAttributeMaxDynamicSharedMemorySize, G_SMEM_BYTES);
    cudaFuncSetAttribute(o_gemm_kernel,
                         cudaFuncAttributeMaxDynamicSharedMemorySize, G_SMEM_BYTES);
    cudaFuncSetAttribute(fa_tc_kernel,
                         cudaFuncAttributeMaxDynamicSharedMemorySize, FA_SMEM_BYTES);
    cudaFuncSetAttribute(foldT_kernel,
                         cudaFuncAttributeMaxDynamicSharedMemorySize, FT_SMEM_BYTES);

    // Weight preparation
    foldT_kernel<<<dim3(16, 16, 2), 256, FT_SMEM_BYTES>>>(
        Wlk, Wkr, WkThi, WkTlo, Wlv, Wvr, WvThi, WvTlo);
    fold_b_kernel<<<dim3(Hh, 2), 128>>>(blk, Wkr, bkr, bk, blv, Wvr, bvr, bv);
    transposeW_kernel<<<dim3(64, 64, 2), 256>>>(
        Wq, WqThi, WqTlo, Wo, WoThi, WoTlo);

    // Split activations into bf16 hi/lo planes
    const int sblocks = (int)(((size_t)Mrows * Dmod / 16) / 256);
    split_act_kernel<<<dim3(sblocks, 1, 3), 256>>>(
        queries, keys, values, Xhi, Xlo);

    // Merged Q/K/V projections (bf16 hi/lo x3)
    qkv_gemm_kernel<<<dim3(Dmod / 128, Mrows / 128, 3), 256, G_SMEM_BYTES>>>(
        Xhi, Xlo, WqThi, WqTlo, WkThi, WkTlo, WvThi, WvTlo,
        bq, bk, bv, Q, Khi, Klo, Vhi, Vlo);

    // Fused causal attention (emits split O planes)
    fa_tc_kernel<<<dim3(Sseq / 128, Hh, Bsz), 256, FA_SMEM_BYTES>>>(
        Q, Khi, Klo, Vhi, Vlo, Ohi, Olo);

    // Output projection
    o_gemm_kernel<<<dim3(Dmod / 128, Mrows / 128), 256, G_SMEM_BYTES>>>(
        Ohi, Olo, WoThi, WoTlo, bo, out);
}

// round 12
// speedup vs baseline: 1.8580x; 1.8580x over previous
#include <cuda_runtime.h>
#include <cuda_bf16.h>
#include <cuda_fp16.h>
#include <math.h>
#include <cstdint>

// Problem constants
#define Bsz   2
#define Sseq  2048
#define Dmod  2048
#define Hh    16
#define DKk   128
#define Ll    64
#define Mrows (Bsz * Sseq)   // 4096

// ---------------------------------------------------------------------------
// Device scratch
// ---------------------------------------------------------------------------
__device__ float    g_Q   [(size_t)Mrows * Dmod];
__device__ uint32_t g_Xh  [(size_t)3 * Mrows * 1024];  // fp16 activations q/k/v
__device__ uint32_t g_Oh  [(size_t)Mrows * 1024];      // fp16 FA output plane
__device__ uint32_t g_Khi[(size_t)Mrows * 1024];       // [b,h,s][64 words] bf16
__device__ uint32_t g_Klo[(size_t)Mrows * 1024];
__device__ uint32_t g_Vhi[(size_t)Mrows * 1024];       // [b,h,d][1024 words]
__device__ uint32_t g_Vlo[(size_t)Mrows * 1024];
__device__ uint32_t g_WqTh[(size_t)Dmod * 1024];       // fp16 weight planes
__device__ uint32_t g_WkTh[(size_t)Dmod * 1024];
__device__ uint32_t g_WvTh[(size_t)Dmod * 1024];
__device__ uint32_t g_WoTh[(size_t)Dmod * 1024];
__device__ float    g_bk[Dmod];
__device__ float    g_bv[Dmod];

// ---------------------------------------------------------------------------
// Helpers
// ---------------------------------------------------------------------------
__device__ __forceinline__ uint32_t smem_u32(const void* p) {
    uint32_t a;
    asm("{ .reg .u64 t; cvta.to.shared.u64 t, %1; cvt.u32.u64 %0, t; }"
        : "=r"(a) : "l"(p));
    return a;
}

#define CP_ASYNC16(dst, src) \
    asm volatile("cp.async.cg.shared.global [%0], [%1], 16;" \
        :: "r"((uint32_t)(dst)), "l"(src) : "memory")
#define CP_COMMIT() asm volatile("cp.async.commit_group;" ::: "memory")
#define CP_WAIT(n)  asm volatile("cp.async.wait_group %0;" :: "n"(n) : "memory")

// pack two fp32 into fp16x2: e0 -> lower half (first k element)
__device__ __forceinline__ uint32_t packh(float e0, float e1) {
    uint32_t r;
    asm("cvt.rn.f16x2.f32 %0, %1, %2;" : "=r"(r) : "f"(e1), "f"(e0));
    return r;
}

__device__ __forceinline__ uint32_t packbf(float e0, float e1) {
    uint32_t r;
    asm("cvt.rn.bf16x2.f32 %0, %1, %2;" : "=r"(r) : "f"(e1), "f"(e0));
    return r;
}

__device__ __forceinline__ void split2(float e0, float e1,
                                       uint32_t& hi, uint32_t& lo) {
    hi = packbf(e0, e1);
    float r0 = e0 - __uint_as_float(hi << 16);
    float r1 = e1 - __uint_as_float(hi & 0xFFFF0000u);
    lo = packbf(r0, r1);
}

__device__ __forceinline__ void mma_f16(float* c, const uint32_t* a,
                                        uint32_t b0, uint32_t b1) {
    asm volatile(
        "mma.sync.aligned.m16n8k16.row.col.f32.f16.f16.f32 "
        "{%0,%1,%2,%3}, {%4,%5,%6,%7}, {%8,%9}, {%0,%1,%2,%3};"
        : "+f"(c[0]), "+f"(c[1]), "+f"(c[2]), "+f"(c[3])
        : "r"(a[0]), "r"(a[1]), "r"(a[2]), "r"(a[3]), "r"(b0), "r"(b1));
}

__device__ __forceinline__ void mma_bf16(float* c, const uint32_t* a,
                                         uint32_t b0, uint32_t b1) {
    asm volatile(
        "mma.sync.aligned.m16n8k16.row.col.f32.bf16.bf16.f32 "
        "{%0,%1,%2,%3}, {%4,%5,%6,%7}, {%8,%9}, {%0,%1,%2,%3};"
        : "+f"(c[0]), "+f"(c[1]), "+f"(c[2]), "+f"(c[3])
        : "r"(a[0]), "r"(a[1]), "r"(a[2]), "r"(a[3]), "r"(b0), "r"(b1));
}

__device__ __forceinline__ float ex2(float x) {
    float y;
    asm("ex2.approx.ftz.f32 %0, %1;" : "=f"(y) : "f"(x));
    return y;
}

// ---------------------------------------------------------------------------
// Convert activations to fp16 word planes with pair permutation.
// 8-word (16-elem) group: phys order {w0,w4,w1,w5,w2,w6,w3,w7}; uint2 at
// phys 2*t4 = logical words (t4, t4+4) = one m16n8k16 fragment pair.
// ---------------------------------------------------------------------------
__global__ __launch_bounds__(256) void cvt_half_kernel(
    const float* __restrict__ in0, const float* __restrict__ in1,
    const float* __restrict__ in2, uint32_t* __restrict__ out)
{
    const int z = blockIdx.z;
    const float* in = (z == 0) ? in0 : (z == 1) ? in1 : in2;
    uint32_t* Oh = out + (size_t)z * Mrows * 1024;

    const size_t idx = (size_t)blockIdx.x * 256 + threadIdx.x;
    const size_t ebase = idx * 16;
    const float4 a = *(const float4*)(in + ebase);
    const float4 b = *(const float4*)(in + ebase + 4);
    const float4 c = *(const float4*)(in + ebase + 8);
    const float4 d = *(const float4*)(in + ebase + 12);

    uint32_t h[8];
    h[0] = packh(a.x, a.y); h[1] = packh(a.z, a.w);
    h[2] = packh(b.x, b.y); h[3] = packh(b.z, b.w);
    h[4] = packh(c.x, c.y); h[5] = packh(c.z, c.w);
    h[6] = packh(d.x, d.y); h[7] = packh(d.z, d.w);

    const size_t wbase = idx * 8;
    *(uint4*)(Oh + wbase)     = make_uint4(h[0], h[4], h[1], h[5]);
    *(uint4*)(Oh + wbase + 4) = make_uint4(h[2], h[6], h[3], h[7]);
}

// ---------------------------------------------------------------------------
// Fused fold + transpose -> fp16 plane (merged z over K/V weights)
// ---------------------------------------------------------------------------
#define FT_SMEM_BYTES ((64 * 132 + 64 * 128) * 4)

__global__ __launch_bounds__(256) void foldT_kernel(
    const float* __restrict__ Wl0, const float* __restrict__ Wr0,
    uint32_t* __restrict__ WTh0,
    const float* __restrict__ Wl1, const float* __restrict__ Wr1,
    uint32_t* __restrict__ WTh1)
{
    const float* Wl = blockIdx.z ? Wl1 : Wl0;
    const float* Wr = blockIdx.z ? Wr1 : Wr0;
    uint32_t* WTh = blockIdx.z ? WTh1 : WTh0;

    extern __shared__ float fsm[];
    float* sWl = fsm;             // [l][132]
    float* sWr = fsm + 64 * 132;  // [l][128]

    const int dblk = blockIdx.x;
    const int h    = blockIdx.y;
    const int t    = threadIdx.x;

    #pragma unroll
    for (int i = 0; i < 8; i++) {
        int u = t + i * 256;
        int l = u >> 5, c4 = u & 31;
        *(float4*)&sWr[l * 128 + c4 * 4] = *(const float4*)(Wr + l * DKk + c4 * 4);
    }
    #pragma unroll
    for (int i = 0; i < 8; i++) {
        int u = t + i * 256;
        int d = u >> 4, l4 = u & 15;
        float4 x = *(const float4*)(Wl + (size_t)(dblk * 128 + d) * (Hh * Ll)
                                    + h * Ll + l4 * 4);
        sWl[(l4 * 4 + 0) * 132 + d] = x.x;
        sWl[(l4 * 4 + 1) * 132 + d] = x.y;
        sWl[(l4 * 4 + 2) * 132 + d] = x.z;
        sWl[(l4 * 4 + 3) * 132 + d] = x.w;
    }
    __syncthreads();

    const int d8 = (t & 15) * 8;
    const int cg = t >> 4;
    float acc[8][8];
    #pragma unroll
    for (int dd = 0; dd < 8; dd++)
        #pragma unroll
        for (int j = 0; j < 8; j++) acc[dd][j] = 0.f;

    for (int l = 0; l < Ll; l++) {
        float4 a0 = *(float4*)&sWl[l * 132 + d8];
        float4 a1 = *(float4*)&sWl[l * 132 + d8 + 4];
        const float* wr = &sWr[l * 128 + cg * 8];
        #pragma unroll
        for (int j = 0; j < 8; j++) {
            float wv = wr[j];
            acc[0][j] += a0.x * wv;
            acc[1][j] += a0.y * wv;
            acc[2][j] += a0.z * wv;
            acc[3][j] += a0.w * wv;
            acc[4][j] += a1.x * wv;
            acc[5][j] += a1.y * wv;
            acc[6][j] += a1.z * wv;
            acc[7][j] += a1.w * wv;
        }
    }

    // store word pairs, pair-permuted: phys = wb + 2*i2 + (t&1)
    const int wb  = dblk * 64 + ((d8 >> 1) & ~7);
    const int off = t & 1;
    #pragma unroll
    for (int j = 0; j < 8; j++) {
        const int n = h * 128 + cg * 8 + j;
        #pragma unroll
        for (int i2 = 0; i2 < 4; i2++)
            WTh[(size_t)n * 1024 + wb + 2 * i2 + off] =
                packh(acc[2 * i2][j], acc[2 * i2 + 1][j]);
    }
}

__global__ __launch_bounds__(128) void fold_b_kernel(
    const float* __restrict__ bl0, const float* __restrict__ Wr0,
    const float* __restrict__ br0, float* __restrict__ be0,
    const float* __restrict__ bl1, const float* __restrict__ Wr1,
    const float* __restrict__ br1, float* __restrict__ be1)
{
    const float* bl = blockIdx.y ? bl1 : bl0;
    const float* Wr = blockIdx.y ? Wr1 : Wr0;
    const float* br = blockIdx.y ? br1 : br0;
    float* beff = blockIdx.y ? be1 : be0;
    const int h = blockIdx.x;
    const int c = threadIdx.x;
    float acc = br[c];
    #pragma unroll 16
    for (int l = 0; l < Ll; l++)
        acc += bl[h * Ll + l] * Wr[l * DKk + c];
    beff[h * DKk + c] = acc;
}

// ---------------------------------------------------------------------------
// 32x32 tiled transpose -> fp16 plane (merged z over Wq/Wo)
// ---------------------------------------------------------------------------
__global__ __launch_bounds__(256) void transposeW_kernel(
    const float* __restrict__ in0, uint32_t* __restrict__ h0,
    const float* __restrict__ in1, uint32_t* __restrict__ h1)
{
    const float* in = blockIdx.z ? in1 : in0;
    uint32_t* Oh = blockIdx.z ? h1 : h0;
    __shared__ float tile[32][33];
    const int bx = blockIdx.x * 32;   // n block
    const int by = blockIdx.y * 32;   // k block
    const int tx = threadIdx.x & 31;
    const int ty = threadIdx.x >> 5;
    #pragma unroll
    for (int i = 0; i < 32; i += 8)
        tile[ty + i][tx] = in[(size_t)(by + ty + i) * Dmod + bx + tx];
    __syncthreads();

    const int c = tx;
    const int u = ty;
    #pragma unroll
    for (int ii = 0; ii < 2; ii++) {
        const int uf = u + 8 * ii;
        const int r  = uf & 7;
        const int phys = (by >> 1) + (uf & 8) + (((r & 3) << 1) | (r >> 2));
        Oh[(size_t)(bx + c) * 1024 + phys] =
            packh(tile[2 * uf][c], tile[2 * uf + 1][c]);
    }
}

// ---------------------------------------------------------------------------
// fp16 tensor-core GEMM body: C = A @ WT^T + bias.
// Operands: fp16 word planes, pair-permuted (uint2 = fragment word pair).
// CTA 128x128, BK=64 (4 x k16), 2-stage cp.async, 256 thr, occupancy 2.
// smem: 2 stages x 2 ops x 128 rows x 36 words x 4B = 73728 B.
// MODE 0: fp32 out. MODE 1: K bf16 split planes. MODE 2: V planes transposed.
// ---------------------------------------------------------------------------
#define G_BK 64
#define G_NK (Dmod / G_BK)            // 32
#define G_ST 36                       // words per row (32 used + 4 pad)
#define G_OP_WORDS (128 * G_ST)       // 4608
#define G_STAGE_WORDS (2 * G_OP_WORDS)
#define G_SMEM_BYTES (2 * G_STAGE_WORDS * 4)  // 73728

template<int MODE>
__device__ __forceinline__ void gemm_body(
    uint32_t* smw, uint32_t smem_base,
    const uint32_t* __restrict__ AhG, const uint32_t* __restrict__ WhG,
    const float* __restrict__ bias, float* __restrict__ C,
    uint32_t* __restrict__ Chi, uint32_t* __restrict__ Clo,
    int m0, int n0)
{
    const int t    = threadIdx.x;
    const int wid  = t >> 5;
    const int lane = t & 31;
    const int g    = lane >> 2;
    const int tid4 = lane & 3;
    const int wm   = wid >> 2;
    const int wn   = wid & 3;

    float acc[4][4][4];
    #pragma unroll
    for (int mf = 0; mf < 4; mf++)
        #pragma unroll
        for (int nf = 0; nf < 4; nf++)
            #pragma unroll
            for (int r = 0; r < 4; r++) acc[mf][nf][r] = 0.f;

    auto load_stage = [&](int s, int k0) {
        const uint32_t aB = smem_base + (uint32_t)s * G_STAGE_WORDS * 4;
        const uint32_t bB = aB + G_OP_WORDS * 4;
        const int w0 = k0 >> 1;   // global word offset (BK=64 elems = 32 words)
        #pragma unroll
        for (int i = 0; i < 4; i++) {
            int u = t + i * 256;
            int row = u >> 3, c = u & 7;
            uint32_t doff = (uint32_t)(row * G_ST + c * 4) * 4;
            CP_ASYNC16(aB + doff, AhG + (size_t)(m0 + row) * 1024 + w0 + c * 4);
        }
        #pragma unroll
        for (int i = 0; i < 4; i++) {
            int u = t + i * 256;
            int row = u >> 3, c = u & 7;
            uint32_t doff = (uint32_t)(row * G_ST + c * 4) * 4;
            CP_ASYNC16(bB + doff, WhG + (size_t)(n0 + row) * 1024 + w0 + c * 4);
        }
    };

    load_stage(0, 0);
    CP_COMMIT();
    load_stage(1, G_BK);
    CP_COMMIT();

    for (int k = 0; k < G_NK; k++) {
        const int s = k & 1;
        CP_WAIT(1);
        __syncthreads();

        const uint32_t* sA = smw + (size_t)s * G_STAGE_WORDS;
        const uint32_t* sB = sA + G_OP_WORDS;

        #pragma unroll
        for (int ks = 0; ks < 4; ks++) {
            const int wk = 8 * ks + 2 * tid4;
            uint2 bq[4];
            #pragma unroll
            for (int nf = 0; nf < 4; nf++)
                bq[nf] = *(const uint2*)&sB[(wn * 32 + nf * 8 + g) * G_ST + wk];
            #pragma unroll
            for (int mf = 0; mf < 4; mf++) {
                const int ra = (wm * 64 + mf * 16 + g) * G_ST + wk;
                uint2 a0 = *(const uint2*)&sA[ra];
                uint2 a1 = *(const uint2*)&sA[ra + 8 * G_ST];
                uint32_t af[4] = {a0.x, a1.x, a0.y, a1.y};
                #pragma unroll
                for (int nf = 0; nf < 4; nf++)
                    mma_f16(acc[mf][nf], af, bq[nf].x, bq[nf].y);
            }
        }

        __syncthreads();
        if (k + 2 < G_NK) load_stage(s, (k + 2) * G_BK);
        CP_COMMIT();
    }

    #pragma unroll
    for (int mf = 0; mf < 4; mf++) {
        const int r0 = m0 + wm * 64 + mf * 16 + g;
        #pragma unroll
        for (int nf = 0; nf < 4; nf++) {
            const int c0 = n0 + wn * 32 + nf * 8 + 2 * tid4;
            const float b0 = bias[c0], b1 = bias[c0 + 1];
            float v0 = acc[mf][nf][0] + b0, v1 = acc[mf][nf][1] + b1;
            float v2 = acc[mf][nf][2] + b0, v3 = acc[mf][nf][3] + b1;
            if (MODE == 0) {
                *(float2*)(C + (size_t)r0 * Dmod + c0)       = make_float2(v0, v1);
                *(float2*)(C + (size_t)(r0 + 8) * Dmod + c0) = make_float2(v2, v3);
            } else if (MODE == 1) {
                const int bb = r0 >> 11, s2 = r0 & 2047, hh = c0 >> 7;
                const int j = (c0 & 127) >> 1;
                const int p = (j & ~7) | (2 * tid4 + (nf & 1));
                const size_t base = ((size_t)(bb * Hh + hh) * Sseq + s2) * 64 + p;
                uint32_t hi, lo;
                split2(v0, v1, hi, lo);
                Chi[base] = hi; Clo[base] = lo;
                split2(v2, v3, hi, lo);
                Chi[base + 512] = hi; Clo[base + 512] = lo;
            } else {
                float u0 = __shfl_xor_sync(0xFFFFFFFFu, v0, 4);
                float u1 = __shfl_xor_sync(0xFFFFFFFFu, v1, 4);
                float u2 = __shfl_xor_sync(0xFFFFFFFFu, v2, 4);
                float u3 = __shfl_xor_sync(0xFFFFFFFFu, v3, 4);
                if ((g & 1) == 0) {
                    const int bb = r0 >> 11, s2 = r0 & 2047, hh = c0 >> 7;
                    const int d = c0 & 127;
                    const size_t base0 =
                        ((size_t)(bb * Hh + hh) * DKk + d) * 1024 + ((s2 & ~15) >> 1);
                    uint32_t hi, lo;
                    split2(v0, u0, hi, lo);
                    Chi[base0 + g] = hi;            Clo[base0 + g] = lo;
                    split2(v2, u2, hi, lo);
                    Chi[base0 + g + 1] = hi;        Clo[base0 + g + 1] = lo;
                    split2(v1, u1, hi, lo);
                    Chi[base0 + 1024 + g] = hi;     Clo[base0 + 1024 + g] = lo;
                    split2(v3, u3, hi, lo);
                    Chi[base0 + 1024 + g + 1] = hi; Clo[base0 + 1024 + g + 1] = lo;
                }
            }
        }
    }
}

// Merged Q/K/V projection (grid.z selects input/weight/epilogue)
__global__ __launch_bounds__(256, 2) void qkv_gemm_kernel(
    const uint32_t* __restrict__ Xh,
    const uint32_t* __restrict__ WqTh, const uint32_t* __restrict__ WkTh,
    const uint32_t* __restrict__ WvTh,
    const float* __restrict__ bq, const float* __restrict__ bk,
    const float* __restrict__ bv,
    float* __restrict__ Q,
    uint32_t* __restrict__ Khi, uint32_t* __restrict__ Klo,
    uint32_t* __restrict__ Vhi, uint32_t* __restrict__ Vlo)
{
    extern __shared__ uint32_t smw[];
    const uint32_t smem_base = smem_u32(smw);
    const int m0 = blockIdx.y * 128;
    const int n0 = blockIdx.x * 128;
    const int z = blockIdx.z;
    const uint32_t* Ah = Xh + (size_t)z * Mrows * 1024;
    if (z == 0)
        gemm_body<0>(smw, smem_base, Ah, WqTh, bq, Q, nullptr, nullptr, m0, n0);
    else if (z == 1)
        gemm_body<1>(smw, smem_base, Ah, WkTh, bk, nullptr, Khi, Klo, m0, n0);
    else
        gemm_body<2>(smw, smem_base, Ah, WvTh, bv, nullptr, Vhi, Vlo, m0, n0);
}

__global__ __launch_bounds__(256, 2) void o_gemm_kernel(
    const uint32_t* __restrict__ Ah, const uint32_t* __restrict__ WTh,
    const float* __restrict__ bias, float* __restrict__ C)
{
    extern __shared__ uint32_t smw[];
    const uint32_t smem_base = smem_u32(smw);
    gemm_body<0>(smw, smem_base, Ah, WTh, bias, C, nullptr, nullptr,
                 blockIdx.y * 128, blockIdx.x * 128);
}

// ---------------------------------------------------------------------------
// Tensor-core causal FA (bf16 hi/lo x3, unchanged mainloop).
// Epilogue emits fp16 plane for the O projection.
// ---------------------------------------------------------------------------
#define KROWW 72
#define VROWW 40
#define FA_STAGE_WORDS (2 * 64 * KROWW + 2 * 128 * VROWW)
#define FA_SMEM_BYTES (2 * FA_STAGE_WORDS * 4)

__global__ __launch_bounds__(256, 1) void fa_tc_kernel(
    const float* __restrict__ Q,
    const uint32_t* __restrict__ KhiG, const uint32_t* __restrict__ KloG,
    const uint32_t* __restrict__ VhiG, const uint32_t* __restrict__ VloG,
    uint32_t* __restrict__ OhG)
{
    extern __shared__ uint32_t su[];
    const uint32_t smem_base = smem_u32(su);

    const int qb = (int)gridDim.x - 1 - (int)blockIdx.x;
    const int h  = blockIdx.y;
    const int b  = blockIdx.z;
    const int t  = threadIdx.x;
    const int w  = t >> 5;
    const int lane = t & 31;
    const int g  = lane >> 2;
    const int t4 = lane & 3;
    const int q0 = qb * 128;

    const size_t bh_off = (size_t)b * Sseq * Dmod + (size_t)h * DKk;
    const size_t bhS = (size_t)(b * Hh + h) * Sseq;
    const size_t bhD = (size_t)(b * Hh + h) * DKk;

    const float qscale = 0.088388347648318447f * 1.4426950408889634f;
    uint32_t qhi[8][4], qlo[8][4];
    {
        const float* Qw = Q + bh_off + (size_t)(q0 + w * 16) * Dmod;
        #pragma unroll
        for (int ks = 0; ks < 8; ks++) {
            const int d0 = ks * 16 + 2 * t4;
            float2 x0 = *(const float2*)(Qw + (size_t)g * Dmod + d0);
            float2 x1 = *(const float2*)(Qw + (size_t)(g + 8) * Dmod + d0);
            float2 x2 = *(const float2*)(Qw + (size_t)g * Dmod + d0 + 8);
            float2 x3 = *(const float2*)(Qw + (size_t)(g + 8) * Dmod + d0 + 8);
            split2(x0.x * qscale, x0.y * qscale, qhi[ks][0], qlo[ks][0]);
            split2(x1.x * qscale, x1.y * qscale, qhi[ks][1], qlo[ks][1]);
            split2(x2.x * qscale, x2.y * qscale, qhi[ks][2], qlo[ks][2]);
            split2(x3.x * qscale, x3.y * qscale, qhi[ks][3], qlo[ks][3]);
        }
    }

    auto load_tile = [&](int stage, int kt) {
        const int kv0 = kt * 64;
        const uint32_t sb = smem_base + (uint32_t)stage * FA_STAGE_WORDS * 4;
        const uint32_t kh = sb;
        const uint32_t kl = sb + 64 * KROWW * 4;
        const uint32_t vh = sb + 2 * 64 * KROWW * 4;
        const uint32_t vl = vh + 128 * VROWW * 4;
        #pragma unroll
        for (int i = 0; i < 4; i++) {
            int u = t + i * 256;
            int row = u >> 4, w4 = (u & 15) * 4;
            size_t src = (bhS + kv0 + row) * 64 + w4;
            uint32_t doff = (uint32_t)(row * KROWW + w4) * 4;
            CP_ASYNC16(kh + doff, KhiG + src);
            CP_ASYNC16(kl + doff, KloG + src);
        }
        #pragma unroll
        for (int i = 0; i < 4; i++) {
            int u = t + i * 256;
            int row = u >> 3, w4 = (u & 7) * 4;
            size_t src = (bhD + row) * 1024 + (kv0 >> 1) + w4;
            uint32_t doff = (uint32_t)(row * VROWW + w4) * 4;
            CP_ASYNC16(vh + doff, VhiG + src);
            CP_ASYNC16(vl + doff, VloG + src);
        }
    };

    float oacc[16][4];
    #pragma unroll
    for (int nf = 0; nf < 16; nf++)
        #pragma unroll
        for (int r = 0; r < 4; r++) oacc[nf][r] = 0.f;

    float m0 = -1e30f, m1 = -1e30f, l0 = 0.f, l1 = 0.f;
    const int row0 = q0 + w * 16 + g;
    const int row1 = row0 + 8;

    const int ntiles = 2 * qb + 2;
    load_tile(0, 0);
    CP_COMMIT();

    for (int kt = 0; kt < ntiles; kt++) {
        const int st = kt & 1;
        const int kv0 = kt * 64;
        if (kt + 1 < ntiles) {
            load_tile(st ^ 1, kt + 1);
            CP_COMMIT();
            CP_WAIT(1);
        } else {
            CP_WAIT(0);
        }
        __syncthreads();

        const uint32_t* Khi = su + (size_t)st * FA_STAGE_WORDS;
        const uint32_t* Klo = Khi + 64 * KROWW;
        const uint32_t* Vhi = Khi + 2 * 64 * KROWW;
        const uint32_t* Vlo = Vhi + 128 * VROWW;

        float acc[8][4];
        #pragma unroll
        for (int nf = 0; nf < 8; nf++)
            #pragma unroll
            for (int r = 0; r < 4; r++) acc[nf][r] = 0.f;

        #pragma unroll
        for (int ks = 0; ks < 8; ks++) {
            #pragma unroll
            for (int nf = 0; nf < 8; nf++) {
                const int r = (nf * 8 + g) * KROWW + 8 * ks + 2 * t4;
                uint2 bh = *(const uint2*)&Khi[r];
                uint2 bl = *(const uint2*)&Klo[r];
                mma_bf16(acc[nf], qhi[ks], bh.x, bh.y);
                mma_bf16(acc[nf], qhi[ks], bl.x, bl.y);
                mma_bf16(acc[nf], qlo[ks], bh.x, bh.y);
            }
        }

        if (kv0 + 63 > q0) {
            #pragma unroll
            for (int nf = 0; nf < 8; nf++) {
                const int c = kv0 + nf * 8 + 2 * t4;
                if (c     > row0) acc[nf][0] = -1e30f;
                if (c + 1 > row0) acc[nf][1] = -1e30f;
                if (c     > row1) acc[nf][2] = -1e30f;
                if (c + 1 > row1) acc[nf][3] = -1e30f;
            }
        }

        float mx0 = -1e30f, mx1 = -1e30f;
        #pragma unroll
        for (int nf = 0; nf < 8; nf++) {
            mx0 = fmaxf(mx0, fmaxf(acc[nf][0], acc[nf][1]));
            mx1 = fmaxf(mx1, fmaxf(acc[nf][2], acc[nf][3]));
        }
        mx0 = fmaxf(mx0, __shfl_xor_sync(0xFFFFFFFFu, mx0, 1));
        mx0 = fmaxf(mx0, __shfl_xor_sync(0xFFFFFFFFu, mx0, 2));
        mx1 = fmaxf(mx1, __shfl_xor_sync(0xFFFFFFFFu, mx1, 1));
        mx1 = fmaxf(mx1, __shfl_xor_sync(0xFFFFFFFFu, mx1, 2));

        const float mn0 = fmaxf(m0, mx0);
        const float mn1 = fmaxf(m1, mx1);
        const float cr0 = ex2(m0 - mn0);
        const float cr1 = ex2(m1 - mn1);

        float ps0 = 0.f, ps1 = 0.f;
        #pragma unroll
        for (int nf = 0; nf < 8; nf++) {
            acc[nf][0] = ex2(acc[nf][0] - mn0);
            acc[nf][1] = ex2(acc[nf][1] - mn0);
            acc[nf][2] = ex2(acc[nf][2] - mn1);
            acc[nf][3] = ex2(acc[nf][3] - mn1);
            ps0 += acc[nf][0] + acc[nf][1];
            ps1 += acc[nf][2] + acc[nf][3];
        }
        ps0 += __shfl_xor_sync(0xFFFFFFFFu, ps0, 1);
        ps0 += __shfl_xor_sync(0xFFFFFFFFu, ps0, 2);
        ps1 += __shfl_xor_sync(0xFFFFFFFFu, ps1, 1);
        ps1 += __shfl_xor_sync(0xFFFFFFFFu, ps1, 2);

        l0 = l0 * cr0 + ps0;
        l1 = l1 * cr1 + ps1;
        m0 = mn0;
        m1 = mn1;

        #pragma unroll
        for (int nf = 0; nf < 16; nf++) {
            oacc[nf][0] *= cr0;
            oacc[nf][1] *= cr0;
            oacc[nf][2] *= cr1;
            oacc[nf][3] *= cr1;
        }

        #pragma unroll
        for (int ks2 = 0; ks2 < 4; ks2++) {
            uint32_t ahi[4], alo[4];
            split2(acc[2 * ks2][0],     acc[2 * ks2][1],     ahi[0], alo[0]);
            split2(acc[2 * ks2][2],     acc[2 * ks2][3],     ahi[1], alo[1]);
            split2(acc[2 * ks2 + 1][0], acc[2 * ks2 + 1][1], ahi[2], alo[2]);
            split2(acc[2 * ks2 + 1][2], acc[2 * ks2 + 1][3], ahi[3], alo[3]);
            #pragma unroll
            for (int nf = 0; nf < 16; nf++) {
                const int r = (nf * 8 + g) * VROWW + 8 * ks2 + 2 * t4;
                uint2 bh = *(const uint2*)&Vhi[r];
                uint2 bl = *(const uint2*)&Vlo[r];
                mma_bf16(oacc[nf], ahi, bh.x, bh.y);
                mma_bf16(oacc[nf], ahi, bl.x, bl.y);
                mma_bf16(oacc[nf], alo, bh.x, bh.y);
            }
        }
        __syncthreads();
    }

    // epilogue: normalize, emit fp16 plane (pair-permuted words)
    const float inv0 = 1.0f / l0;
    const float inv1 = 1.0f / l1;
    const size_t rowg  = (size_t)(b * Sseq + q0 + w * 16 + g) * 1024 + h * 64;
    const size_t rowg8 = rowg + 8 * 1024;
    #pragma unroll
    for (int nf = 0; nf < 16; nf++) {
        const int w_log = nf * 4 + t4;
        const int phys  = (w_log & ~7) + 2 * t4 + (nf & 1);
        OhG[rowg + phys]  = packh(oacc[nf][0] * inv0, oacc[nf][1] * inv0);
        OhG[rowg8 + phys] = packh(oacc[nf][2] * inv1, oacc[nf][3] * inv1);
    }
}

// ---------------------------------------------------------------------------
// kernel_launch
// ---------------------------------------------------------------------------
extern "C" void kernel_launch(void* const* d_in, const int* in_sizes, int n_in,
                              void* d_out, int out_size)
{
    const float* queries = (const float*)d_in[0];
    const float* keys    = (const float*)d_in[1];
    const float* values  = (const float*)d_in[2];
    const float* Wq      = (const float*)d_in[3];
    const float* bq      = (const float*)d_in[4];
    const float* Wlk     = (const float*)d_in[5];
    const float* blk     = (const float*)d_in[6];
    const float* Wlv     = (const float*)d_in[7];
    const float* blv     = (const float*)d_in[8];
    const float* Wkr     = (const float*)d_in[9];
    const float* bkr     = (const float*)d_in[10];
    const float* Wvr     = (const float*)d_in[11];
    const float* bvr     = (const float*)d_in[12];
    const float* Wo      = (const float*)d_in[13];
    const float* bo      = (const float*)d_in[14];
    float* out = (float*)d_out;

    float *Q, *bk, *bv;
    uint32_t *Xh, *Oh, *Khi, *Klo, *Vhi, *Vlo;
    uint32_t *WqTh, *WkTh, *WvTh, *WoTh;
    cudaGetSymbolAddress((void**)&Q,    g_Q);
    cudaGetSymbolAddress((void**)&Xh,   g_Xh);
    cudaGetSymbolAddress((void**)&Oh,   g_Oh);
    cudaGetSymbolAddress((void**)&Khi,  g_Khi);
    cudaGetSymbolAddress((void**)&Klo,  g_Klo);
    cudaGetSymbolAddress((void**)&Vhi,  g_Vhi);
    cudaGetSymbolAddress((void**)&Vlo,  g_Vlo);
    cudaGetSymbolAddress((void**)&WqTh, g_WqTh);
    cudaGetSymbolAddress((void**)&WkTh, g_WkTh);
    cudaGetSymbolAddress((void**)&WvTh, g_WvTh);
    cudaGetSymbolAddress((void**)&WoTh, g_WoTh);
    cudaGetSymbolAddress((void**)&bk,   g_bk);
    cudaGetSymbolAddress((void**)&bv,   g_bv);

    cudaFuncSetAttribute(qkv_gemm_kernel,
                         cudaFuncAttributeMaxDynamicSharedMemorySize, G_SMEM_BYTES);
    cudaFuncSetAttribute(o_gemm_kernel,
                         cudaFuncAttributeMaxDynamicSharedMemorySize, G_SMEM_BYTES);
    cudaFuncSetAttribute(fa_tc_kernel,
                         cudaFuncAttributeMaxDynamicSharedMemorySize, FA_SMEM_BYTES);
    cudaFuncSetAttribute(foldT_kernel,
                         cudaFuncAttributeMaxDynamicSharedMemorySize, FT_SMEM_BYTES);

    // Weight preparation
    foldT_kernel<<<dim3(16, 16, 2), 256, FT_SMEM_BYTES>>>(
        Wlk, Wkr, WkTh, Wlv, Wvr, WvTh);
    fold_b_kernel<<<dim3(Hh, 2), 128>>>(blk, Wkr, bkr, bk, blv, Wvr, bvr, bv);
    transposeW_kernel<<<dim3(64, 64, 2), 256>>>(Wq, WqTh, Wo, WoTh);

    // Convert activations to fp16 planes
    const int cblocks = (int)(((size_t)Mrows * Dmod / 16) / 256);
    cvt_half_kernel<<<dim3(cblocks, 1, 3), 256>>>(queries, keys, values, Xh);

    // Merged Q/K/V projections (fp16 tensor cores)
    qkv_gemm_kernel<<<dim3(Dmod / 128, Mrows / 128, 3), 256, G_SMEM_BYTES>>>(
        Xh, WqTh, WkTh, WvTh, bq, bk, bv, Q, Khi, Klo, Vhi, Vlo);

    // Fused causal attention (emits fp16 O plane)
    fa_tc_kernel<<<dim3(Sseq / 128, Hh, Bsz), 256, FA_SMEM_BYTES>>>(
        Q, Khi, Klo, Vhi, Vlo, Oh);

    // Output projection
    o_gemm_kernel<<<dim3(Dmod / 128, Mrows / 128), 256, G_SMEM_BYTES>>>(
        Oh, WoTh, bo, out);
}

// round 13
// speedup vs baseline: 2.0869x; 1.1232x over previous
#include <cuda_runtime.h>
#include <cuda_bf16.h>
#include <cuda_fp16.h>
#include <math.h>
#include <cstdint>

// Problem constants
#define Bsz   2
#define Sseq  2048
#define Dmod  2048
#define Hh    16
#define DKk   128
#define Ll    64
#define Mrows (Bsz * Sseq)   // 4096

// ---------------------------------------------------------------------------
// Device scratch
// ---------------------------------------------------------------------------
__device__ uint32_t g_Xh  [(size_t)3 * Mrows * 1024];  // fp16 activations q/k/v
__device__ uint32_t g_Qhi [(size_t)Mrows * 1024];      // Q fp16 hi/lo planes
__device__ uint32_t g_Qlo [(size_t)Mrows * 1024];      //   [b,h,s][64 words]
__device__ uint32_t g_Kh  [(size_t)Mrows * 1024];      // K fp16 [b,h,s][64 w]
__device__ uint32_t g_Vh  [(size_t)Mrows * 1024];      // V fp16 [b,h,d][1024 w]
__device__ uint32_t g_Oh  [(size_t)Mrows * 1024];      // FA out fp16 plane
__device__ uint32_t g_WqTh[(size_t)Dmod * 1024];       // fp16 weight planes
__device__ uint32_t g_WkTh[(size_t)Dmod * 1024];
__device__ uint32_t g_WvTh[(size_t)Dmod * 1024];
__device__ uint32_t g_WoTh[(size_t)Dmod * 1024];
__device__ float    g_bk[Dmod];
__device__ float    g_bv[Dmod];

// ---------------------------------------------------------------------------
// Helpers
// ---------------------------------------------------------------------------
__device__ __forceinline__ uint32_t smem_u32(const void* p) {
    uint32_t a;
    asm("{ .reg .u64 t; cvta.to.shared.u64 t, %1; cvt.u32.u64 %0, t; }"
        : "=r"(a) : "l"(p));
    return a;
}

#define CP_ASYNC16(dst, src) \
    asm volatile("cp.async.cg.shared.global [%0], [%1], 16;" \
        :: "r"((uint32_t)(dst)), "l"(src) : "memory")
#define CP_COMMIT() asm volatile("cp.async.commit_group;" ::: "memory")
#define CP_WAIT(n)  asm volatile("cp.async.wait_group %0;" :: "n"(n) : "memory")

// pack two fp32 into fp16x2: e0 -> lower half (first k element)
__device__ __forceinline__ uint32_t packh(float e0, float e1) {
    uint32_t r;
    asm("cvt.rn.f16x2.f32 %0, %1, %2;" : "=r"(r) : "f"(e1), "f"(e0));
    return r;
}

// fp16 hi/lo split (residual beyond 11 bits)
__device__ __forceinline__ void split2h(float e0, float e1,
                                        uint32_t& hi, uint32_t& lo) {
    hi = packh(e0, e1);
    float f0, f1;
    asm("{ .reg .f16 a, b;\n mov.b32 {a, b}, %2;\n"
        " cvt.f32.f16 %0, a;\n cvt.f32.f16 %1, b; }"
        : "=f"(f0), "=f"(f1) : "r"(hi));
    lo = packh(e0 - f0, e1 - f1);
}

__device__ __forceinline__ void mma_f16(float* c, const uint32_t* a,
                                        uint32_t b0, uint32_t b1) {
    asm volatile(
        "mma.sync.aligned.m16n8k16.row.col.f32.f16.f16.f32 "
        "{%0,%1,%2,%3}, {%4,%5,%6,%7}, {%8,%9}, {%0,%1,%2,%3};"
        : "+f"(c[0]), "+f"(c[1]), "+f"(c[2]), "+f"(c[3])
        : "r"(a[0]), "r"(a[1]), "r"(a[2]), "r"(a[3]), "r"(b0), "r"(b1));
}

__device__ __forceinline__ float ex2(float x) {
    float y;
    asm("ex2.approx.ftz.f32 %0, %1;" : "=f"(y) : "f"(x));
    return y;
}

// ---------------------------------------------------------------------------
// Convert activations to fp16 word planes with pair permutation.
// ---------------------------------------------------------------------------
__global__ __launch_bounds__(256) void cvt_half_kernel(
    const float* __restrict__ in0, const float* __restrict__ in1,
    const float* __restrict__ in2, uint32_t* __restrict__ out)
{
    const int z = blockIdx.z;
    const float* in = (z == 0) ? in0 : (z == 1) ? in1 : in2;
    uint32_t* Oh = out + (size_t)z * Mrows * 1024;

    const size_t idx = (size_t)blockIdx.x * 256 + threadIdx.x;
    const size_t ebase = idx * 16;
    const float4 a = *(const float4*)(in + ebase);
    const float4 b = *(const float4*)(in + ebase + 4);
    const float4 c = *(const float4*)(in + ebase + 8);
    const float4 d = *(const float4*)(in + ebase + 12);

    uint32_t h[8];
    h[0] = packh(a.x, a.y); h[1] = packh(a.z, a.w);
    h[2] = packh(b.x, b.y); h[3] = packh(b.z, b.w);
    h[4] = packh(c.x, c.y); h[5] = packh(c.z, c.w);
    h[6] = packh(d.x, d.y); h[7] = packh(d.z, d.w);

    const size_t wbase = idx * 8;
    *(uint4*)(Oh + wbase)     = make_uint4(h[0], h[4], h[1], h[5]);
    *(uint4*)(Oh + wbase + 4) = make_uint4(h[2], h[6], h[3], h[7]);
}

// ---------------------------------------------------------------------------
// Fused fold + transpose -> fp16 plane (merged z over K/V weights)
// ---------------------------------------------------------------------------
#define FT_SMEM_BYTES ((64 * 132 + 64 * 128) * 4)

__global__ __launch_bounds__(256) void foldT_kernel(
    const float* __restrict__ Wl0, const float* __restrict__ Wr0,
    uint32_t* __restrict__ WTh0,
    const float* __restrict__ Wl1, const float* __restrict__ Wr1,
    uint32_t* __restrict__ WTh1)
{
    const float* Wl = blockIdx.z ? Wl1 : Wl0;
    const float* Wr = blockIdx.z ? Wr1 : Wr0;
    uint32_t* WTh = blockIdx.z ? WTh1 : WTh0;

    extern __shared__ float fsm[];
    float* sWl = fsm;             // [l][132]
    float* sWr = fsm + 64 * 132;  // [l][128]

    const int dblk = blockIdx.x;
    const int h    = blockIdx.y;
    const int t    = threadIdx.x;

    #pragma unroll
    for (int i = 0; i < 8; i++) {
        int u = t + i * 256;
        int l = u >> 5, c4 = u & 31;
        *(float4*)&sWr[l * 128 + c4 * 4] = *(const float4*)(Wr + l * DKk + c4 * 4);
    }
    #pragma unroll
    for (int i = 0; i < 8; i++) {
        int u = t + i * 256;
        int d = u >> 4, l4 = u & 15;
        float4 x = *(const float4*)(Wl + (size_t)(dblk * 128 + d) * (Hh * Ll)
                                    + h * Ll + l4 * 4);
        sWl[(l4 * 4 + 0) * 132 + d] = x.x;
        sWl[(l4 * 4 + 1) * 132 + d] = x.y;
        sWl[(l4 * 4 + 2) * 132 + d] = x.z;
        sWl[(l4 * 4 + 3) * 132 + d] = x.w;
    }
    __syncthreads();

    const int d8 = (t & 15) * 8;
    const int cg = t >> 4;
    float acc[8][8];
    #pragma unroll
    for (int dd = 0; dd < 8; dd++)
        #pragma unroll
        for (int j = 0; j < 8; j++) acc[dd][j] = 0.f;

    for (int l = 0; l < Ll; l++) {
        float4 a0 = *(float4*)&sWl[l * 132 + d8];
        float4 a1 = *(float4*)&sWl[l * 132 + d8 + 4];
        const float* wr = &sWr[l * 128 + cg * 8];
        #pragma unroll
        for (int j = 0; j < 8; j++) {
            float wv = wr[j];
            acc[0][j] += a0.x * wv;
            acc[1][j] += a0.y * wv;
            acc[2][j] += a0.z * wv;
            acc[3][j] += a0.w * wv;
            acc[4][j] += a1.x * wv;
            acc[5][j] += a1.y * wv;
            acc[6][j] += a1.z * wv;
            acc[7][j] += a1.w * wv;
        }
    }

    const int wb  = dblk * 64 + ((d8 >> 1) & ~7);
    const int off = t & 1;
    #pragma unroll
    for (int j = 0; j < 8; j++) {
        const int n = h * 128 + cg * 8 + j;
        #pragma unroll
        for (int i2 = 0; i2 < 4; i2++)
            WTh[(size_t)n * 1024 + wb + 2 * i2 + off] =
                packh(acc[2 * i2][j], acc[2 * i2 + 1][j]);
    }
}

__global__ __launch_bounds__(128) void fold_b_kernel(
    const float* __restrict__ bl0, const float* __restrict__ Wr0,
    const float* __restrict__ br0, float* __restrict__ be0,
    const float* __restrict__ bl1, const float* __restrict__ Wr1,
    const float* __restrict__ br1, float* __restrict__ be1)
{
    const float* bl = blockIdx.y ? bl1 : bl0;
    const float* Wr = blockIdx.y ? Wr1 : Wr0;
    const float* br = blockIdx.y ? br1 : br0;
    float* beff = blockIdx.y ? be1 : be0;
    const int h = blockIdx.x;
    const int c = threadIdx.x;
    float acc = br[c];
    #pragma unroll 16
    for (int l = 0; l < Ll; l++)
        acc += bl[h * Ll + l] * Wr[l * DKk + c];
    beff[h * DKk + c] = acc;
}

// ---------------------------------------------------------------------------
// 32x32 tiled transpose -> fp16 plane (merged z over Wq/Wo)
// ---------------------------------------------------------------------------
__global__ __launch_bounds__(256) void transposeW_kernel(
    const float* __restrict__ in0, uint32_t* __restrict__ h0,
    const float* __restrict__ in1, uint32_t* __restrict__ h1)
{
    const float* in = blockIdx.z ? in1 : in0;
    uint32_t* Oh = blockIdx.z ? h1 : h0;
    __shared__ float tile[32][33];
    const int bx = blockIdx.x * 32;
    const int by = blockIdx.y * 32;
    const int tx = threadIdx.x & 31;
    const int ty = threadIdx.x >> 5;
    #pragma unroll
    for (int i = 0; i < 32; i += 8)
        tile[ty + i][tx] = in[(size_t)(by + ty + i) * Dmod + bx + tx];
    __syncthreads();

    const int c = tx;
    const int u = ty;
    #pragma unroll
    for (int ii = 0; ii < 2; ii++) {
        const int uf = u + 8 * ii;
        const int r  = uf & 7;
        const int phys = (by >> 1) + (uf & 8) + (((r & 3) << 1) | (r >> 2));
        Oh[(size_t)(bx + c) * 1024 + phys] =
            packh(tile[2 * uf][c], tile[2 * uf + 1][c]);
    }
}

// ---------------------------------------------------------------------------
// fp16 tensor-core GEMM body: C = A @ WT^T + bias.
// MODE 0: fp32 out. MODE 1: K fp16 plane. MODE 2: V fp16 plane transposed.
// MODE 3: Q fp16 hi/lo planes (pre-scaled for softmax) in K layout.
// ---------------------------------------------------------------------------
#define G_BK 64
#define G_NK (Dmod / G_BK)            // 32
#define G_ST 36                       // words per row (32 used + 4 pad)
#define G_OP_WORDS (128 * G_ST)
#define G_STAGE_WORDS (2 * G_OP_WORDS)
#define G_SMEM_BYTES (2 * G_STAGE_WORDS * 4)  // 73728

template<int MODE>
__device__ __forceinline__ void gemm_body(
    uint32_t* smw, uint32_t smem_base,
    const uint32_t* __restrict__ AhG, const uint32_t* __restrict__ WhG,
    const float* __restrict__ bias, float* __restrict__ C,
    uint32_t* __restrict__ P1, uint32_t* __restrict__ P2,
    int m0, int n0)
{
    const int t    = threadIdx.x;
    const int wid  = t >> 5;
    const int lane = t & 31;
    const int g    = lane >> 2;
    const int tid4 = lane & 3;
    const int wm   = wid >> 2;
    const int wn   = wid & 3;

    float acc[4][4][4];
    #pragma unroll
    for (int mf = 0; mf < 4; mf++)
        #pragma unroll
        for (int nf = 0; nf < 4; nf++)
            #pragma unroll
            for (int r = 0; r < 4; r++) acc[mf][nf][r] = 0.f;

    auto load_stage = [&](int s, int k0) {
        const uint32_t aB = smem_base + (uint32_t)s * G_STAGE_WORDS * 4;
        const uint32_t bB = aB + G_OP_WORDS * 4;
        const int w0 = k0 >> 1;
        #pragma unroll
        for (int i = 0; i < 4; i++) {
            int u = t + i * 256;
            int row = u >> 3, c = u & 7;
            uint32_t doff = (uint32_t)(row * G_ST + c * 4) * 4;
            CP_ASYNC16(aB + doff, AhG + (size_t)(m0 + row) * 1024 + w0 + c * 4);
        }
        #pragma unroll
        for (int i = 0; i < 4; i++) {
            int u = t + i * 256;
            int row = u >> 3, c = u & 7;
            uint32_t doff = (uint32_t)(row * G_ST + c * 4) * 4;
            CP_ASYNC16(bB + doff, WhG + (size_t)(n0 + row) * 1024 + w0 + c * 4);
        }
    };

    load_stage(0, 0);
    CP_COMMIT();
    load_stage(1, G_BK);
    CP_COMMIT();

    for (int k = 0; k < G_NK; k++) {
        const int s = k & 1;
        CP_WAIT(1);
        __syncthreads();

        const uint32_t* sA = smw + (size_t)s * G_STAGE_WORDS;
        const uint32_t* sB = sA + G_OP_WORDS;

        #pragma unroll
        for (int ks = 0; ks < 4; ks++) {
            const int wk = 8 * ks + 2 * tid4;
            uint2 bq[4];
            #pragma unroll
            for (int nf = 0; nf < 4; nf++)
                bq[nf] = *(const uint2*)&sB[(wn * 32 + nf * 8 + g) * G_ST + wk];
            #pragma unroll
            for (int mf = 0; mf < 4; mf++) {
                const int ra = (wm * 64 + mf * 16 + g) * G_ST + wk;
                uint2 a0 = *(const uint2*)&sA[ra];
                uint2 a1 = *(const uint2*)&sA[ra + 8 * G_ST];
                uint32_t af[4] = {a0.x, a1.x, a0.y, a1.y};
                #pragma unroll
                for (int nf = 0; nf < 4; nf++)
                    mma_f16(acc[mf][nf], af, bq[nf].x, bq[nf].y);
            }
        }

        __syncthreads();
        if (k + 2 < G_NK) load_stage(s, (k + 2) * G_BK);
        CP_COMMIT();
    }

    #pragma unroll
    for (int mf = 0; mf < 4; mf++) {
        const int r0 = m0 + wm * 64 + mf * 16 + g;
        #pragma unroll
        for (int nf = 0; nf < 4; nf++) {
            const int c0 = n0 + wn * 32 + nf * 8 + 2 * tid4;
            const float b0 = bias[c0], b1 = bias[c0 + 1];
            float v0 = acc[mf][nf][0] + b0, v1 = acc[mf][nf][1] + b1;
            float v2 = acc[mf][nf][2] + b0, v3 = acc[mf][nf][3] + b1;
            if (MODE == 0) {
                *(float2*)(C + (size_t)r0 * Dmod + c0)       = make_float2(v0, v1);
                *(float2*)(C + (size_t)(r0 + 8) * Dmod + c0) = make_float2(v2, v3);
            } else if (MODE == 1 || MODE == 3) {
                const int bb = r0 >> 11, s2 = r0 & 2047, hh = c0 >> 7;
                const int j = (c0 & 127) >> 1;
                const int p = (j & ~7) | (2 * tid4 + (nf & 1));
                const size_t base = ((size_t)(bb * Hh + hh) * Sseq + s2) * 64 + p;
                if (MODE == 1) {
                    P1[base]       = packh(v0, v1);
                    P1[base + 512] = packh(v2, v3);
                } else {
                    const float qs = 0.088388347648318447f * 1.4426950408889634f;
                    uint32_t hi, lo;
                    split2h(v0 * qs, v1 * qs, hi, lo);
                    P1[base] = hi; P2[base] = lo;
                    split2h(v2 * qs, v3 * qs, hi, lo);
                    P1[base + 512] = hi; P2[base + 512] = lo;
                }
            } else {
                float u0 = __shfl_xor_sync(0xFFFFFFFFu, v0, 4);
                float u1 = __shfl_xor_sync(0xFFFFFFFFu, v1, 4);
                float u2 = __shfl_xor_sync(0xFFFFFFFFu, v2, 4);
                float u3 = __shfl_xor_sync(0xFFFFFFFFu, v3, 4);
                if ((g & 1) == 0) {
                    const int bb = r0 >> 11, s2 = r0 & 2047, hh = c0 >> 7;
                    const int d = c0 & 127;
                    const size_t base0 =
                        ((size_t)(bb * Hh + hh) * DKk + d) * 1024 + ((s2 & ~15) >> 1);
                    P1[base0 + g]            = packh(v0, u0);
                    P1[base0 + g + 1]        = packh(v2, u2);
                    P1[base0 + 1024 + g]     = packh(v1, u1);
                    P1[base0 + 1024 + g + 1] = packh(v3, u3);
                }
            }
        }
    }
}

// Merged Q/K/V projection (grid.z selects input/weight/epilogue)
__global__ __launch_bounds__(256, 2) void qkv_gemm_kernel(
    const uint32_t* __restrict__ Xh,
    const uint32_t* __restrict__ WqTh, const uint32_t* __restrict__ WkTh,
    const uint32_t* __restrict__ WvTh,
    const float* __restrict__ bq, const float* __restrict__ bk,
    const float* __restrict__ bv,
    uint32_t* __restrict__ Qhi, uint32_t* __restrict__ Qlo,
    uint32_t* __restrict__ Kh, uint32_t* __restrict__ Vh)
{
    extern __shared__ uint32_t smw[];
    const uint32_t smem_base = smem_u32(smw);
    const int m0 = blockIdx.y * 128;
    const int n0 = blockIdx.x * 128;
    const int z = blockIdx.z;
    const uint32_t* Ah = Xh + (size_t)z * Mrows * 1024;
    if (z == 0)
        gemm_body<3>(smw, smem_base, Ah, WqTh, bq, nullptr, Qhi, Qlo, m0, n0);
    else if (z == 1)
        gemm_body<1>(smw, smem_base, Ah, WkTh, bk, nullptr, Kh, nullptr, m0, n0);
    else
        gemm_body<2>(smw, smem_base, Ah, WvTh, bv, nullptr, Vh, nullptr, m0, n0);
}

__global__ __launch_bounds__(256, 2) void o_gemm_kernel(
    const uint32_t* __restrict__ Ah, const uint32_t* __restrict__ WTh,
    const float* __restrict__ bias, float* __restrict__ C)
{
    extern __shared__ uint32_t smw[];
    const uint32_t smem_base = smem_u32(smw);
    gemm_body<0>(smw, smem_base, Ah, WTh, bias, C, nullptr, nullptr,
                 blockIdx.y * 128, blockIdx.x * 128);
}

// ---------------------------------------------------------------------------
// Tensor-core causal FA: fp16 everywhere.
// Q fp16 hi/lo planes preloaded (direct uint2 global loads, pre-scaled).
// K/V single fp16 planes; QK = (qhi+qlo)*k (2 MMA), PV = (phi+plo)*v (2 MMA).
// ---------------------------------------------------------------------------
#define KROWW 72   // K row stride in words (64 used)
#define VROWW 40   // V row stride in words (32 used)
#define FA_STAGE_WORDS (64 * KROWW + 128 * VROWW)   // 9728
#define FA_SMEM_BYTES (2 * FA_STAGE_WORDS * 4)      // 77824

__global__ __launch_bounds__(256, 1) void fa_tc_kernel(
    const uint32_t* __restrict__ QhiG, const uint32_t* __restrict__ QloG,
    const uint32_t* __restrict__ KhG, const uint32_t* __restrict__ VhG,
    uint32_t* __restrict__ OhG)
{
    extern __shared__ uint32_t su[];
    const uint32_t smem_base = smem_u32(su);

    const int qb = (int)gridDim.x - 1 - (int)blockIdx.x;
    const int h  = blockIdx.y;
    const int b  = blockIdx.z;
    const int t  = threadIdx.x;
    const int w  = t >> 5;
    const int lane = t & 31;
    const int g  = lane >> 2;
    const int t4 = lane & 3;
    const int q0 = qb * 128;

    const size_t bhS = (size_t)(b * Hh + h) * Sseq;
    const size_t bhD = (size_t)(b * Hh + h) * DKk;

    // Preload Q fragments from hi/lo planes (pre-scaled in projection)
    uint32_t qh[8][4], ql[8][4];
    {
        const size_t rg  = (bhS + q0 + w * 16 + g) * 64;
        const size_t rg8 = rg + 8 * 64;
        #pragma unroll
        for (int ks = 0; ks < 8; ks++) {
            const int wk = 8 * ks + 2 * t4;
            uint2 h0 = *(const uint2*)&QhiG[rg + wk];
            uint2 h1 = *(const uint2*)&QhiG[rg8 + wk];
            uint2 l0 = *(const uint2*)&QloG[rg + wk];
            uint2 l1 = *(const uint2*)&QloG[rg8 + wk];
            qh[ks][0] = h0.x; qh[ks][1] = h1.x; qh[ks][2] = h0.y; qh[ks][3] = h1.y;
            ql[ks][0] = l0.x; ql[ks][1] = l1.x; ql[ks][2] = l0.y; ql[ks][3] = l1.y;
        }
    }

    auto load_tile = [&](int stage, int kt) {
        const int kv0 = kt * 64;
        const uint32_t sb = smem_base + (uint32_t)stage * FA_STAGE_WORDS * 4;
        const uint32_t kB = sb;
        const uint32_t vB = sb + 64 * KROWW * 4;
        #pragma unroll
        for (int i = 0; i < 4; i++) {
            int u = t + i * 256;                 // 1024 chunks K
            int row = u >> 4, w4 = (u & 15) * 4;
            CP_ASYNC16(kB + (uint32_t)(row * KROWW + w4) * 4,
                       KhG + (bhS + kv0 + row) * 64 + w4);
        }
        #pragma unroll
        for (int i = 0; i < 4; i++) {
            int u = t + i * 256;                 // 1024 chunks V
            int row = u >> 3, w4 = (u & 7) * 4;
            CP_ASYNC16(vB + (uint32_t)(row * VROWW + w4) * 4,
                       VhG + (bhD + row) * 1024 + (kv0 >> 1) + w4);
        }
    };

    float oacc[16][4];
    #pragma unroll
    for (int nf = 0; nf < 16; nf++)
        #pragma unroll
        for (int r = 0; r < 4; r++) oacc[nf][r] = 0.f;

    float m0 = -1e30f, m1 = -1e30f, l0 = 0.f, l1 = 0.f;
    const int row0 = q0 + w * 16 + g;
    const int row1 = row0 + 8;

    const int ntiles = 2 * qb + 2;
    load_tile(0, 0);
    CP_COMMIT();

    for (int kt = 0; kt < ntiles; kt++) {
        const int st = kt & 1;
        const int kv0 = kt * 64;
        if (kt + 1 < ntiles) {
            load_tile(st ^ 1, kt + 1);
            CP_COMMIT();
            CP_WAIT(1);
        } else {
            CP_WAIT(0);
        }
        __syncthreads();

        const uint32_t* Ks = su + (size_t)st * FA_STAGE_WORDS;
        const uint32_t* Vs = Ks + 64 * KROWW;

        float acc[8][4];
        #pragma unroll
        for (int nf = 0; nf < 8; nf++)
            #pragma unroll
            for (int r = 0; r < 4; r++) acc[nf][r] = 0.f;

        #pragma unroll
        for (int ks = 0; ks < 8; ks++) {
            #pragma unroll
            for (int nf = 0; nf < 8; nf++) {
                const int r = (nf * 8 + g) * KROWW + 8 * ks + 2 * t4;
                uint2 kw = *(const uint2*)&Ks[r];
                mma_f16(acc[nf], qh[ks], kw.x, kw.y);
                mma_f16(acc[nf], ql[ks], kw.x, kw.y);
            }
        }

        if (kv0 + 63 > q0) {
            #pragma unroll
            for (int nf = 0; nf < 8; nf++) {
                const int c = kv0 + nf * 8 + 2 * t4;
                if (c     > row0) acc[nf][0] = -1e30f;
                if (c + 1 > row0) acc[nf][1] = -1e30f;
                if (c     > row1) acc[nf][2] = -1e30f;
                if (c + 1 > row1) acc[nf][3] = -1e30f;
            }
        }

        float mx0 = -1e30f, mx1 = -1e30f;
        #pragma unroll
        for (int nf = 0; nf < 8; nf++) {
            mx0 = fmaxf(mx0, fmaxf(acc[nf][0], acc[nf][1]));
            mx1 = fmaxf(mx1, fmaxf(acc[nf][2], acc[nf][3]));
        }
        mx0 = fmaxf(mx0, __shfl_xor_sync(0xFFFFFFFFu, mx0, 1));
        mx0 = fmaxf(mx0, __shfl_xor_sync(0xFFFFFFFFu, mx0, 2));
        mx1 = fmaxf(mx1, __shfl_xor_sync(0xFFFFFFFFu, mx1, 1));
        mx1 = fmaxf(mx1, __shfl_xor_sync(0xFFFFFFFFu, mx1, 2));

        const float mn0 = fmaxf(m0, mx0);
        const float mn1 = fmaxf(m1, mx1);
        const float cr0 = ex2(m0 - mn0);
        const float cr1 = ex2(m1 - mn1);

        float ps0 = 0.f, ps1 = 0.f;
        #pragma unroll
        for (int nf = 0; nf < 8; nf++) {
            acc[nf][0] = ex2(acc[nf][0] - mn0);
            acc[nf][1] = ex2(acc[nf][1] - mn0);
            acc[nf][2] = ex2(acc[nf][2] - mn1);
            acc[nf][3] = ex2(acc[nf][3] - mn1);
            ps0 += acc[nf][0] + acc[nf][1];
            ps1 += acc[nf][2] + acc[nf][3];
        }
        ps0 += __shfl_xor_sync(0xFFFFFFFFu, ps0, 1);
        ps0 += __shfl_xor_sync(0xFFFFFFFFu, ps0, 2);
        ps1 += __shfl_xor_sync(0xFFFFFFFFu, ps1, 1);
        ps1 += __shfl_xor_sync(0xFFFFFFFFu, ps1, 2);

        l0 = l0 * cr0 + ps0;
        l1 = l1 * cr1 + ps1;
        m0 = mn0;
        m1 = mn1;

        #pragma unroll
        for (int nf = 0; nf < 16; nf++) {
            oacc[nf][0] *= cr0;
            oacc[nf][1] *= cr0;
            oacc[nf][2] *= cr1;
            oacc[nf][3] *= cr1;
        }

        #pragma unroll
        for (int ks2 = 0; ks2 < 4; ks2++) {
            uint32_t ph[4], pl[4];
            split2h(acc[2 * ks2][0],     acc[2 * ks2][1],     ph[0], pl[0]);
            split2h(acc[2 * ks2][2],     acc[2 * ks2][3],     ph[1], pl[1]);
            split2h(acc[2 * ks2 + 1][0], acc[2 * ks2 + 1][1], ph[2], pl[2]);
            split2h(acc[2 * ks2 + 1][2], acc[2 * ks2 + 1][3], ph[3], pl[3]);
            #pragma unroll
            for (int nf = 0; nf < 16; nf++) {
                const int r = (nf * 8 + g) * VROWW + 8 * ks2 + 2 * t4;
                uint2 vw = *(const uint2*)&Vs[r];
                mma_f16(oacc[nf], ph, vw.x, vw.y);
                mma_f16(oacc[nf], pl, vw.x, vw.y);
            }
        }
        __syncthreads();
    }

    // epilogue: normalize, emit fp16 O plane (pair-permuted words)
    const float inv0 = 1.0f / l0;
    const float inv1 = 1.0f / l1;
    const size_t rowg  = (size_t)(b * Sseq + q0 + w * 16 + g) * 1024 + h * 64;
    const size_t rowg8 = rowg + 8 * 1024;
    #pragma unroll
    for (int nf = 0; nf < 16; nf++) {
        const int w_log = nf * 4 + t4;
        const int phys  = (w_log & ~7) + 2 * t4 + (nf & 1);
        OhG[rowg + phys]  = packh(oacc[nf][0] * inv0, oacc[nf][1] * inv0);
        OhG[rowg8 + phys] = packh(oacc[nf][2] * inv1, oacc[nf][3] * inv1);
    }
}

// ---------------------------------------------------------------------------
// kernel_launch
// ---------------------------------------------------------------------------
extern "C" void kernel_launch(void* const* d_in, const int* in_sizes, int n_in,
                              void* d_out, int out_size)
{
    const float* queries = (const float*)d_in[0];
    const float* keys    = (const float*)d_in[1];
    const float* values  = (const float*)d_in[2];
    const float* Wq      = (const float*)d_in[3];
    const float* bq      = (const float*)d_in[4];
    const float* Wlk     = (const float*)d_in[5];
    const float* blk     = (const float*)d_in[6];
    const float* Wlv     = (const float*)d_in[7];
    const float* blv     = (const float*)d_in[8];
    const float* Wkr     = (const float*)d_in[9];
    const float* bkr     = (const float*)d_in[10];
    const float* Wvr     = (const float*)d_in[11];
    const float* bvr     = (const float*)d_in[12];
    const float* Wo      = (const float*)d_in[13];
    const float* bo      = (const float*)d_in[14];
    float* out = (float*)d_out;

    float *bk, *bv;
    uint32_t *Xh, *Qhi, *Qlo, *Kh, *Vh, *Oh;
    uint32_t *WqTh, *WkTh, *WvTh, *WoTh;
    cudaGetSymbolAddress((void**)&Xh,   g_Xh);
    cudaGetSymbolAddress((void**)&Qhi,  g_Qhi);
    cudaGetSymbolAddress((void**)&Qlo,  g_Qlo);
    cudaGetSymbolAddress((void**)&Kh,   g_Kh);
    cudaGetSymbolAddress((void**)&Vh,   g_Vh);
    cudaGetSymbolAddress((void**)&Oh,   g_Oh);
    cudaGetSymbolAddress((void**)&WqTh, g_WqTh);
    cudaGetSymbolAddress((void**)&WkTh, g_WkTh);
    cudaGetSymbolAddress((void**)&WvTh, g_WvTh);
    cudaGetSymbolAddress((void**)&WoTh, g_WoTh);
    cudaGetSymbolAddress((void**)&bk,   g_bk);
    cudaGetSymbolAddress((void**)&bv,   g_bv);

    cudaFuncSetAttribute(qkv_gemm_kernel,
                         cudaFuncAttributeMaxDynamicSharedMemorySize, G_SMEM_BYTES);
    cudaFuncSetAttribute(o_gemm_kernel,
                         cudaFuncAttributeMaxDynamicSharedMemorySize, G_SMEM_BYTES);
    cudaFuncSetAttribute(fa_tc_kernel,
                         cudaFuncAttributeMaxDynamicSharedMemorySize, FA_SMEM_BYTES);
    cudaFuncSetAttribute(foldT_kernel,
                         cudaFuncAttributeMaxDynamicSharedMemorySize, FT_SMEM_BYTES);

    // Weight preparation
    foldT_kernel<<<dim3(16, 16, 2), 256, FT_SMEM_BYTES>>>(
        Wlk, Wkr, WkTh, Wlv, Wvr, WvTh);
    fold_b_kernel<<<dim3(Hh, 2), 128>>>(blk, Wkr, bkr, bk, blv, Wvr, bvr, bv);
    transposeW_kernel<<<dim3(64, 64, 2), 256>>>(Wq, WqTh, Wo, WoTh);

    // Convert activations to fp16 planes
    const int cblocks = (int)(((size_t)Mrows * Dmod / 16) / 256);
    cvt_half_kernel<<<dim3(cblocks, 1, 3), 256>>>(queries, keys, values, Xh);

    // Merged Q/K/V projections (Q -> hi/lo planes; K,V -> fp16 planes)
    qkv_gemm_kernel<<<dim3(Dmod / 128, Mrows / 128, 3), 256, G_SMEM_BYTES>>>(
        Xh, WqTh, WkTh, WvTh, bq, bk, bv, Qhi, Qlo, Kh, Vh);

    // Fused causal attention (all-fp16, 2-term MMA)
    fa_tc_kernel<<<dim3(Sseq / 128, Hh, Bsz), 256, FA_SMEM_BYTES>>>(
        Qhi, Qlo, Kh, Vh, Oh);

    // Output projection
    o_gemm_kernel<<<dim3(Dmod / 128, Mrows / 128), 256, G_SMEM_BYTES>>>(
        Oh, WoTh, bo, out);
}

// round 14
// speedup vs baseline: 2.1583x; 1.0342x over previous
#include <cuda_runtime.h>
#include <cuda_bf16.h>
#include <cuda_fp16.h>
#include <math.h>
#include <cstdint>

// Problem constants
#define Bsz   2
#define Sseq  2048
#define Dmod  2048
#define Hh    16
#define DKk   128
#define Ll    64
#define Mrows (Bsz * Sseq)   // 4096

// ---------------------------------------------------------------------------
// Device scratch
// ---------------------------------------------------------------------------
__device__ uint32_t g_Xh  [(size_t)3 * Mrows * 1024];  // fp16 activations q/k/v
__device__ uint32_t g_Qh  [(size_t)Mrows * 1024];      // Q fp16 (pre-scaled)
__device__ uint32_t g_Kh  [(size_t)Mrows * 1024];      // K fp16 [b,h,s][64 w]
__device__ uint32_t g_Vh  [(size_t)Mrows * 1024];      // V fp16 [b,h,d][1024 w]
__device__ uint32_t g_Oh  [(size_t)Mrows * 1024];      // FA out fp16 plane
__device__ uint32_t g_WqTh[(size_t)Dmod * 1024];       // fp16 weight planes
__device__ uint32_t g_WkTh[(size_t)Dmod * 1024];
__device__ uint32_t g_WvTh[(size_t)Dmod * 1024];
__device__ uint32_t g_WoTh[(size_t)Dmod * 1024];
__device__ float    g_bk[Dmod];
__device__ float    g_bv[Dmod];

// ---------------------------------------------------------------------------
// Helpers
// ---------------------------------------------------------------------------
__device__ __forceinline__ uint32_t smem_u32(const void* p) {
    uint32_t a;
    asm("{ .reg .u64 t; cvta.to.shared.u64 t, %1; cvt.u32.u64 %0, t; }"
        : "=r"(a) : "l"(p));
    return a;
}

#define CP_ASYNC16(dst, src) \
    asm volatile("cp.async.cg.shared.global [%0], [%1], 16;" \
        :: "r"((uint32_t)(dst)), "l"(src) : "memory")
#define CP_COMMIT() asm volatile("cp.async.commit_group;" ::: "memory")
#define CP_WAIT(n)  asm volatile("cp.async.wait_group %0;" :: "n"(n) : "memory")

// pack two fp32 into fp16x2: e0 -> lower half (first k element)
__device__ __forceinline__ uint32_t packh(float e0, float e1) {
    uint32_t r;
    asm("cvt.rn.f16x2.f32 %0, %1, %2;" : "=r"(r) : "f"(e1), "f"(e0));
    return r;
}

// fp16 hi/lo split (residual beyond 11 bits)
__device__ __forceinline__ void split2h(float e0, float e1,
                                        uint32_t& hi, uint32_t& lo) {
    hi = packh(e0, e1);
    float f0, f1;
    asm("{ .reg .f16 a, b;\n mov.b32 {a, b}, %2;\n"
        " cvt.f32.f16 %0, a;\n cvt.f32.f16 %1, b; }"
        : "=f"(f0), "=f"(f1) : "r"(hi));
    lo = packh(e0 - f0, e1 - f1);
}

__device__ __forceinline__ void mma_f16(float* c, const uint32_t* a,
                                        uint32_t b0, uint32_t b1) {
    asm volatile(
        "mma.sync.aligned.m16n8k16.row.col.f32.f16.f16.f32 "
        "{%0,%1,%2,%3}, {%4,%5,%6,%7}, {%8,%9}, {%0,%1,%2,%3};"
        : "+f"(c[0]), "+f"(c[1]), "+f"(c[2]), "+f"(c[3])
        : "r"(a[0]), "r"(a[1]), "r"(a[2]), "r"(a[3]), "r"(b0), "r"(b1));
}

__device__ __forceinline__ float ex2(float x) {
    float y;
    asm("ex2.approx.ftz.f32 %0, %1;" : "=f"(y) : "f"(x));
    return y;
}

// ---------------------------------------------------------------------------
// Unified prep kernel: flat grid, role by block range.
//   [0, 6144)            cvt: activations -> fp16 planes (DRAM-bound, first)
//   [6144, 14336)        transposeW (Wq, Wo)
//   [14336, 14848)       foldT (K/V weights)
//   [14848, 14880)       fold_b
// ---------------------------------------------------------------------------
#define PREP_CVT    6144
#define PREP_TRW    (PREP_CVT + 8192)      // 14336
#define PREP_FOLDT  (PREP_TRW + 512)       // 14848
#define PREP_BLOCKS (PREP_FOLDT + 32)      // 14880
#define PREP_SMEM_BYTES ((64 * 132 + 64 * 128) * 4)   // 66560 (foldT max)

__global__ __launch_bounds__(256) void prep_kernel(
    const float* __restrict__ queries, const float* __restrict__ keys,
    const float* __restrict__ values, uint32_t* __restrict__ Xh,
    const float* __restrict__ Wq, uint32_t* __restrict__ WqTh,
    const float* __restrict__ Wo, uint32_t* __restrict__ WoTh,
    const float* __restrict__ Wlk, const float* __restrict__ Wkr,
    uint32_t* __restrict__ WkTh,
    const float* __restrict__ Wlv, const float* __restrict__ Wvr,
    uint32_t* __restrict__ WvTh,
    const float* __restrict__ blk, const float* __restrict__ bkr,
    float* __restrict__ bk,
    const float* __restrict__ blv, const float* __restrict__ bvr,
    float* __restrict__ bv)
{
    extern __shared__ float psm[];
    const int bid = blockIdx.x;
    const int t = threadIdx.x;

    if (bid < PREP_CVT) {
        // ---- cvt: 2048 blocks per tensor ----
        const int z = bid >> 11;
        const int xb = bid & 2047;
        const float* in = (z == 0) ? queries : (z == 1) ? keys : values;
        uint32_t* Oh = Xh + (size_t)z * Mrows * 1024;
        const size_t idx = (size_t)xb * 256 + t;
        const size_t ebase = idx * 16;
        const float4 a = *(const float4*)(in + ebase);
        const float4 b = *(const float4*)(in + ebase + 4);
        const float4 c = *(const float4*)(in + ebase + 8);
        const float4 d = *(const float4*)(in + ebase + 12);
        uint32_t h[8];
        h[0] = packh(a.x, a.y); h[1] = packh(a.z, a.w);
        h[2] = packh(b.x, b.y); h[3] = packh(b.z, b.w);
        h[4] = packh(c.x, c.y); h[5] = packh(c.z, c.w);
        h[6] = packh(d.x, d.y); h[7] = packh(d.z, d.w);
        const size_t wbase = idx * 8;
        *(uint4*)(Oh + wbase)     = make_uint4(h[0], h[4], h[1], h[5]);
        *(uint4*)(Oh + wbase + 4) = make_uint4(h[2], h[6], h[3], h[7]);
    } else if (bid < PREP_TRW) {
        // ---- transposeW: 4096 blocks per weight ----
        const int r = bid - PREP_CVT;
        const int z = r >> 12;
        const int rr = r & 4095;
        const float* in = z ? Wo : Wq;
        uint32_t* Oh = z ? WoTh : WqTh;
        float (*tile)[33] = (float(*)[33])psm;
        const int bx = (rr & 63) * 32;
        const int by = (rr >> 6) * 32;
        const int tx = t & 31;
        const int ty = t >> 5;
        #pragma unroll
        for (int i = 0; i < 32; i += 8)
            tile[ty + i][tx] = in[(size_t)(by + ty + i) * Dmod + bx + tx];
        __syncthreads();
        const int c = tx;
        #pragma unroll
        for (int ii = 0; ii < 2; ii++) {
            const int uf = ty + 8 * ii;
            const int rb = uf & 7;
            const int phys = (by >> 1) + (uf & 8) + (((rb & 3) << 1) | (rb >> 2));
            Oh[(size_t)(bx + c) * 1024 + phys] =
                packh(tile[2 * uf][c], tile[2 * uf + 1][c]);
        }
    } else if (bid < PREP_FOLDT) {
        // ---- foldT: 256 blocks per weight ----
        const int r = bid - PREP_TRW;
        const int z = r >> 8;
        const int rr = r & 255;
        const float* Wl = z ? Wlv : Wlk;
        const float* Wr = z ? Wvr : Wkr;
        uint32_t* WTh = z ? WvTh : WkTh;
        float* sWl = psm;             // [l][132]
        float* sWr = psm + 64 * 132;  // [l][128]
        const int dblk = rr & 15;
        const int h    = rr >> 4;

        #pragma unroll
        for (int i = 0; i < 8; i++) {
            int u = t + i * 256;
            int l = u >> 5, c4 = u & 31;
            *(float4*)&sWr[l * 128 + c4 * 4] =
                *(const float4*)(Wr + l * DKk + c4 * 4);
        }
        #pragma unroll
        for (int i = 0; i < 8; i++) {
            int u = t + i * 256;
            int d = u >> 4, l4 = u & 15;
            float4 x = *(const float4*)(Wl + (size_t)(dblk * 128 + d) * (Hh * Ll)
                                        + h * Ll + l4 * 4);
            sWl[(l4 * 4 + 0) * 132 + d] = x.x;
            sWl[(l4 * 4 + 1) * 132 + d] = x.y;
            sWl[(l4 * 4 + 2) * 132 + d] = x.z;
            sWl[(l4 * 4 + 3) * 132 + d] = x.w;
        }
        __syncthreads();

        const int d8 = (t & 15) * 8;
        const int cg = t >> 4;
        float acc[8][8];
        #pragma unroll
        for (int dd = 0; dd < 8; dd++)
            #pragma unroll
            for (int j = 0; j < 8; j++) acc[dd][j] = 0.f;

        for (int l = 0; l < Ll; l++) {
            float4 a0 = *(float4*)&sWl[l * 132 + d8];
            float4 a1 = *(float4*)&sWl[l * 132 + d8 + 4];
            const float* wr = &sWr[l * 128 + cg * 8];
            #pragma unroll
            for (int j = 0; j < 8; j++) {
                float wv = wr[j];
                acc[0][j] += a0.x * wv;
                acc[1][j] += a0.y * wv;
                acc[2][j] += a0.z * wv;
                acc[3][j] += a0.w * wv;
                acc[4][j] += a1.x * wv;
                acc[5][j] += a1.y * wv;
                acc[6][j] += a1.z * wv;
                acc[7][j] += a1.w * wv;
            }
        }

        const int wb  = dblk * 64 + ((d8 >> 1) & ~7);
        const int off = t & 1;
        #pragma unroll
        for (int j = 0; j < 8; j++) {
            const int n = h * 128 + cg * 8 + j;
            #pragma unroll
            for (int i2 = 0; i2 < 4; i2++)
                WTh[(size_t)n * 1024 + wb + 2 * i2 + off] =
                    packh(acc[2 * i2][j], acc[2 * i2 + 1][j]);
        }
    } else {
        // ---- fold_b: 32 blocks (16 per bias) ----
        if (t < 128) {
            const int r = bid - PREP_FOLDT;
            const int z = r >> 4;
            const int h = r & 15;
            const float* bl = z ? blv : blk;
            const float* Wr = z ? Wvr : Wkr;
            const float* br = z ? bvr : bkr;
            float* beff = z ? bv : bk;
            float acc = br[t];
            #pragma unroll 16
            for (int l = 0; l < Ll; l++)
                acc += bl[h * Ll + l] * Wr[l * DKk + t];
            beff[h * DKk + t] = acc;
        }
    }
}

// ---------------------------------------------------------------------------
// fp16 tensor-core GEMM body: C = A @ WT^T + bias.
// MODE 0: fp32 out. MODE 1: K fp16 plane. MODE 2: V fp16 plane transposed.
// MODE 3: Q fp16 plane, pre-scaled for softmax (K layout).
// ---------------------------------------------------------------------------
#define G_BK 64
#define G_NK (Dmod / G_BK)            // 32
#define G_ST 36
#define G_OP_WORDS (128 * G_ST)
#define G_STAGE_WORDS (2 * G_OP_WORDS)
#define G_SMEM_BYTES (2 * G_STAGE_WORDS * 4)  // 73728

template<int MODE>
__device__ __forceinline__ void gemm_body(
    uint32_t* smw, uint32_t smem_base,
    const uint32_t* __restrict__ AhG, const uint32_t* __restrict__ WhG,
    const float* __restrict__ bias, float* __restrict__ C,
    uint32_t* __restrict__ P1,
    int m0, int n0)
{
    const int t    = threadIdx.x;
    const int wid  = t >> 5;
    const int lane = t & 31;
    const int g    = lane >> 2;
    const int tid4 = lane & 3;
    const int wm   = wid >> 2;
    const int wn   = wid & 3;

    float acc[4][4][4];
    #pragma unroll
    for (int mf = 0; mf < 4; mf++)
        #pragma unroll
        for (int nf = 0; nf < 4; nf++)
            #pragma unroll
            for (int r = 0; r < 4; r++) acc[mf][nf][r] = 0.f;

    auto load_stage = [&](int s, int k0) {
        const uint32_t aB = smem_base + (uint32_t)s * G_STAGE_WORDS * 4;
        const uint32_t bB = aB + G_OP_WORDS * 4;
        const int w0 = k0 >> 1;
        #pragma unroll
        for (int i = 0; i < 4; i++) {
            int u = t + i * 256;
            int row = u >> 3, c = u & 7;
            uint32_t doff = (uint32_t)(row * G_ST + c * 4) * 4;
            CP_ASYNC16(aB + doff, AhG + (size_t)(m0 + row) * 1024 + w0 + c * 4);
        }
        #pragma unroll
        for (int i = 0; i < 4; i++) {
            int u = t + i * 256;
            int row = u >> 3, c = u & 7;
            uint32_t doff = (uint32_t)(row * G_ST + c * 4) * 4;
            CP_ASYNC16(bB + doff, WhG + (size_t)(n0 + row) * 1024 + w0 + c * 4);
        }
    };

    load_stage(0, 0);
    CP_COMMIT();
    load_stage(1, G_BK);
    CP_COMMIT();

    for (int k = 0; k < G_NK; k++) {
        const int s = k & 1;
        CP_WAIT(1);
        __syncthreads();

        const uint32_t* sA = smw + (size_t)s * G_STAGE_WORDS;
        const uint32_t* sB = sA + G_OP_WORDS;

        #pragma unroll
        for (int ks = 0; ks < 4; ks++) {
            const int wk = 8 * ks + 2 * tid4;
            uint2 bq[4];
            #pragma unroll
            for (int nf = 0; nf < 4; nf++)
                bq[nf] = *(const uint2*)&sB[(wn * 32 + nf * 8 + g) * G_ST + wk];
            #pragma unroll
            for (int mf = 0; mf < 4; mf++) {
                const int ra = (wm * 64 + mf * 16 + g) * G_ST + wk;
                uint2 a0 = *(const uint2*)&sA[ra];
                uint2 a1 = *(const uint2*)&sA[ra + 8 * G_ST];
                uint32_t af[4] = {a0.x, a1.x, a0.y, a1.y};
                #pragma unroll
                for (int nf = 0; nf < 4; nf++)
                    mma_f16(acc[mf][nf], af, bq[nf].x, bq[nf].y);
            }
        }

        __syncthreads();
        if (k + 2 < G_NK) load_stage(s, (k + 2) * G_BK);
        CP_COMMIT();
    }

    #pragma unroll
    for (int mf = 0; mf < 4; mf++) {
        const int r0 = m0 + wm * 64 + mf * 16 + g;
        #pragma unroll
        for (int nf = 0; nf < 4; nf++) {
            const int c0 = n0 + wn * 32 + nf * 8 + 2 * tid4;
            const float b0 = bias[c0], b1 = bias[c0 + 1];
            float v0 = acc[mf][nf][0] + b0, v1 = acc[mf][nf][1] + b1;
            float v2 = acc[mf][nf][2] + b0, v3 = acc[mf][nf][3] + b1;
            if (MODE == 0) {
                *(float2*)(C + (size_t)r0 * Dmod + c0)       = make_float2(v0, v1);
                *(float2*)(C + (size_t)(r0 + 8) * Dmod + c0) = make_float2(v2, v3);
            } else if (MODE == 1 || MODE == 3) {
                const int bb = r0 >> 11, s2 = r0 & 2047, hh = c0 >> 7;
                const int j = (c0 & 127) >> 1;
                const int p = (j & ~7) | (2 * tid4 + (nf & 1));
                const size_t base = ((size_t)(bb * Hh + hh) * Sseq + s2) * 64 + p;
                if (MODE == 1) {
                    P1[base]       = packh(v0, v1);
                    P1[base + 512] = packh(v2, v3);
                } else {
                    const float qs = 0.088388347648318447f * 1.4426950408889634f;
                    P1[base]       = packh(v0 * qs, v1 * qs);
                    P1[base + 512] = packh(v2 * qs, v3 * qs);
                }
            } else {
                float u0 = __shfl_xor_sync(0xFFFFFFFFu, v0, 4);
                float u1 = __shfl_xor_sync(0xFFFFFFFFu, v1, 4);
                float u2 = __shfl_xor_sync(0xFFFFFFFFu, v2, 4);
                float u3 = __shfl_xor_sync(0xFFFFFFFFu, v3, 4);
                if ((g & 1) == 0) {
                    const int bb = r0 >> 11, s2 = r0 & 2047, hh = c0 >> 7;
                    const int d = c0 & 127;
                    const size_t base0 =
                        ((size_t)(bb * Hh + hh) * DKk + d) * 1024 + ((s2 & ~15) >> 1);
                    P1[base0 + g]            = packh(v0, u0);
                    P1[base0 + g + 1]        = packh(v2, u2);
                    P1[base0 + 1024 + g]     = packh(v1, u1);
                    P1[base0 + 1024 + g + 1] = packh(v3, u3);
                }
            }
        }
    }
}

// Merged Q/K/V projection (grid.z selects input/weight/epilogue)
__global__ __launch_bounds__(256, 2) void qkv_gemm_kernel(
    const uint32_t* __restrict__ Xh,
    const uint32_t* __restrict__ WqTh, const uint32_t* __restrict__ WkTh,
    const uint32_t* __restrict__ WvTh,
    const float* __restrict__ bq, const float* __restrict__ bk,
    const float* __restrict__ bv,
    uint32_t* __restrict__ Qh, uint32_t* __restrict__ Kh,
    uint32_t* __restrict__ Vh)
{
    extern __shared__ uint32_t smw[];
    const uint32_t smem_base = smem_u32(smw);
    const int m0 = blockIdx.y * 128;
    const int n0 = blockIdx.x * 128;
    const int z = blockIdx.z;
    const uint32_t* Ah = Xh + (size_t)z * Mrows * 1024;
    if (z == 0)
        gemm_body<3>(smw, smem_base, Ah, WqTh, bq, nullptr, Qh, m0, n0);
    else if (z == 1)
        gemm_body<1>(smw, smem_base, Ah, WkTh, bk, nullptr, Kh, m0, n0);
    else
        gemm_body<2>(smw, smem_base, Ah, WvTh, bv, nullptr, Vh, m0, n0);
}

__global__ __launch_bounds__(256, 2) void o_gemm_kernel(
    const uint32_t* __restrict__ Ah, const uint32_t* __restrict__ WTh,
    const float* __restrict__ bias, float* __restrict__ C)
{
    extern __shared__ uint32_t smw[];
    const uint32_t smem_base = smem_u32(smw);
    gemm_body<0>(smw, smem_base, Ah, WTh, bias, C, nullptr,
                 blockIdx.y * 128, blockIdx.x * 128);
}

// ---------------------------------------------------------------------------
// Tensor-core causal FA: Q single fp16 plane (pre-scaled), K/V fp16 planes.
// QK = q*k (1 MMA); PV = (phi+plo)*v (2 MMA).
// ---------------------------------------------------------------------------
#define KROWW 72
#define VROWW 40
#define FA_STAGE_WORDS (64 * KROWW + 128 * VROWW)   // 9728
#define FA_SMEM_BYTES (2 * FA_STAGE_WORDS * 4)      // 77824

__global__ __launch_bounds__(256, 1) void fa_tc_kernel(
    const uint32_t* __restrict__ QhG,
    const uint32_t* __restrict__ KhG, const uint32_t* __restrict__ VhG,
    uint32_t* __restrict__ OhG)
{
    extern __shared__ uint32_t su[];
    const uint32_t smem_base = smem_u32(su);

    const int qb = (int)gridDim.x - 1 - (int)blockIdx.x;
    const int h  = blockIdx.y;
    const int b  = blockIdx.z;
    const int t  = threadIdx.x;
    const int w  = t >> 5;
    const int lane = t & 31;
    const int g  = lane >> 2;
    const int t4 = lane & 3;
    const int q0 = qb * 128;

    const size_t bhS = (size_t)(b * Hh + h) * Sseq;
    const size_t bhD = (size_t)(b * Hh + h) * DKk;

    // Preload Q fragments (single plane, pre-scaled)
    uint32_t qh[8][4];
    {
        const size_t rg  = (bhS + q0 + w * 16 + g) * 64;
        const size_t rg8 = rg + 8 * 64;
        #pragma unroll
        for (int ks = 0; ks < 8; ks++) {
            const int wk = 8 * ks + 2 * t4;
            uint2 h0 = *(const uint2*)&QhG[rg + wk];
            uint2 h1 = *(const uint2*)&QhG[rg8 + wk];
            qh[ks][0] = h0.x; qh[ks][1] = h1.x; qh[ks][2] = h0.y; qh[ks][3] = h1.y;
        }
    }

    auto load_tile = [&](int stage, int kt) {
        const int kv0 = kt * 64;
        const uint32_t sb = smem_base + (uint32_t)stage * FA_STAGE_WORDS * 4;
        const uint32_t kB = sb;
        const uint32_t vB = sb + 64 * KROWW * 4;
        #pragma unroll
        for (int i = 0; i < 4; i++) {
            int u = t + i * 256;
            int row = u >> 4, w4 = (u & 15) * 4;
            CP_ASYNC16(kB + (uint32_t)(row * KROWW + w4) * 4,
                       KhG + (bhS + kv0 + row) * 64 + w4);
        }
        #pragma unroll
        for (int i = 0; i < 4; i++) {
            int u = t + i * 256;
            int row = u >> 3, w4 = (u & 7) * 4;
            CP_ASYNC16(vB + (uint32_t)(row * VROWW + w4) * 4,
                       VhG + (bhD + row) * 1024 + (kv0 >> 1) + w4);
        }
    };

    float oacc[16][4];
    #pragma unroll
    for (int nf = 0; nf < 16; nf++)
        #pragma unroll
        for (int r = 0; r < 4; r++) oacc[nf][r] = 0.f;

    float m0 = -1e30f, m1 = -1e30f, l0 = 0.f, l1 = 0.f;
    const int row0 = q0 + w * 16 + g;
    const int row1 = row0 + 8;

    const int ntiles = 2 * qb + 2;
    load_tile(0, 0);
    CP_COMMIT();

    for (int kt = 0; kt < ntiles; kt++) {
        const int st = kt & 1;
        const int kv0 = kt * 64;
        if (kt + 1 < ntiles) {
            load_tile(st ^ 1, kt + 1);
            CP_COMMIT();
            CP_WAIT(1);
        } else {
            CP_WAIT(0);
        }
        __syncthreads();

        const uint32_t* Ks = su + (size_t)st * FA_STAGE_WORDS;
        const uint32_t* Vs = Ks + 64 * KROWW;

        float acc[8][4];
        #pragma unroll
        for (int nf = 0; nf < 8; nf++)
            #pragma unroll
            for (int r = 0; r < 4; r++) acc[nf][r] = 0.f;

        #pragma unroll
        for (int ks = 0; ks < 8; ks++) {
            #pragma unroll
            for (int nf = 0; nf < 8; nf++) {
                const int r = (nf * 8 + g) * KROWW + 8 * ks + 2 * t4;
                uint2 kw = *(const uint2*)&Ks[r];
                mma_f16(acc[nf], qh[ks], kw.x, kw.y);
            }
        }

        if (kv0 + 63 > q0) {
            #pragma unroll
            for (int nf = 0; nf < 8; nf++) {
                const int c = kv0 + nf * 8 + 2 * t4;
                if (c     > row0) acc[nf][0] = -1e30f;
                if (c + 1 > row0) acc[nf][1] = -1e30f;
                if (c     > row1) acc[nf][2] = -1e30f;
                if (c + 1 > row1) acc[nf][3] = -1e30f;
            }
        }

        float mx0 = -1e30f, mx1 = -1e30f;
        #pragma unroll
        for (int nf = 0; nf < 8; nf++) {
            mx0 = fmaxf(mx0, fmaxf(acc[nf][0], acc[nf][1]));
            mx1 = fmaxf(mx1, fmaxf(acc[nf][2], acc[nf][3]));
        }
        mx0 = fmaxf(mx0, __shfl_xor_sync(0xFFFFFFFFu, mx0, 1));
        mx0 = fmaxf(mx0, __shfl_xor_sync(0xFFFFFFFFu, mx0, 2));
        mx1 = fmaxf(mx1, __shfl_xor_sync(0xFFFFFFFFu, mx1, 1));
        mx1 = fmaxf(mx1, __shfl_xor_sync(0xFFFFFFFFu, mx1, 2));

        const float mn0 = fmaxf(m0, mx0);
        const float mn1 = fmaxf(m1, mx1);
        const float cr0 = ex2(m0 - mn0);
        const float cr1 = ex2(m1 - mn1);

        float ps0 = 0.f, ps1 = 0.f;
        #pragma unroll
        for (int nf = 0; nf < 8; nf++) {
            acc[nf][0] = ex2(acc[nf][0] - mn0);
            acc[nf][1] = ex2(acc[nf][1] - mn0);
            acc[nf][2] = ex2(acc[nf][2] - mn1);
            acc[nf][3] = ex2(acc[nf][3] - mn1);
            ps0 += acc[nf][0] + acc[nf][1];
            ps1 += acc[nf][2] + acc[nf][3];
        }
        ps0 += __shfl_xor_sync(0xFFFFFFFFu, ps0, 1);
        ps0 += __shfl_xor_sync(0xFFFFFFFFu, ps0, 2);
        ps1 += __shfl_xor_sync(0xFFFFFFFFu, ps1, 1);
        ps1 += __shfl_xor_sync(0xFFFFFFFFu, ps1, 2);

        l0 = l0 * cr0 + ps0;
        l1 = l1 * cr1 + ps1;
        m0 = mn0;
        m1 = mn1;

        #pragma unroll
        for (int nf = 0; nf < 16; nf++) {
            oacc[nf][0] *= cr0;
            oacc[nf][1] *= cr0;
            oacc[nf][2] *= cr1;
            oacc[nf][3] *= cr1;
        }

        #pragma unroll
        for (int ks2 = 0; ks2 < 4; ks2++) {
            uint32_t ph[4], pl[4];
            split2h(acc[2 * ks2][0],     acc[2 * ks2][1],     ph[0], pl[0]);
            split2h(acc[2 * ks2][2],     acc[2 * ks2][3],     ph[1], pl[1]);
            split2h(acc[2 * ks2 + 1][0], acc[2 * ks2 + 1][1], ph[2], pl[2]);
            split2h(acc[2 * ks2 + 1][2], acc[2 * ks2 + 1][3], ph[3], pl[3]);
            #pragma unroll
            for (int nf = 0; nf < 16; nf++) {
                const int r = (nf * 8 + g) * VROWW + 8 * ks2 + 2 * t4;
                uint2 vw = *(const uint2*)&Vs[r];
                mma_f16(oacc[nf], ph, vw.x, vw.y);
                mma_f16(oacc[nf], pl, vw.x, vw.y);
            }
        }
        __syncthreads();
    }

    // epilogue: normalize, emit fp16 O plane (pair-permuted words)
    const float inv0 = 1.0f / l0;
    const float inv1 = 1.0f / l1;
    const size_t rowg  = (size_t)(b * Sseq + q0 + w * 16 + g) * 1024 + h * 64;
    const size_t rowg8 = rowg + 8 * 1024;
    #pragma unroll
    for (int nf = 0; nf < 16; nf++) {
        const int w_log = nf * 4 + t4;
        const int phys  = (w_log & ~7) + 2 * t4 + (nf & 1);
        OhG[rowg + phys]  = packh(oacc[nf][0] * inv0, oacc[nf][1] * inv0);
        OhG[rowg8 + phys] = packh(oacc[nf][2] * inv1, oacc[nf][3] * inv1);
    }
}

// ---------------------------------------------------------------------------
// kernel_launch
// ---------------------------------------------------------------------------
extern "C" void kernel_launch(void* const* d_in, const int* in_sizes, int n_in,
                              void* d_out, int out_size)
{
    const float* queries = (const float*)d_in[0];
    const float* keys    = (const float*)d_in[1];
    const float* values  = (const float*)d_in[2];
    const float* Wq      = (const float*)d_in[3];
    const float* bq      = (const float*)d_in[4];
    const float* Wlk     = (const float*)d_in[5];
    const float* blk     = (const float*)d_in[6];
    const float* Wlv     = (const float*)d_in[7];
    const float* blv     = (const float*)d_in[8];
    const float* Wkr     = (const float*)d_in[9];
    const float* bkr     = (const float*)d_in[10];
    const float* Wvr     = (const float*)d_in[11];
    const float* bvr     = (const float*)d_in[12];
    const float* Wo      = (const float*)d_in[13];
    const float* bo      = (const float*)d_in[14];
    float* out = (float*)d_out;

    float *bk, *bv;
    uint32_t *Xh, *Qh, *Kh, *Vh, *Oh;
    uint32_t *WqTh, *WkTh, *WvTh, *WoTh;
    cudaGetSymbolAddress((void**)&Xh,   g_Xh);
    cudaGetSymbolAddress((void**)&Qh,   g_Qh);
    cudaGetSymbolAddress((void**)&Kh,   g_Kh);
    cudaGetSymbolAddress((void**)&Vh,   g_Vh);
    cudaGetSymbolAddress((void**)&Oh,   g_Oh);
    cudaGetSymbolAddress((void**)&WqTh, g_WqTh);
    cudaGetSymbolAddress((void**)&WkTh, g_WkTh);
    cudaGetSymbolAddress((void**)&WvTh, g_WvTh);
    cudaGetSymbolAddress((void**)&WoTh, g_WoTh);
    cudaGetSymbolAddress((void**)&bk,   g_bk);
    cudaGetSymbolAddress((void**)&bv,   g_bv);

    cudaFuncSetAttribute(prep_kernel,
                         cudaFuncAttributeMaxDynamicSharedMemorySize, PREP_SMEM_BYTES);
    cudaFuncSetAttribute(qkv_gemm_kernel,
                         cudaFuncAttributeMaxDynamicSharedMemorySize, G_SMEM_BYTES);
    cudaFuncSetAttribute(o_gemm_kernel,
                         cudaFuncAttributeMaxDynamicSharedMemorySize, G_SMEM_BYTES);
    cudaFuncSetAttribute(fa_tc_kernel,
                         cudaFuncAttributeMaxDynamicSharedMemorySize, FA_SMEM_BYTES);

    // Unified preparation: cvt + transposeW + foldT + fold_b in one launch
    prep_kernel<<<PREP_BLOCKS, 256, PREP_SMEM_BYTES>>>(
        queries, keys, values, Xh,
        Wq, WqTh, Wo, WoTh,
        Wlk, Wkr, WkTh, Wlv, Wvr, WvTh,
        blk, bkr, bk, blv, bvr, bv);

    // Merged Q/K/V projections (Q -> scaled fp16 plane; K,V -> fp16 planes)
    qkv_gemm_kernel<<<dim3(Dmod / 128, Mrows / 128, 3), 256, G_SMEM_BYTES>>>(
        Xh, WqTh, WkTh, WvTh, bq, bk, bv, Qh, Kh, Vh);

    // Fused causal attention (Q 1-term, PV 2-term)
    fa_tc_kernel<<<dim3(Sseq / 128, Hh, Bsz), 256, FA_SMEM_BYTES>>>(
        Qh, Kh, Vh, Oh);

    // Output projection
    o_gemm_kernel<<<dim3(Dmod / 128, Mrows / 128), 256, G_SMEM_BYTES>>>(
        Oh, WoTh, bo, out);
}

// round 15
// speedup vs baseline: 2.2768x; 1.0549x over previous
#include <cuda_runtime.h>
#include <cuda_bf16.h>
#include <cuda_fp16.h>
#include <math.h>
#include <cstdint>

// Problem constants
#define Bsz   2
#define Sseq  2048
#define Dmod  2048
#define Hh    16
#define DKk   128
#define Ll    64
#define Mrows (Bsz * Sseq)   // 4096

// ---------------------------------------------------------------------------
// Device scratch
// ---------------------------------------------------------------------------
__device__ uint32_t g_Xh  [(size_t)3 * Mrows * 1024];  // fp16 activations q/k/v
__device__ uint32_t g_Qh  [(size_t)Mrows * 1024];      // Q fp16 (pre-scaled)
__device__ uint32_t g_Kh  [(size_t)Mrows * 1024];      // K fp16 [b,h,s][64 w]
__device__ uint32_t g_Vh  [(size_t)Mrows * 1024];      // V fp16 [b,h,d][1024 w]
__device__ uint32_t g_Oh  [(size_t)Mrows * 1024];      // FA out fp16 plane
__device__ uint32_t g_WqTh[(size_t)Dmod * 1024];       // fp16 weight planes
__device__ uint32_t g_WkTh[(size_t)Dmod * 1024];
__device__ uint32_t g_WvTh[(size_t)Dmod * 1024];
__device__ uint32_t g_WoTh[(size_t)Dmod * 1024];
__device__ float    g_bk[Dmod];
__device__ float    g_bv[Dmod];

// ---------------------------------------------------------------------------
// Helpers
// ---------------------------------------------------------------------------
__device__ __forceinline__ uint32_t smem_u32(const void* p) {
    uint32_t a;
    asm("{ .reg .u64 t; cvta.to.shared.u64 t, %1; cvt.u32.u64 %0, t; }"
        : "=r"(a) : "l"(p));
    return a;
}

#define CP_ASYNC16(dst, src) \
    asm volatile("cp.async.cg.shared.global [%0], [%1], 16;" \
        :: "r"((uint32_t)(dst)), "l"(src) : "memory")
#define CP_COMMIT() asm volatile("cp.async.commit_group;" ::: "memory")
#define CP_WAIT(n)  asm volatile("cp.async.wait_group %0;" :: "n"(n) : "memory")

// pack two fp32 into fp16x2: e0 -> lower half (first k element)
__device__ __forceinline__ uint32_t packh(float e0, float e1) {
    uint32_t r;
    asm("cvt.rn.f16x2.f32 %0, %1, %2;" : "=r"(r) : "f"(e1), "f"(e0));
    return r;
}

__device__ __forceinline__ void mma_f16(float* c, const uint32_t* a,
                                        uint32_t b0, uint32_t b1) {
    asm volatile(
        "mma.sync.aligned.m16n8k16.row.col.f32.f16.f16.f32 "
        "{%0,%1,%2,%3}, {%4,%5,%6,%7}, {%8,%9}, {%0,%1,%2,%3};"
        : "+f"(c[0]), "+f"(c[1]), "+f"(c[2]), "+f"(c[3])
        : "r"(a[0]), "r"(a[1]), "r"(a[2]), "r"(a[3]), "r"(b0), "r"(b1));
}

__device__ __forceinline__ float ex2(float x) {
    float y;
    asm("ex2.approx.ftz.f32 %0, %1;" : "=f"(y) : "f"(x));
    return y;
}

// ---------------------------------------------------------------------------
// Unified prep kernel: flat grid, role by block range.
//   [0, 6144)            cvt: activations -> fp16 planes (DRAM-bound, first)
//   [6144, 14336)        transposeW (Wq, Wo)
//   [14336, 14848)       foldT (K/V weights)
//   [14848, 14880)       fold_b
// ---------------------------------------------------------------------------
#define PREP_CVT    6144
#define PREP_TRW    (PREP_CVT + 8192)      // 14336
#define PREP_FOLDT  (PREP_TRW + 512)       // 14848
#define PREP_BLOCKS (PREP_FOLDT + 32)      // 14880
#define PREP_SMEM_BYTES ((64 * 132 + 64 * 128) * 4)   // 66560 (foldT max)

__global__ __launch_bounds__(256) void prep_kernel(
    const float* __restrict__ queries, const float* __restrict__ keys,
    const float* __restrict__ values, uint32_t* __restrict__ Xh,
    const float* __restrict__ Wq, uint32_t* __restrict__ WqTh,
    const float* __restrict__ Wo, uint32_t* __restrict__ WoTh,
    const float* __restrict__ Wlk, const float* __restrict__ Wkr,
    uint32_t* __restrict__ WkTh,
    const float* __restrict__ Wlv, const float* __restrict__ Wvr,
    uint32_t* __restrict__ WvTh,
    const float* __restrict__ blk, const float* __restrict__ bkr,
    float* __restrict__ bk,
    const float* __restrict__ blv, const float* __restrict__ bvr,
    float* __restrict__ bv)
{
    extern __shared__ float psm[];
    const int bid = blockIdx.x;
    const int t = threadIdx.x;

    if (bid < PREP_CVT) {
        // ---- cvt: 2048 blocks per tensor ----
        const int z = bid >> 11;
        const int xb = bid & 2047;
        const float* in = (z == 0) ? queries : (z == 1) ? keys : values;
        uint32_t* Oh = Xh + (size_t)z * Mrows * 1024;
        const size_t idx = (size_t)xb * 256 + t;
        const size_t ebase = idx * 16;
        const float4 a = *(const float4*)(in + ebase);
        const float4 b = *(const float4*)(in + ebase + 4);
        const float4 c = *(const float4*)(in + ebase + 8);
        const float4 d = *(const float4*)(in + ebase + 12);
        uint32_t h[8];
        h[0] = packh(a.x, a.y); h[1] = packh(a.z, a.w);
        h[2] = packh(b.x, b.y); h[3] = packh(b.z, b.w);
        h[4] = packh(c.x, c.y); h[5] = packh(c.z, c.w);
        h[6] = packh(d.x, d.y); h[7] = packh(d.z, d.w);
        const size_t wbase = idx * 8;
        *(uint4*)(Oh + wbase)     = make_uint4(h[0], h[4], h[1], h[5]);
        *(uint4*)(Oh + wbase + 4) = make_uint4(h[2], h[6], h[3], h[7]);
    } else if (bid < PREP_TRW) {
        // ---- transposeW: 4096 blocks per weight ----
        const int r = bid - PREP_CVT;
        const int z = r >> 12;
        const int rr = r & 4095;
        const float* in = z ? Wo : Wq;
        uint32_t* Oh = z ? WoTh : WqTh;
        float (*tile)[33] = (float(*)[33])psm;
        const int bx = (rr & 63) * 32;
        const int by = (rr >> 6) * 32;
        const int tx = t & 31;
        const int ty = t >> 5;
        #pragma unroll
        for (int i = 0; i < 32; i += 8)
            tile[ty + i][tx] = in[(size_t)(by + ty + i) * Dmod + bx + tx];
        __syncthreads();
        const int c = tx;
        #pragma unroll
        for (int ii = 0; ii < 2; ii++) {
            const int uf = ty + 8 * ii;
            const int rb = uf & 7;
            const int phys = (by >> 1) + (uf & 8) + (((rb & 3) << 1) | (rb >> 2));
            Oh[(size_t)(bx + c) * 1024 + phys] =
                packh(tile[2 * uf][c], tile[2 * uf + 1][c]);
        }
    } else if (bid < PREP_FOLDT) {
        // ---- foldT: 256 blocks per weight ----
        const int r = bid - PREP_TRW;
        const int z = r >> 8;
        const int rr = r & 255;
        const float* Wl = z ? Wlv : Wlk;
        const float* Wr = z ? Wvr : Wkr;
        uint32_t* WTh = z ? WvTh : WkTh;
        float* sWl = psm;             // [l][132]
        float* sWr = psm + 64 * 132;  // [l][128]
        const int dblk = rr & 15;
        const int h    = rr >> 4;

        #pragma unroll
        for (int i = 0; i < 8; i++) {
            int u = t + i * 256;
            int l = u >> 5, c4 = u & 31;
            *(float4*)&sWr[l * 128 + c4 * 4] =
                *(const float4*)(Wr + l * DKk + c4 * 4);
        }
        #pragma unroll
        for (int i = 0; i < 8; i++) {
            int u = t + i * 256;
            int d = u >> 4, l4 = u & 15;
            float4 x = *(const float4*)(Wl + (size_t)(dblk * 128 + d) * (Hh * Ll)
                                        + h * Ll + l4 * 4);
            sWl[(l4 * 4 + 0) * 132 + d] = x.x;
            sWl[(l4 * 4 + 1) * 132 + d] = x.y;
            sWl[(l4 * 4 + 2) * 132 + d] = x.z;
            sWl[(l4 * 4 + 3) * 132 + d] = x.w;
        }
        __syncthreads();

        const int d8 = (t & 15) * 8;
        const int cg = t >> 4;
        float acc[8][8];
        #pragma unroll
        for (int dd = 0; dd < 8; dd++)
            #pragma unroll
            for (int j = 0; j < 8; j++) acc[dd][j] = 0.f;

        for (int l = 0; l < Ll; l++) {
            float4 a0 = *(float4*)&sWl[l * 132 + d8];
            float4 a1 = *(float4*)&sWl[l * 132 + d8 + 4];
            const float* wr = &sWr[l * 128 + cg * 8];
            #pragma unroll
            for (int j = 0; j < 8; j++) {
                float wv = wr[j];
                acc[0][j] += a0.x * wv;
                acc[1][j] += a0.y * wv;
                acc[2][j] += a0.z * wv;
                acc[3][j] += a0.w * wv;
                acc[4][j] += a1.x * wv;
                acc[5][j] += a1.y * wv;
                acc[6][j] += a1.z * wv;
                acc[7][j] += a1.w * wv;
            }
        }

        const int wb  = dblk * 64 + ((d8 >> 1) & ~7);
        const int off = t & 1;
        #pragma unroll
        for (int j = 0; j < 8; j++) {
            const int n = h * 128 + cg * 8 + j;
            #pragma unroll
            for (int i2 = 0; i2 < 4; i2++)
                WTh[(size_t)n * 1024 + wb + 2 * i2 + off] =
                    packh(acc[2 * i2][j], acc[2 * i2 + 1][j]);
        }
    } else {
        // ---- fold_b: 32 blocks (16 per bias) ----
        if (t < 128) {
            const int r = bid - PREP_FOLDT;
            const int z = r >> 4;
            const int h = r & 15;
            const float* bl = z ? blv : blk;
            const float* Wr = z ? Wvr : Wkr;
            const float* br = z ? bvr : bkr;
            float* beff = z ? bv : bk;
            float acc = br[t];
            #pragma unroll 16
            for (int l = 0; l < Ll; l++)
                acc += bl[h * Ll + l] * Wr[l * DKk + t];
            beff[h * DKk + t] = acc;
        }
    }
}

// ---------------------------------------------------------------------------
// fp16 tensor-core GEMM body: C = A @ WT^T + bias.
// MODE 0: fp32 out. MODE 1: K fp16 plane. MODE 2: V fp16 plane transposed.
// MODE 3: Q fp16 plane, pre-scaled for softmax (K layout).
// ---------------------------------------------------------------------------
#define G_BK 64
#define G_NK (Dmod / G_BK)            // 32
#define G_ST 36
#define G_OP_WORDS (128 * G_ST)
#define G_STAGE_WORDS (2 * G_OP_WORDS)
#define G_SMEM_BYTES (2 * G_STAGE_WORDS * 4)  // 73728

template<int MODE>
__device__ __forceinline__ void gemm_body(
    uint32_t* smw, uint32_t smem_base,
    const uint32_t* __restrict__ AhG, const uint32_t* __restrict__ WhG,
    const float* __restrict__ bias, float* __restrict__ C,
    uint32_t* __restrict__ P1,
    int m0, int n0)
{
    const int t    = threadIdx.x;
    const int wid  = t >> 5;
    const int lane = t & 31;
    const int g    = lane >> 2;
    const int tid4 = lane & 3;
    const int wm   = wid >> 2;
    const int wn   = wid & 3;

    float acc[4][4][4];
    #pragma unroll
    for (int mf = 0; mf < 4; mf++)
        #pragma unroll
        for (int nf = 0; nf < 4; nf++)
            #pragma unroll
            for (int r = 0; r < 4; r++) acc[mf][nf][r] = 0.f;

    auto load_stage = [&](int s, int k0) {
        const uint32_t aB = smem_base + (uint32_t)s * G_STAGE_WORDS * 4;
        const uint32_t bB = aB + G_OP_WORDS * 4;
        const int w0 = k0 >> 1;
        #pragma unroll
        for (int i = 0; i < 4; i++) {
            int u = t + i * 256;
            int row = u >> 3, c = u & 7;
            uint32_t doff = (uint32_t)(row * G_ST + c * 4) * 4;
            CP_ASYNC16(aB + doff, AhG + (size_t)(m0 + row) * 1024 + w0 + c * 4);
        }
        #pragma unroll
        for (int i = 0; i < 4; i++) {
            int u = t + i * 256;
            int row = u >> 3, c = u & 7;
            uint32_t doff = (uint32_t)(row * G_ST + c * 4) * 4;
            CP_ASYNC16(bB + doff, WhG + (size_t)(n0 + row) * 1024 + w0 + c * 4);
        }
    };

    load_stage(0, 0);
    CP_COMMIT();
    load_stage(1, G_BK);
    CP_COMMIT();

    for (int k = 0; k < G_NK; k++) {
        const int s = k & 1;
        CP_WAIT(1);
        __syncthreads();

        const uint32_t* sA = smw + (size_t)s * G_STAGE_WORDS;
        const uint32_t* sB = sA + G_OP_WORDS;

        #pragma unroll
        for (int ks = 0; ks < 4; ks++) {
            const int wk = 8 * ks + 2 * tid4;
            uint2 bq[4];
            #pragma unroll
            for (int nf = 0; nf < 4; nf++)
                bq[nf] = *(const uint2*)&sB[(wn * 32 + nf * 8 + g) * G_ST + wk];
            #pragma unroll
            for (int mf = 0; mf < 4; mf++) {
                const int ra = (wm * 64 + mf * 16 + g) * G_ST + wk;
                uint2 a0 = *(const uint2*)&sA[ra];
                uint2 a1 = *(const uint2*)&sA[ra + 8 * G_ST];
                uint32_t af[4] = {a0.x, a1.x, a0.y, a1.y};
                #pragma unroll
                for (int nf = 0; nf < 4; nf++)
                    mma_f16(acc[mf][nf], af, bq[nf].x, bq[nf].y);
            }
        }

        __syncthreads();
        if (k + 2 < G_NK) load_stage(s, (k + 2) * G_BK);
        CP_COMMIT();
    }

    #pragma unroll
    for (int mf = 0; mf < 4; mf++) {
        const int r0 = m0 + wm * 64 + mf * 16 + g;
        #pragma unroll
        for (int nf = 0; nf < 4; nf++) {
            const int c0 = n0 + wn * 32 + nf * 8 + 2 * tid4;
            const float b0 = bias[c0], b1 = bias[c0 + 1];
            float v0 = acc[mf][nf][0] + b0, v1 = acc[mf][nf][1] + b1;
            float v2 = acc[mf][nf][2] + b0, v3 = acc[mf][nf][3] + b1;
            if (MODE == 0) {
                *(float2*)(C + (size_t)r0 * Dmod + c0)       = make_float2(v0, v1);
                *(float2*)(C + (size_t)(r0 + 8) * Dmod + c0) = make_float2(v2, v3);
            } else if (MODE == 1 || MODE == 3) {
                const int bb = r0 >> 11, s2 = r0 & 2047, hh = c0 >> 7;
                const int j = (c0 & 127) >> 1;
                const int p = (j & ~7) | (2 * tid4 + (nf & 1));
                const size_t base = ((size_t)(bb * Hh + hh) * Sseq + s2) * 64 + p;
                if (MODE == 1) {
                    P1[base]       = packh(v0, v1);
                    P1[base + 512] = packh(v2, v3);
                } else {
                    const float qs = 0.088388347648318447f * 1.4426950408889634f;
                    P1[base]       = packh(v0 * qs, v1 * qs);
                    P1[base + 512] = packh(v2 * qs, v3 * qs);
                }
            } else {
                float u0 = __shfl_xor_sync(0xFFFFFFFFu, v0, 4);
                float u1 = __shfl_xor_sync(0xFFFFFFFFu, v1, 4);
                float u2 = __shfl_xor_sync(0xFFFFFFFFu, v2, 4);
                float u3 = __shfl_xor_sync(0xFFFFFFFFu, v3, 4);
                if ((g & 1) == 0) {
                    const int bb = r0 >> 11, s2 = r0 & 2047, hh = c0 >> 7;
                    const int d = c0 & 127;
                    const size_t base0 =
                        ((size_t)(bb * Hh + hh) * DKk + d) * 1024 + ((s2 & ~15) >> 1);
                    P1[base0 + g]            = packh(v0, u0);
                    P1[base0 + g + 1]        = packh(v2, u2);
                    P1[base0 + 1024 + g]     = packh(v1, u1);
                    P1[base0 + 1024 + g + 1] = packh(v3, u3);
                }
            }
        }
    }
}

// Merged Q/K/V projection (grid.z selects input/weight/epilogue)
__global__ __launch_bounds__(256, 2) void qkv_gemm_kernel(
    const uint32_t* __restrict__ Xh,
    const uint32_t* __restrict__ WqTh, const uint32_t* __restrict__ WkTh,
    const uint32_t* __restrict__ WvTh,
    const float* __restrict__ bq, const float* __restrict__ bk,
    const float* __restrict__ bv,
    uint32_t* __restrict__ Qh, uint32_t* __restrict__ Kh,
    uint32_t* __restrict__ Vh)
{
    extern __shared__ uint32_t smw[];
    const uint32_t smem_base = smem_u32(smw);
    const int m0 = blockIdx.y * 128;
    const int n0 = blockIdx.x * 128;
    const int z = blockIdx.z;
    const uint32_t* Ah = Xh + (size_t)z * Mrows * 1024;
    if (z == 0)
        gemm_body<3>(smw, smem_base, Ah, WqTh, bq, nullptr, Qh, m0, n0);
    else if (z == 1)
        gemm_body<1>(smw, smem_base, Ah, WkTh, bk, nullptr, Kh, m0, n0);
    else
        gemm_body<2>(smw, smem_base, Ah, WvTh, bv, nullptr, Vh, m0, n0);
}

__global__ __launch_bounds__(256, 2) void o_gemm_kernel(
    const uint32_t* __restrict__ Ah, const uint32_t* __restrict__ WTh,
    const float* __restrict__ bias, float* __restrict__ C)
{
    extern __shared__ uint32_t smw[];
    const uint32_t smem_base = smem_u32(smw);
    gemm_body<0>(smw, smem_base, Ah, WTh, bias, C, nullptr,
                 blockIdx.y * 128, blockIdx.x * 128);
}

// ---------------------------------------------------------------------------
// Tensor-core causal FA: Q single fp16 plane (pre-scaled), K/V fp16 planes.
// QK = q*k (1 MMA); PV = p*v (1 MMA, P fp16).
// ---------------------------------------------------------------------------
#define KROWW 72
#define VROWW 40
#define FA_STAGE_WORDS (64 * KROWW + 128 * VROWW)   // 9728
#define FA_SMEM_BYTES (2 * FA_STAGE_WORDS * 4)      // 77824

__global__ __launch_bounds__(256, 1) void fa_tc_kernel(
    const uint32_t* __restrict__ QhG,
    const uint32_t* __restrict__ KhG, const uint32_t* __restrict__ VhG,
    uint32_t* __restrict__ OhG)
{
    extern __shared__ uint32_t su[];
    const uint32_t smem_base = smem_u32(su);

    const int qb = (int)gridDim.x - 1 - (int)blockIdx.x;
    const int h  = blockIdx.y;
    const int b  = blockIdx.z;
    const int t  = threadIdx.x;
    const int w  = t >> 5;
    const int lane = t & 31;
    const int g  = lane >> 2;
    const int t4 = lane & 3;
    const int q0 = qb * 128;

    const size_t bhS = (size_t)(b * Hh + h) * Sseq;
    const size_t bhD = (size_t)(b * Hh + h) * DKk;

    // Preload Q fragments (single plane, pre-scaled)
    uint32_t qh[8][4];
    {
        const size_t rg  = (bhS + q0 + w * 16 + g) * 64;
        const size_t rg8 = rg + 8 * 64;
        #pragma unroll
        for (int ks = 0; ks < 8; ks++) {
            const int wk = 8 * ks + 2 * t4;
            uint2 h0 = *(const uint2*)&QhG[rg + wk];
            uint2 h1 = *(const uint2*)&QhG[rg8 + wk];
            qh[ks][0] = h0.x; qh[ks][1] = h1.x; qh[ks][2] = h0.y; qh[ks][3] = h1.y;
        }
    }

    auto load_tile = [&](int stage, int kt) {
        const int kv0 = kt * 64;
        const uint32_t sb = smem_base + (uint32_t)stage * FA_STAGE_WORDS * 4;
        const uint32_t kB = sb;
        const uint32_t vB = sb + 64 * KROWW * 4;
        #pragma unroll
        for (int i = 0; i < 4; i++) {
            int u = t + i * 256;
            int row = u >> 4, w4 = (u & 15) * 4;
            CP_ASYNC16(kB + (uint32_t)(row * KROWW + w4) * 4,
                       KhG + (bhS + kv0 + row) * 64 + w4);
        }
        #pragma unroll
        for (int i = 0; i < 4; i++) {
            int u = t + i * 256;
            int row = u >> 3, w4 = (u & 7) * 4;
            CP_ASYNC16(vB + (uint32_t)(row * VROWW + w4) * 4,
                       VhG + (bhD + row) * 1024 + (kv0 >> 1) + w4);
        }
    };

    float oacc[16][4];
    #pragma unroll
    for (int nf = 0; nf < 16; nf++)
        #pragma unroll
        for (int r = 0; r < 4; r++) oacc[nf][r] = 0.f;

    float m0 = -1e30f, m1 = -1e30f, l0 = 0.f, l1 = 0.f;
    const int row0 = q0 + w * 16 + g;
    const int row1 = row0 + 8;

    const int ntiles = 2 * qb + 2;
    load_tile(0, 0);
    CP_COMMIT();

    for (int kt = 0; kt < ntiles; kt++) {
        const int st = kt & 1;
        const int kv0 = kt * 64;
        if (kt + 1 < ntiles) {
            load_tile(st ^ 1, kt + 1);
            CP_COMMIT();
            CP_WAIT(1);
        } else {
            CP_WAIT(0);
        }
        __syncthreads();

        const uint32_t* Ks = su + (size_t)st * FA_STAGE_WORDS;
        const uint32_t* Vs = Ks + 64 * KROWW;

        float acc[8][4];
        #pragma unroll
        for (int nf = 0; nf < 8; nf++)
            #pragma unroll
            for (int r = 0; r < 4; r++) acc[nf][r] = 0.f;

        #pragma unroll
        for (int ks = 0; ks < 8; ks++) {
            #pragma unroll
            for (int nf = 0; nf < 8; nf++) {
                const int r = (nf * 8 + g) * KROWW + 8 * ks + 2 * t4;
                uint2 kw = *(const uint2*)&Ks[r];
                mma_f16(acc[nf], qh[ks], kw.x, kw.y);
            }
        }

        if (kv0 + 63 > q0) {
            #pragma unroll
            for (int nf = 0; nf < 8; nf++) {
                const int c = kv0 + nf * 8 + 2 * t4;
                if (c     > row0) acc[nf][0] = -1e30f;
                if (c + 1 > row0) acc[nf][1] = -1e30f;
                if (c     > row1) acc[nf][2] = -1e30f;
                if (c + 1 > row1) acc[nf][3] = -1e30f;
            }
        }

        float mx0 = -1e30f, mx1 = -1e30f;
        #pragma unroll
        for (int nf = 0; nf < 8; nf++) {
            mx0 = fmaxf(mx0, fmaxf(acc[nf][0], acc[nf][1]));
            mx1 = fmaxf(mx1, fmaxf(acc[nf][2], acc[nf][3]));
        }
        mx0 = fmaxf(mx0, __shfl_xor_sync(0xFFFFFFFFu, mx0, 1));
        mx0 = fmaxf(mx0, __shfl_xor_sync(0xFFFFFFFFu, mx0, 2));
        mx1 = fmaxf(mx1, __shfl_xor_sync(0xFFFFFFFFu, mx1, 1));
        mx1 = fmaxf(mx1, __shfl_xor_sync(0xFFFFFFFFu, mx1, 2));

        const float mn0 = fmaxf(m0, mx0);
        const float mn1 = fmaxf(m1, mx1);
        const float cr0 = ex2(m0 - mn0);
        const float cr1 = ex2(m1 - mn1);

        float ps0 = 0.f, ps1 = 0.f;
        #pragma unroll
        for (int nf = 0; nf < 8; nf++) {
            acc[nf][0] = ex2(acc[nf][0] - mn0);
            acc[nf][1] = ex2(acc[nf][1] - mn0);
            acc[nf][2] = ex2(acc[nf][2] - mn1);
            acc[nf][3] = ex2(acc[nf][3] - mn1);
            ps0 += acc[nf][0] + acc[nf][1];
            ps1 += acc[nf][2] + acc[nf][3];
        }
        ps0 += __shfl_xor_sync(0xFFFFFFFFu, ps0, 1);
        ps0 += __shfl_xor_sync(0xFFFFFFFFu, ps0, 2);
        ps1 += __shfl_xor_sync(0xFFFFFFFFu, ps1, 1);
        ps1 += __shfl_xor_sync(0xFFFFFFFFu, ps1, 2);

        l0 = l0 * cr0 + ps0;
        l1 = l1 * cr1 + ps1;
        m0 = mn0;
        m1 = mn1;

        #pragma unroll
        for (int nf = 0; nf < 16; nf++) {
            oacc[nf][0] *= cr0;
            oacc[nf][1] *= cr0;
            oacc[nf][2] *= cr1;
            oacc[nf][3] *= cr1;
        }

        // ---- P @ V, P single fp16 ----
        #pragma unroll
        for (int ks2 = 0; ks2 < 4; ks2++) {
            uint32_t ph[4];
            ph[0] = packh(acc[2 * ks2][0],     acc[2 * ks2][1]);
            ph[1] = packh(acc[2 * ks2][2],     acc[2 * ks2][3]);
            ph[2] = packh(acc[2 * ks2 + 1][0], acc[2 * ks2 + 1][1]);
            ph[3] = packh(acc[2 * ks2 + 1][2], acc[2 * ks2 + 1][3]);
            #pragma unroll
            for (int nf = 0; nf < 16; nf++) {
                const int r = (nf * 8 + g) * VROWW + 8 * ks2 + 2 * t4;
                uint2 vw = *(const uint2*)&Vs[r];
                mma_f16(oacc[nf], ph, vw.x, vw.y);
            }
        }
        __syncthreads();
    }

    // epilogue: normalize, emit fp16 O plane (pair-permuted words)
    const float inv0 = 1.0f / l0;
    const float inv1 = 1.0f / l1;
    const size_t rowg  = (size_t)(b * Sseq + q0 + w * 16 + g) * 1024 + h * 64;
    const size_t rowg8 = rowg + 8 * 1024;
    #pragma unroll
    for (int nf = 0; nf < 16; nf++) {
        const int w_log = nf * 4 + t4;
        const int phys  = (w_log & ~7) + 2 * t4 + (nf & 1);
        OhG[rowg + phys]  = packh(oacc[nf][0] * inv0, oacc[nf][1] * inv0);
        OhG[rowg8 + phys] = packh(oacc[nf][2] * inv1, oacc[nf][3] * inv1);
    }
}

// ---------------------------------------------------------------------------
// kernel_launch
// ---------------------------------------------------------------------------
extern "C" void kernel_launch(void* const* d_in, const int* in_sizes, int n_in,
                              void* d_out, int out_size)
{
    const float* queries = (const float*)d_in[0];
    const float* keys    = (const float*)d_in[1];
    const float* values  = (const float*)d_in[2];
    const float* Wq      = (const float*)d_in[3];
    const float* bq      = (const float*)d_in[4];
    const float* Wlk     = (const float*)d_in[5];
    const float* blk     = (const float*)d_in[6];
    const float* Wlv     = (const float*)d_in[7];
    const float* blv     = (const float*)d_in[8];
    const float* Wkr     = (const float*)d_in[9];
    const float* bkr     = (const float*)d_in[10];
    const float* Wvr     = (const float*)d_in[11];
    const float* bvr     = (const float*)d_in[12];
    const float* Wo      = (const float*)d_in[13];
    const float* bo      = (const float*)d_in[14];
    float* out = (float*)d_out;

    float *bk, *bv;
    uint32_t *Xh, *Qh, *Kh, *Vh, *Oh;
    uint32_t *WqTh, *WkTh, *WvTh, *WoTh;
    cudaGetSymbolAddress((void**)&Xh,   g_Xh);
    cudaGetSymbolAddress((void**)&Qh,   g_Qh);
    cudaGetSymbolAddress((void**)&Kh,   g_Kh);
    cudaGetSymbolAddress((void**)&Vh,   g_Vh);
    cudaGetSymbolAddress((void**)&Oh,   g_Oh);
    cudaGetSymbolAddress((void**)&WqTh, g_WqTh);
    cudaGetSymbolAddress((void**)&WkTh, g_WkTh);
    cudaGetSymbolAddress((void**)&WvTh, g_WvTh);
    cudaGetSymbolAddress((void**)&WoTh, g_WoTh);
    cudaGetSymbolAddress((void**)&bk,   g_bk);
    cudaGetSymbolAddress((void**)&bv,   g_bv);

    cudaFuncSetAttribute(prep_kernel,
                         cudaFuncAttributeMaxDynamicSharedMemorySize, PREP_SMEM_BYTES);
    cudaFuncSetAttribute(qkv_gemm_kernel,
                         cudaFuncAttributeMaxDynamicSharedMemorySize, G_SMEM_BYTES);
    cudaFuncSetAttribute(o_gemm_kernel,
                         cudaFuncAttributeMaxDynamicSharedMemorySize, G_SMEM_BYTES);
    cudaFuncSetAttribute(fa_tc_kernel,
                         cudaFuncAttributeMaxDynamicSharedMemorySize, FA_SMEM_BYTES);

    // Unified preparation: cvt + transposeW + foldT + fold_b in one launch
    prep_kernel<<<PREP_BLOCKS, 256, PREP_SMEM_BYTES>>>(
        queries, keys, values, Xh,
        Wq, WqTh, Wo, WoTh,
        Wlk, Wkr, WkTh, Wlv, Wvr, WvTh,
        blk, bkr, bk, blv, bvr, bv);

    // Merged Q/K/V projections (Q -> scaled fp16 plane; K,V -> fp16 planes)
    qkv_gemm_kernel<<<dim3(Dmod / 128, Mrows / 128, 3), 256, G_SMEM_BYTES>>>(
        Xh, WqTh, WkTh, WvTh, bq, bk, bv, Qh, Kh, Vh);

    // Fused causal attention (all single-term fp16 MMAs)
    fa_tc_kernel<<<dim3(Sseq / 128, Hh, Bsz), 256, FA_SMEM_BYTES>>>(
        Qh, Kh, Vh, Oh);

    // Output projection
    o_gemm_kernel<<<dim3(Dmod / 128, Mrows / 128), 256, G_SMEM_BYTES>>>(
        Oh, WoTh, bo, out);
}

// round 16
// speedup vs baseline: 2.4158x; 1.0610x over previous
#include <cuda_runtime.h>
#include <cuda_bf16.h>
#include <cuda_fp16.h>
#include <math.h>
#include <cstdint>

// Problem constants
#define Bsz   2
#define Sseq  2048
#define Dmod  2048
#define Hh    16
#define DKk   128
#define Ll    64
#define Mrows (Bsz * Sseq)   // 4096

// ---------------------------------------------------------------------------
// Device scratch
// ---------------------------------------------------------------------------
__device__ uint32_t g_Xh  [(size_t)3 * Mrows * 1024];  // fp16 activations q/k/v
__device__ uint32_t g_Qh  [(size_t)Mrows * 1024];      // Q fp16 (pre-scaled)
__device__ uint32_t g_Kh  [(size_t)Mrows * 1024];      // K fp16 [b,h,s][64 w]
__device__ uint32_t g_Vh  [(size_t)Mrows * 1024];      // V fp16 [b,h,d][1024 w]
__device__ uint32_t g_Oh  [(size_t)Mrows * 1024];      // FA out fp16 plane
__device__ uint32_t g_WqTh[(size_t)Dmod * 1024];       // fp16 weight planes
__device__ uint32_t g_WkTh[(size_t)Dmod * 1024];
__device__ uint32_t g_WvTh[(size_t)Dmod * 1024];
__device__ uint32_t g_WoTh[(size_t)Dmod * 1024];
__device__ float    g_bk[Dmod];
__device__ float    g_bv[Dmod];

// ---------------------------------------------------------------------------
// Helpers
// ---------------------------------------------------------------------------
__device__ __forceinline__ uint32_t smem_u32(const void* p) {
    uint32_t a;
    asm("{ .reg .u64 t; cvta.to.shared.u64 t, %1; cvt.u32.u64 %0, t; }"
        : "=r"(a) : "l"(p));
    return a;
}

#define CP_ASYNC16(dst, src) \
    asm volatile("cp.async.cg.shared.global [%0], [%1], 16;" \
        :: "r"((uint32_t)(dst)), "l"(src) : "memory")
#define CP_COMMIT() asm volatile("cp.async.commit_group;" ::: "memory")
#define CP_WAIT(n)  asm volatile("cp.async.wait_group %0;" :: "n"(n) : "memory")

// pack two fp32 into fp16x2: e0 -> lower half (first k element)
__device__ __forceinline__ uint32_t packh(float e0, float e1) {
    uint32_t r;
    asm("cvt.rn.f16x2.f32 %0, %1, %2;" : "=r"(r) : "f"(e1), "f"(e0));
    return r;
}

__device__ __forceinline__ void mma_f16(float* c, const uint32_t* a,
                                        uint32_t b0, uint32_t b1) {
    asm volatile(
        "mma.sync.aligned.m16n8k16.row.col.f32.f16.f16.f32 "
        "{%0,%1,%2,%3}, {%4,%5,%6,%7}, {%8,%9}, {%0,%1,%2,%3};"
        : "+f"(c[0]), "+f"(c[1]), "+f"(c[2]), "+f"(c[3])
        : "r"(a[0]), "r"(a[1]), "r"(a[2]), "r"(a[3]), "r"(b0), "r"(b1));
}

__device__ __forceinline__ float ex2(float x) {
    float y;
    asm("ex2.approx.ftz.f32 %0, %1;" : "=f"(y) : "f"(x));
    return y;
}

// ---------------------------------------------------------------------------
// Unified prep kernel: flat grid, role by block range.
// ---------------------------------------------------------------------------
#define PREP_CVT    6144
#define PREP_TRW    (PREP_CVT + 8192)      // 14336
#define PREP_FOLDT  (PREP_TRW + 512)       // 14848
#define PREP_BLOCKS (PREP_FOLDT + 32)      // 14880
#define PREP_SMEM_BYTES ((64 * 132 + 64 * 128) * 4)   // 66560 (foldT max)

__global__ __launch_bounds__(256) void prep_kernel(
    const float* __restrict__ queries, const float* __restrict__ keys,
    const float* __restrict__ values, uint32_t* __restrict__ Xh,
    const float* __restrict__ Wq, uint32_t* __restrict__ WqTh,
    const float* __restrict__ Wo, uint32_t* __restrict__ WoTh,
    const float* __restrict__ Wlk, const float* __restrict__ Wkr,
    uint32_t* __restrict__ WkTh,
    const float* __restrict__ Wlv, const float* __restrict__ Wvr,
    uint32_t* __restrict__ WvTh,
    const float* __restrict__ blk, const float* __restrict__ bkr,
    float* __restrict__ bk,
    const float* __restrict__ blv, const float* __restrict__ bvr,
    float* __restrict__ bv)
{
    extern __shared__ float psm[];
    const int bid = blockIdx.x;
    const int t = threadIdx.x;

    if (bid < PREP_CVT) {
        const int z = bid >> 11;
        const int xb = bid & 2047;
        const float* in = (z == 0) ? queries : (z == 1) ? keys : values;
        uint32_t* Oh = Xh + (size_t)z * Mrows * 1024;
        const size_t idx = (size_t)xb * 256 + t;
        const size_t ebase = idx * 16;
        const float4 a = *(const float4*)(in + ebase);
        const float4 b = *(const float4*)(in + ebase + 4);
        const float4 c = *(const float4*)(in + ebase + 8);
        const float4 d = *(const float4*)(in + ebase + 12);
        uint32_t h[8];
        h[0] = packh(a.x, a.y); h[1] = packh(a.z, a.w);
        h[2] = packh(b.x, b.y); h[3] = packh(b.z, b.w);
        h[4] = packh(c.x, c.y); h[5] = packh(c.z, c.w);
        h[6] = packh(d.x, d.y); h[7] = packh(d.z, d.w);
        const size_t wbase = idx * 8;
        *(uint4*)(Oh + wbase)     = make_uint4(h[0], h[4], h[1], h[5]);
        *(uint4*)(Oh + wbase + 4) = make_uint4(h[2], h[6], h[3], h[7]);
    } else if (bid < PREP_TRW) {
        const int r = bid - PREP_CVT;
        const int z = r >> 12;
        const int rr = r & 4095;
        const float* in = z ? Wo : Wq;
        uint32_t* Oh = z ? WoTh : WqTh;
        float (*tile)[33] = (float(*)[33])psm;
        const int bx = (rr & 63) * 32;
        const int by = (rr >> 6) * 32;
        const int tx = t & 31;
        const int ty = t >> 5;
        #pragma unroll
        for (int i = 0; i < 32; i += 8)
            tile[ty + i][tx] = in[(size_t)(by + ty + i) * Dmod + bx + tx];
        __syncthreads();
        const int c = tx;
        #pragma unroll
        for (int ii = 0; ii < 2; ii++) {
            const int uf = ty + 8 * ii;
            const int rb = uf & 7;
            const int phys = (by >> 1) + (uf & 8) + (((rb & 3) << 1) | (rb >> 2));
            Oh[(size_t)(bx + c) * 1024 + phys] =
                packh(tile[2 * uf][c], tile[2 * uf + 1][c]);
        }
    } else if (bid < PREP_FOLDT) {
        const int r = bid - PREP_TRW;
        const int z = r >> 8;
        const int rr = r & 255;
        const float* Wl = z ? Wlv : Wlk;
        const float* Wr = z ? Wvr : Wkr;
        uint32_t* WTh = z ? WvTh : WkTh;
        float* sWl = psm;             // [l][132]
        float* sWr = psm + 64 * 132;  // [l][128]
        const int dblk = rr & 15;
        const int h    = rr >> 4;

        #pragma unroll
        for (int i = 0; i < 8; i++) {
            int u = t + i * 256;
            int l = u >> 5, c4 = u & 31;
            *(float4*)&sWr[l * 128 + c4 * 4] =
                *(const float4*)(Wr + l * DKk + c4 * 4);
        }
        #pragma unroll
        for (int i = 0; i < 8; i++) {
            int u = t + i * 256;
            int d = u >> 4, l4 = u & 15;
            float4 x = *(const float4*)(Wl + (size_t)(dblk * 128 + d) * (Hh * Ll)
                                        + h * Ll + l4 * 4);
            sWl[(l4 * 4 + 0) * 132 + d] = x.x;
            sWl[(l4 * 4 + 1) * 132 + d] = x.y;
            sWl[(l4 * 4 + 2) * 132 + d] = x.z;
            sWl[(l4 * 4 + 3) * 132 + d] = x.w;
        }
        __syncthreads();

        const int d8 = (t & 15) * 8;
        const int cg = t >> 4;
        float acc[8][8];
        #pragma unroll
        for (int dd = 0; dd < 8; dd++)
            #pragma unroll
            for (int j = 0; j < 8; j++) acc[dd][j] = 0.f;

        for (int l = 0; l < Ll; l++) {
            float4 a0 = *(float4*)&sWl[l * 132 + d8];
            float4 a1 = *(float4*)&sWl[l * 132 + d8 + 4];
            const float* wr = &sWr[l * 128 + cg * 8];
            #pragma unroll
            for (int j = 0; j < 8; j++) {
                float wv = wr[j];
                acc[0][j] += a0.x * wv;
                acc[1][j] += a0.y * wv;
                acc[2][j] += a0.z * wv;
                acc[3][j] += a0.w * wv;
                acc[4][j] += a1.x * wv;
                acc[5][j] += a1.y * wv;
                acc[6][j] += a1.z * wv;
                acc[7][j] += a1.w * wv;
            }
        }

        const int wb  = dblk * 64 + ((d8 >> 1) & ~7);
        const int off = t & 1;
        #pragma unroll
        for (int j = 0; j < 8; j++) {
            const int n = h * 128 + cg * 8 + j;
            #pragma unroll
            for (int i2 = 0; i2 < 4; i2++)
                WTh[(size_t)n * 1024 + wb + 2 * i2 + off] =
                    packh(acc[2 * i2][j], acc[2 * i2 + 1][j]);
        }
    } else {
        if (t < 128) {
            const int r = bid - PREP_FOLDT;
            const int z = r >> 4;
            const int h = r & 15;
            const float* bl = z ? blv : blk;
            const float* Wr = z ? Wvr : Wkr;
            const float* br = z ? bvr : bkr;
            float* beff = z ? bv : bk;
            float acc = br[t];
            #pragma unroll 16
            for (int l = 0; l < Ll; l++)
                acc += bl[h * Ll + l] * Wr[l * DKk + t];
            beff[h * DKk + t] = acc;
        }
    }
}

// ---------------------------------------------------------------------------
// fp16 tensor-core GEMM body: C = A @ WT^T + bias.
// CTA 128x64, 128 threads (4 warps, warp tile 64x32), BK=64, 2 stages.
// smem/stage: A 128x36 + B 64x36 words = 27648 B; 2 stages = 55296 B
// -> 4 CTAs/SM (4 independent barrier domains at same 16 warps/SM).
// MODE 0: fp32 out. MODE 1: K fp16 plane. MODE 2: V fp16 plane transposed.
// MODE 3: Q fp16 plane, pre-scaled for softmax (K layout).
// ---------------------------------------------------------------------------
#define G_BK 64
#define G_NK (Dmod / G_BK)            // 32
#define G_ST 36
#define G_A_WORDS (128 * G_ST)        // 4608
#define G_B_WORDS (64 * G_ST)         // 2304
#define G_STAGE_WORDS (G_A_WORDS + G_B_WORDS)   // 6912
#define G_SMEM_BYTES (2 * G_STAGE_WORDS * 4)    // 55296

template<int MODE>
__device__ __forceinline__ void gemm_body(
    uint32_t* smw, uint32_t smem_base,
    const uint32_t* __restrict__ AhG, const uint32_t* __restrict__ WhG,
    const float* __restrict__ bias, float* __restrict__ C,
    uint32_t* __restrict__ P1,
    int m0, int n0)
{
    const int t    = threadIdx.x;
    const int wid  = t >> 5;
    const int lane = t & 31;
    const int g    = lane >> 2;
    const int tid4 = lane & 3;
    const int wm   = wid >> 1;    // 0..1
    const int wn   = wid & 1;     // 0..1

    float acc[4][4][4];
    #pragma unroll
    for (int mf = 0; mf < 4; mf++)
        #pragma unroll
        for (int nf = 0; nf < 4; nf++)
            #pragma unroll
            for (int r = 0; r < 4; r++) acc[mf][nf][r] = 0.f;

    auto load_stage = [&](int s, int k0) {
        const uint32_t aB = smem_base + (uint32_t)s * G_STAGE_WORDS * 4;
        const uint32_t bB = aB + G_A_WORDS * 4;
        const int w0 = k0 >> 1;
        #pragma unroll
        for (int i = 0; i < 8; i++) {
            int u = t + i * 128;             // 1024 uint4 units (A)
            int row = u >> 3, c = u & 7;
            uint32_t doff = (uint32_t)(row * G_ST + c * 4) * 4;
            CP_ASYNC16(aB + doff, AhG + (size_t)(m0 + row) * 1024 + w0 + c * 4);
        }
        #pragma unroll
        for (int i = 0; i < 4; i++) {
            int u = t + i * 128;             // 512 uint4 units (B)
            int row = u >> 3, c = u & 7;
            uint32_t doff = (uint32_t)(row * G_ST + c * 4) * 4;
            CP_ASYNC16(bB + doff, WhG + (size_t)(n0 + row) * 1024 + w0 + c * 4);
        }
    };

    load_stage(0, 0);
    CP_COMMIT();
    load_stage(1, G_BK);
    CP_COMMIT();

    for (int k = 0; k < G_NK; k++) {
        const int s = k & 1;
        CP_WAIT(1);
        __syncthreads();

        const uint32_t* sA = smw + (size_t)s * G_STAGE_WORDS;
        const uint32_t* sB = sA + G_A_WORDS;

        #pragma unroll
        for (int ks = 0; ks < 4; ks++) {
            const int wk = 8 * ks + 2 * tid4;
            uint2 bq[4];
            #pragma unroll
            for (int nf = 0; nf < 4; nf++)
                bq[nf] = *(const uint2*)&sB[(wn * 32 + nf * 8 + g) * G_ST + wk];
            #pragma unroll
            for (int mf = 0; mf < 4; mf++) {
                const int ra = (wm * 64 + mf * 16 + g) * G_ST + wk;
                uint2 a0 = *(const uint2*)&sA[ra];
                uint2 a1 = *(const uint2*)&sA[ra + 8 * G_ST];
                uint32_t af[4] = {a0.x, a1.x, a0.y, a1.y};
                #pragma unroll
                for (int nf = 0; nf < 4; nf++)
                    mma_f16(acc[mf][nf], af, bq[nf].x, bq[nf].y);
            }
        }

        __syncthreads();
        if (k + 2 < G_NK) load_stage(s, (k + 2) * G_BK);
        CP_COMMIT();
    }

    #pragma unroll
    for (int mf = 0; mf < 4; mf++) {
        const int r0 = m0 + wm * 64 + mf * 16 + g;
        #pragma unroll
        for (int nf = 0; nf < 4; nf++) {
            const int c0 = n0 + wn * 32 + nf * 8 + 2 * tid4;
            const float b0 = bias[c0], b1 = bias[c0 + 1];
            float v0 = acc[mf][nf][0] + b0, v1 = acc[mf][nf][1] + b1;
            float v2 = acc[mf][nf][2] + b0, v3 = acc[mf][nf][3] + b1;
            if (MODE == 0) {
                *(float2*)(C + (size_t)r0 * Dmod + c0)       = make_float2(v0, v1);
                *(float2*)(C + (size_t)(r0 + 8) * Dmod + c0) = make_float2(v2, v3);
            } else if (MODE == 1 || MODE == 3) {
                const int bb = r0 >> 11, s2 = r0 & 2047, hh = c0 >> 7;
                const int j = (c0 & 127) >> 1;
                const int p = (j & ~7) | (2 * tid4 + (nf & 1));
                const size_t base = ((size_t)(bb * Hh + hh) * Sseq + s2) * 64 + p;
                if (MODE == 1) {
                    P1[base]       = packh(v0, v1);
                    P1[base + 512] = packh(v2, v3);
                } else {
                    const float qs = 0.088388347648318447f * 1.4426950408889634f;
                    P1[base]       = packh(v0 * qs, v1 * qs);
                    P1[base + 512] = packh(v2 * qs, v3 * qs);
                }
            } else {
                float u0 = __shfl_xor_sync(0xFFFFFFFFu, v0, 4);
                float u1 = __shfl_xor_sync(0xFFFFFFFFu, v1, 4);
                float u2 = __shfl_xor_sync(0xFFFFFFFFu, v2, 4);
                float u3 = __shfl_xor_sync(0xFFFFFFFFu, v3, 4);
                if ((g & 1) == 0) {
                    const int bb = r0 >> 11, s2 = r0 & 2047, hh = c0 >> 7;
                    const int d = c0 & 127;
                    const size_t base0 =
                        ((size_t)(bb * Hh + hh) * DKk + d) * 1024 + ((s2 & ~15) >> 1);
                    P1[base0 + g]            = packh(v0, u0);
                    P1[base0 + g + 1]        = packh(v2, u2);
                    P1[base0 + 1024 + g]     = packh(v1, u1);
                    P1[base0 + 1024 + g + 1] = packh(v3, u3);
                }
            }
        }
    }
}

// Merged Q/K/V projection (grid.z selects input/weight/epilogue)
__global__ __launch_bounds__(128, 4) void qkv_gemm_kernel(
    const uint32_t* __restrict__ Xh,
    const uint32_t* __restrict__ WqTh, const uint32_t* __restrict__ WkTh,
    const uint32_t* __restrict__ WvTh,
    const float* __restrict__ bq, const float* __restrict__ bk,
    const float* __restrict__ bv,
    uint32_t* __restrict__ Qh, uint32_t* __restrict__ Kh,
    uint32_t* __restrict__ Vh)
{
    extern __shared__ uint32_t smw[];
    const uint32_t smem_base = smem_u32(smw);
    const int m0 = blockIdx.y * 128;
    const int n0 = blockIdx.x * 64;
    const int z = blockIdx.z;
    const uint32_t* Ah = Xh + (size_t)z * Mrows * 1024;
    if (z == 0)
        gemm_body<3>(smw, smem_base, Ah, WqTh, bq, nullptr, Qh, m0, n0);
    else if (z == 1)
        gemm_body<1>(smw, smem_base, Ah, WkTh, bk, nullptr, Kh, m0, n0);
    else
        gemm_body<2>(smw, smem_base, Ah, WvTh, bv, nullptr, Vh, m0, n0);
}

__global__ __launch_bounds__(128, 4) void o_gemm_kernel(
    const uint32_t* __restrict__ Ah, const uint32_t* __restrict__ WTh,
    const float* __restrict__ bias, float* __restrict__ C)
{
    extern __shared__ uint32_t smw[];
    const uint32_t smem_base = smem_u32(smw);
    gemm_body<0>(smw, smem_base, Ah, WTh, bias, C, nullptr,
                 blockIdx.y * 128, blockIdx.x * 64);
}

// ---------------------------------------------------------------------------
// Tensor-core causal FA: Q single fp16 plane (pre-scaled), K/V fp16 planes.
// QK = q*k (1 MMA); PV = p*v (1 MMA, P fp16).
// ---------------------------------------------------------------------------
#define KROWW 72
#define VROWW 40
#define FA_STAGE_WORDS (64 * KROWW + 128 * VROWW)   // 9728
#define FA_SMEM_BYTES (2 * FA_STAGE_WORDS * 4)      // 77824

__global__ __launch_bounds__(256, 1) void fa_tc_kernel(
    const uint32_t* __restrict__ QhG,
    const uint32_t* __restrict__ KhG, const uint32_t* __restrict__ VhG,
    uint32_t* __restrict__ OhG)
{
    extern __shared__ uint32_t su[];
    const uint32_t smem_base = smem_u32(su);

    const int qb = (int)gridDim.x - 1 - (int)blockIdx.x;
    const int h  = blockIdx.y;
    const int b  = blockIdx.z;
    const int t  = threadIdx.x;
    const int w  = t >> 5;
    const int lane = t & 31;
    const int g  = lane >> 2;
    const int t4 = lane & 3;
    const int q0 = qb * 128;

    const size_t bhS = (size_t)(b * Hh + h) * Sseq;
    const size_t bhD = (size_t)(b * Hh + h) * DKk;

    // Preload Q fragments (single plane, pre-scaled)
    uint32_t qh[8][4];
    {
        const size_t rg  = (bhS + q0 + w * 16 + g) * 64;
        const size_t rg8 = rg + 8 * 64;
        #pragma unroll
        for (int ks = 0; ks < 8; ks++) {
            const int wk = 8 * ks + 2 * t4;
            uint2 h0 = *(const uint2*)&QhG[rg + wk];
            uint2 h1 = *(const uint2*)&QhG[rg8 + wk];
            qh[ks][0] = h0.x; qh[ks][1] = h1.x; qh[ks][2] = h0.y; qh[ks][3] = h1.y;
        }
    }

    auto load_tile = [&](int stage, int kt) {
        const int kv0 = kt * 64;
        const uint32_t sb = smem_base + (uint32_t)stage * FA_STAGE_WORDS * 4;
        const uint32_t kB = sb;
        const uint32_t vB = sb + 64 * KROWW * 4;
        #pragma unroll
        for (int i = 0; i < 4; i++) {
            int u = t + i * 256;
            int row = u >> 4, w4 = (u & 15) * 4;
            CP_ASYNC16(kB + (uint32_t)(row * KROWW + w4) * 4,
                       KhG + (bhS + kv0 + row) * 64 + w4);
        }
        #pragma unroll
        for (int i = 0; i < 4; i++) {
            int u = t + i * 256;
            int row = u >> 3, w4 = (u & 7) * 4;
            CP_ASYNC16(vB + (uint32_t)(row * VROWW + w4) * 4,
                       VhG + (bhD + row) * 1024 + (kv0 >> 1) + w4);
        }
    };

    float oacc[16][4];
    #pragma unroll
    for (int nf = 0; nf < 16; nf++)
        #pragma unroll
        for (int r = 0; r < 4; r++) oacc[nf][r] = 0.f;

    float m0 = -1e30f, m1 = -1e30f, l0 = 0.f, l1 = 0.f;
    const int row0 = q0 + w * 16 + g;
    const int row1 = row0 + 8;

    const int ntiles = 2 * qb + 2;
    load_tile(0, 0);
    CP_COMMIT();

    for (int kt = 0; kt < ntiles; kt++) {
        const int st = kt & 1;
        const int kv0 = kt * 64;
        if (kt + 1 < ntiles) {
            load_tile(st ^ 1, kt + 1);
            CP_COMMIT();
            CP_WAIT(1);
        } else {
            CP_WAIT(0);
        }
        __syncthreads();

        const uint32_t* Ks = su + (size_t)st * FA_STAGE_WORDS;
        const uint32_t* Vs = Ks + 64 * KROWW;

        float acc[8][4];
        #pragma unroll
        for (int nf = 0; nf < 8; nf++)
            #pragma unroll
            for (int r = 0; r < 4; r++) acc[nf][r] = 0.f;

        #pragma unroll
        for (int ks = 0; ks < 8; ks++) {
            #pragma unroll
            for (int nf = 0; nf < 8; nf++) {
                const int r = (nf * 8 + g) * KROWW + 8 * ks + 2 * t4;
                uint2 kw = *(const uint2*)&Ks[r];
                mma_f16(acc[nf], qh[ks], kw.x, kw.y);
            }
        }

        if (kv0 + 63 > q0) {
            #pragma unroll
            for (int nf = 0; nf < 8; nf++) {
                const int c = kv0 + nf * 8 + 2 * t4;
                if (c     > row0) acc[nf][0] = -1e30f;
                if (c + 1 > row0) acc[nf][1] = -1e30f;
                if (c     > row1) acc[nf][2] = -1e30f;
                if (c + 1 > row1) acc[nf][3] = -1e30f;
            }
        }

        float mx0 = -1e30f, mx1 = -1e30f;
        #pragma unroll
        for (int nf = 0; nf < 8; nf++) {
            mx0 = fmaxf(mx0, fmaxf(acc[nf][0], acc[nf][1]));
            mx1 = fmaxf(mx1, fmaxf(acc[nf][2], acc[nf][3]));
        }
        mx0 = fmaxf(mx0, __shfl_xor_sync(0xFFFFFFFFu, mx0, 1));
        mx0 = fmaxf(mx0, __shfl_xor_sync(0xFFFFFFFFu, mx0, 2));
        mx1 = fmaxf(mx1, __shfl_xor_sync(0xFFFFFFFFu, mx1, 1));
        mx1 = fmaxf(mx1, __shfl_xor_sync(0xFFFFFFFFu, mx1, 2));

        const float mn0 = fmaxf(m0, mx0);
        const float mn1 = fmaxf(m1, mx1);
        const float cr0 = ex2(m0 - mn0);
        const float cr1 = ex2(m1 - mn1);

        float ps0 = 0.f, ps1 = 0.f;
        #pragma unroll
        for (int nf = 0; nf < 8; nf++) {
            acc[nf][0] = ex2(acc[nf][0] - mn0);
            acc[nf][1] = ex2(acc[nf][1] - mn0);
            acc[nf][2] = ex2(acc[nf][2] - mn1);
            acc[nf][3] = ex2(acc[nf][3] - mn1);
            ps0 += acc[nf][0] + acc[nf][1];
            ps1 += acc[nf][2] + acc[nf][3];
        }
        ps0 += __shfl_xor_sync(0xFFFFFFFFu, ps0, 1);
        ps0 += __shfl_xor_sync(0xFFFFFFFFu, ps0, 2);
        ps1 += __shfl_xor_sync(0xFFFFFFFFu, ps1, 1);
        ps1 += __shfl_xor_sync(0xFFFFFFFFu, ps1, 2);

        l0 = l0 * cr0 + ps0;
        l1 = l1 * cr1 + ps1;
        m0 = mn0;
        m1 = mn1;

        #pragma unroll
        for (int nf = 0; nf < 16; nf++) {
            oacc[nf][0] *= cr0;
            oacc[nf][1] *= cr0;
            oacc[nf][2] *= cr1;
            oacc[nf][3] *= cr1;
        }

        // ---- P @ V, P single fp16 ----
        #pragma unroll
        for (int ks2 = 0; ks2 < 4; ks2++) {
            uint32_t ph[4];
            ph[0] = packh(acc[2 * ks2][0],     acc[2 * ks2][1]);
            ph[1] = packh(acc[2 * ks2][2],     acc[2 * ks2][3]);
            ph[2] = packh(acc[2 * ks2 + 1][0], acc[2 * ks2 + 1][1]);
            ph[3] = packh(acc[2 * ks2 + 1][2], acc[2 * ks2 + 1][3]);
            #pragma unroll
            for (int nf = 0; nf < 16; nf++) {
                const int r = (nf * 8 + g) * VROWW + 8 * ks2 + 2 * t4;
                uint2 vw = *(const uint2*)&Vs[r];
                mma_f16(oacc[nf], ph, vw.x, vw.y);
            }
        }
        __syncthreads();
    }

    // epilogue: normalize, emit fp16 O plane (pair-permuted words)
    const float inv0 = 1.0f / l0;
    const float inv1 = 1.0f / l1;
    const size_t rowg  = (size_t)(b * Sseq + q0 + w * 16 + g) * 1024 + h * 64;
    const size_t rowg8 = rowg + 8 * 1024;
    #pragma unroll
    for (int nf = 0; nf < 16; nf++) {
        const int w_log = nf * 4 + t4;
        const int phys  = (w_log & ~7) + 2 * t4 + (nf & 1);
        OhG[rowg + phys]  = packh(oacc[nf][0] * inv0, oacc[nf][1] * inv0);
        OhG[rowg8 + phys] = packh(oacc[nf][2] * inv1, oacc[nf][3] * inv1);
    }
}

// ---------------------------------------------------------------------------
// kernel_launch
// ---------------------------------------------------------------------------
extern "C" void kernel_launch(void* const* d_in, const int* in_sizes, int n_in,
                              void* d_out, int out_size)
{
    const float* queries = (const float*)d_in[0];
    const float* keys    = (const float*)d_in[1];
    const float* values  = (const float*)d_in[2];
    const float* Wq      = (const float*)d_in[3];
    const float* bq      = (const float*)d_in[4];
    const float* Wlk     = (const float*)d_in[5];
    const float* blk     = (const float*)d_in[6];
    const float* Wlv     = (const float*)d_in[7];
    const float* blv     = (const float*)d_in[8];
    const float* Wkr     = (const float*)d_in[9];
    const float* bkr     = (const float*)d_in[10];
    const float* Wvr     = (const float*)d_in[11];
    const float* bvr     = (const float*)d_in[12];
    const float* Wo      = (const float*)d_in[13];
    const float* bo      = (const float*)d_in[14];
    float* out = (float*)d_out;

    float *bk, *bv;
    uint32_t *Xh, *Qh, *Kh, *Vh, *Oh;
    uint32_t *WqTh, *WkTh, *WvTh, *WoTh;
    cudaGetSymbolAddress((void**)&Xh,   g_Xh);
    cudaGetSymbolAddress((void**)&Qh,   g_Qh);
    cudaGetSymbolAddress((void**)&Kh,   g_Kh);
    cudaGetSymbolAddress((void**)&Vh,   g_Vh);
    cudaGetSymbolAddress((void**)&Oh,   g_Oh);
    cudaGetSymbolAddress((void**)&WqTh, g_WqTh);
    cudaGetSymbolAddress((void**)&WkTh, g_WkTh);
    cudaGetSymbolAddress((void**)&WvTh, g_WvTh);
    cudaGetSymbolAddress((void**)&WoTh, g_WoTh);
    cudaGetSymbolAddress((void**)&bk,   g_bk);
    cudaGetSymbolAddress((void**)&bv,   g_bv);

    cudaFuncSetAttribute(prep_kernel,
                         cudaFuncAttributeMaxDynamicSharedMemorySize, PREP_SMEM_BYTES);
    cudaFuncSetAttribute(qkv_gemm_kernel,
                         cudaFuncAttributeMaxDynamicSharedMemorySize, G_SMEM_BYTES);
    cudaFuncSetAttribute(o_gemm_kernel,
                         cudaFuncAttributeMaxDynamicSharedMemorySize, G_SMEM_BYTES);
    cudaFuncSetAttribute(fa_tc_kernel,
                         cudaFuncAttributeMaxDynamicSharedMemorySize, FA_SMEM_BYTES);

    // Unified preparation: cvt + transposeW + foldT + fold_b in one launch
    prep_kernel<<<PREP_BLOCKS, 256, PREP_SMEM_BYTES>>>(
        queries, keys, values, Xh,
        Wq, WqTh, Wo, WoTh,
        Wlk, Wkr, WkTh, Wlv, Wvr, WvTh,
        blk, bkr, bk, blv, bvr, bv);

    // Merged Q/K/V projections (CTA 128x64, 4 CTAs/SM)
    qkv_gemm_kernel<<<dim3(Dmod / 64, Mrows / 128, 3), 128, G_SMEM_BYTES>>>(
        Xh, WqTh, WkTh, WvTh, bq, bk, bv, Qh, Kh, Vh);

    // Fused causal attention (all single-term fp16 MMAs)
    fa_tc_kernel<<<dim3(Sseq / 128, Hh, Bsz), 256, FA_SMEM_BYTES>>>(
        Qh, Kh, Vh, Oh);

    // Output projection
    o_gemm_kernel<<<dim3(Dmod / 64, Mrows / 128), 128, G_SMEM_BYTES>>>(
        Oh, WoTh, bo, out);
}

// round 17
// speedup vs baseline: 2.4522x; 1.0150x over previous
#include <cuda_runtime.h>
#include <cuda_bf16.h>
#include <cuda_fp16.h>
#include <math.h>
#include <cstdint>

// Problem constants
#define Bsz   2
#define Sseq  2048
#define Dmod  2048
#define Hh    16
#define DKk   128
#define Ll    64
#define Mrows (Bsz * Sseq)   // 4096

// ---------------------------------------------------------------------------
// Device scratch
// ---------------------------------------------------------------------------
__device__ uint32_t g_Xh  [(size_t)3 * Mrows * 1024];  // fp16 activations q/k/v
__device__ uint32_t g_Qh  [(size_t)Mrows * 1024];      // Q fp16 (pre-scaled)
__device__ uint32_t g_Kh  [(size_t)Mrows * 1024];      // K fp16 [b,h,s][64 w]
__device__ uint32_t g_Vh  [(size_t)Mrows * 1024];      // V fp16 [b,h,d][1024 w]
__device__ uint32_t g_Oh  [(size_t)Mrows * 1024];      // FA out fp16 plane
__device__ uint32_t g_WqTh[(size_t)Dmod * 1024];       // fp16 weight planes
__device__ uint32_t g_WkTh[(size_t)Dmod * 1024];
__device__ uint32_t g_WvTh[(size_t)Dmod * 1024];
__device__ uint32_t g_WoTh[(size_t)Dmod * 1024];
__device__ float    g_bk[Dmod];
__device__ float    g_bv[Dmod];

// ---------------------------------------------------------------------------
// Helpers
// ---------------------------------------------------------------------------
__device__ __forceinline__ uint32_t smem_u32(const void* p) {
    uint32_t a;
    asm("{ .reg .u64 t; cvta.to.shared.u64 t, %1; cvt.u32.u64 %0, t; }"
        : "=r"(a) : "l"(p));
    return a;
}

#define CP_ASYNC16(dst, src) \
    asm volatile("cp.async.cg.shared.global [%0], [%1], 16;" \
        :: "r"((uint32_t)(dst)), "l"(src) : "memory")
#define CP_COMMIT() asm volatile("cp.async.commit_group;" ::: "memory")
#define CP_WAIT(n)  asm volatile("cp.async.wait_group %0;" :: "n"(n) : "memory")

// pack two fp32 into fp16x2: e0 -> lower half (first k element)
__device__ __forceinline__ uint32_t packh(float e0, float e1) {
    uint32_t r;
    asm("cvt.rn.f16x2.f32 %0, %1, %2;" : "=r"(r) : "f"(e1), "f"(e0));
    return r;
}

__device__ __forceinline__ void mma_f16(float* c, const uint32_t* a,
                                        uint32_t b0, uint32_t b1) {
    asm volatile(
        "mma.sync.aligned.m16n8k16.row.col.f32.f16.f16.f32 "
        "{%0,%1,%2,%3}, {%4,%5,%6,%7}, {%8,%9}, {%0,%1,%2,%3};"
        : "+f"(c[0]), "+f"(c[1]), "+f"(c[2]), "+f"(c[3])
        : "r"(a[0]), "r"(a[1]), "r"(a[2]), "r"(a[3]), "r"(b0), "r"(b1));
}

__device__ __forceinline__ float ex2(float x) {
    float y;
    asm("ex2.approx.ftz.f32 %0, %1;" : "=f"(y) : "f"(x));
    return y;
}

// ---------------------------------------------------------------------------
// Unified prep kernel: flat grid, role by block range.
// ---------------------------------------------------------------------------
#define PREP_CVT    6144
#define PREP_TRW    (PREP_CVT + 8192)      // 14336
#define PREP_FOLDT  (PREP_TRW + 512)       // 14848
#define PREP_BLOCKS (PREP_FOLDT + 32)      // 14880
#define PREP_SMEM_BYTES ((64 * 132 + 64 * 128) * 4)   // 66560 (foldT max)

__global__ __launch_bounds__(256) void prep_kernel(
    const float* __restrict__ queries, const float* __restrict__ keys,
    const float* __restrict__ values, uint32_t* __restrict__ Xh,
    const float* __restrict__ Wq, uint32_t* __restrict__ WqTh,
    const float* __restrict__ Wo, uint32_t* __restrict__ WoTh,
    const float* __restrict__ Wlk, const float* __restrict__ Wkr,
    uint32_t* __restrict__ WkTh,
    const float* __restrict__ Wlv, const float* __restrict__ Wvr,
    uint32_t* __restrict__ WvTh,
    const float* __restrict__ blk, const float* __restrict__ bkr,
    float* __restrict__ bk,
    const float* __restrict__ blv, const float* __restrict__ bvr,
    float* __restrict__ bv)
{
    extern __shared__ float psm[];
    const int bid = blockIdx.x;
    const int t = threadIdx.x;

    if (bid < PREP_CVT) {
        const int z = bid >> 11;
        const int xb = bid & 2047;
        const float* in = (z == 0) ? queries : (z == 1) ? keys : values;
        uint32_t* Oh = Xh + (size_t)z * Mrows * 1024;
        const size_t idx = (size_t)xb * 256 + t;
        const size_t ebase = idx * 16;
        const float4 a = *(const float4*)(in + ebase);
        const float4 b = *(const float4*)(in + ebase + 4);
        const float4 c = *(const float4*)(in + ebase + 8);
        const float4 d = *(const float4*)(in + ebase + 12);
        uint32_t h[8];
        h[0] = packh(a.x, a.y); h[1] = packh(a.z, a.w);
        h[2] = packh(b.x, b.y); h[3] = packh(b.z, b.w);
        h[4] = packh(c.x, c.y); h[5] = packh(c.z, c.w);
        h[6] = packh(d.x, d.y); h[7] = packh(d.z, d.w);
        const size_t wbase = idx * 8;
        *(uint4*)(Oh + wbase)     = make_uint4(h[0], h[4], h[1], h[5]);
        *(uint4*)(Oh + wbase + 4) = make_uint4(h[2], h[6], h[3], h[7]);
    } else if (bid < PREP_TRW) {
        const int r = bid - PREP_CVT;
        const int z = r >> 12;
        const int rr = r & 4095;
        const float* in = z ? Wo : Wq;
        uint32_t* Oh = z ? WoTh : WqTh;
        float (*tile)[33] = (float(*)[33])psm;
        const int bx = (rr & 63) * 32;
        const int by = (rr >> 6) * 32;
        const int tx = t & 31;
        const int ty = t >> 5;
        #pragma unroll
        for (int i = 0; i < 32; i += 8)
            tile[ty + i][tx] = in[(size_t)(by + ty + i) * Dmod + bx + tx];
        __syncthreads();
        const int c = tx;
        #pragma unroll
        for (int ii = 0; ii < 2; ii++) {
            const int uf = ty + 8 * ii;
            const int rb = uf & 7;
            const int phys = (by >> 1) + (uf & 8) + (((rb & 3) << 1) | (rb >> 2));
            Oh[(size_t)(bx + c) * 1024 + phys] =
                packh(tile[2 * uf][c], tile[2 * uf + 1][c]);
        }
    } else if (bid < PREP_FOLDT) {
        const int r = bid - PREP_TRW;
        const int z = r >> 8;
        const int rr = r & 255;
        const float* Wl = z ? Wlv : Wlk;
        const float* Wr = z ? Wvr : Wkr;
        uint32_t* WTh = z ? WvTh : WkTh;
        float* sWl = psm;             // [l][132]
        float* sWr = psm + 64 * 132;  // [l][128]
        const int dblk = rr & 15;
        const int h    = rr >> 4;

        #pragma unroll
        for (int i = 0; i < 8; i++) {
            int u = t + i * 256;
            int l = u >> 5, c4 = u & 31;
            *(float4*)&sWr[l * 128 + c4 * 4] =
                *(const float4*)(Wr + l * DKk + c4 * 4);
        }
        #pragma unroll
        for (int i = 0; i < 8; i++) {
            int u = t + i * 256;
            int d = u >> 4, l4 = u & 15;
            float4 x = *(const float4*)(Wl + (size_t)(dblk * 128 + d) * (Hh * Ll)
                                        + h * Ll + l4 * 4);
            sWl[(l4 * 4 + 0) * 132 + d] = x.x;
            sWl[(l4 * 4 + 1) * 132 + d] = x.y;
            sWl[(l4 * 4 + 2) * 132 + d] = x.z;
            sWl[(l4 * 4 + 3) * 132 + d] = x.w;
        }
        __syncthreads();

        const int d8 = (t & 15) * 8;
        const int cg = t >> 4;
        float acc[8][8];
        #pragma unroll
        for (int dd = 0; dd < 8; dd++)
            #pragma unroll
            for (int j = 0; j < 8; j++) acc[dd][j] = 0.f;

        for (int l = 0; l < Ll; l++) {
            float4 a0 = *(float4*)&sWl[l * 132 + d8];
            float4 a1 = *(float4*)&sWl[l * 132 + d8 + 4];
            const float* wr = &sWr[l * 128 + cg * 8];
            #pragma unroll
            for (int j = 0; j < 8; j++) {
                float wv = wr[j];
                acc[0][j] += a0.x * wv;
                acc[1][j] += a0.y * wv;
                acc[2][j] += a0.z * wv;
                acc[3][j] += a0.w * wv;
                acc[4][j] += a1.x * wv;
                acc[5][j] += a1.y * wv;
                acc[6][j] += a1.z * wv;
                acc[7][j] += a1.w * wv;
            }
        }

        const int wb  = dblk * 64 + ((d8 >> 1) & ~7);
        const int off = t & 1;
        #pragma unroll
        for (int j = 0; j < 8; j++) {
            const int n = h * 128 + cg * 8 + j;
            #pragma unroll
            for (int i2 = 0; i2 < 4; i2++)
                WTh[(size_t)n * 1024 + wb + 2 * i2 + off] =
                    packh(acc[2 * i2][j], acc[2 * i2 + 1][j]);
        }
    } else {
        if (t < 128) {
            const int r = bid - PREP_FOLDT;
            const int z = r >> 4;
            const int h = r & 15;
            const float* bl = z ? blv : blk;
            const float* Wr = z ? Wvr : Wkr;
            const float* br = z ? bvr : bkr;
            float* beff = z ? bv : bk;
            float acc = br[t];
            #pragma unroll 16
            for (int l = 0; l < Ll; l++)
                acc += bl[h * Ll + l] * Wr[l * DKk + t];
            beff[h * DKk + t] = acc;
        }
    }
}

// ---------------------------------------------------------------------------
// fp16 tensor-core GEMM body (unchanged R16 config: CTA 128x64, 4 CTAs/SM)
// ---------------------------------------------------------------------------
#define G_BK 64
#define G_NK (Dmod / G_BK)            // 32
#define G_ST 36
#define G_A_WORDS (128 * G_ST)        // 4608
#define G_B_WORDS (64 * G_ST)         // 2304
#define G_STAGE_WORDS (G_A_WORDS + G_B_WORDS)   // 6912
#define G_SMEM_BYTES (2 * G_STAGE_WORDS * 4)    // 55296

template<int MODE>
__device__ __forceinline__ void gemm_body(
    uint32_t* smw, uint32_t smem_base,
    const uint32_t* __restrict__ AhG, const uint32_t* __restrict__ WhG,
    const float* __restrict__ bias, float* __restrict__ C,
    uint32_t* __restrict__ P1,
    int m0, int n0)
{
    const int t    = threadIdx.x;
    const int wid  = t >> 5;
    const int lane = t & 31;
    const int g    = lane >> 2;
    const int tid4 = lane & 3;
    const int wm   = wid >> 1;    // 0..1
    const int wn   = wid & 1;     // 0..1

    float acc[4][4][4];
    #pragma unroll
    for (int mf = 0; mf < 4; mf++)
        #pragma unroll
        for (int nf = 0; nf < 4; nf++)
            #pragma unroll
            for (int r = 0; r < 4; r++) acc[mf][nf][r] = 0.f;

    auto load_stage = [&](int s, int k0) {
        const uint32_t aB = smem_base + (uint32_t)s * G_STAGE_WORDS * 4;
        const uint32_t bB = aB + G_A_WORDS * 4;
        const int w0 = k0 >> 1;
        #pragma unroll
        for (int i = 0; i < 8; i++) {
            int u = t + i * 128;
            int row = u >> 3, c = u & 7;
            uint32_t doff = (uint32_t)(row * G_ST + c * 4) * 4;
            CP_ASYNC16(aB + doff, AhG + (size_t)(m0 + row) * 1024 + w0 + c * 4);
        }
        #pragma unroll
        for (int i = 0; i < 4; i++) {
            int u = t + i * 128;
            int row = u >> 3, c = u & 7;
            uint32_t doff = (uint32_t)(row * G_ST + c * 4) * 4;
            CP_ASYNC16(bB + doff, WhG + (size_t)(n0 + row) * 1024 + w0 + c * 4);
        }
    };

    load_stage(0, 0);
    CP_COMMIT();
    load_stage(1, G_BK);
    CP_COMMIT();

    for (int k = 0; k < G_NK; k++) {
        const int s = k & 1;
        CP_WAIT(1);
        __syncthreads();

        const uint32_t* sA = smw + (size_t)s * G_STAGE_WORDS;
        const uint32_t* sB = sA + G_A_WORDS;

        #pragma unroll
        for (int ks = 0; ks < 4; ks++) {
            const int wk = 8 * ks + 2 * tid4;
            uint2 bq[4];
            #pragma unroll
            for (int nf = 0; nf < 4; nf++)
                bq[nf] = *(const uint2*)&sB[(wn * 32 + nf * 8 + g) * G_ST + wk];
            #pragma unroll
            for (int mf = 0; mf < 4; mf++) {
                const int ra = (wm * 64 + mf * 16 + g) * G_ST + wk;
                uint2 a0 = *(const uint2*)&sA[ra];
                uint2 a1 = *(const uint2*)&sA[ra + 8 * G_ST];
                uint32_t af[4] = {a0.x, a1.x, a0.y, a1.y};
                #pragma unroll
                for (int nf = 0; nf < 4; nf++)
                    mma_f16(acc[mf][nf], af, bq[nf].x, bq[nf].y);
            }
        }

        __syncthreads();
        if (k + 2 < G_NK) load_stage(s, (k + 2) * G_BK);
        CP_COMMIT();
    }

    #pragma unroll
    for (int mf = 0; mf < 4; mf++) {
        const int r0 = m0 + wm * 64 + mf * 16 + g;
        #pragma unroll
        for (int nf = 0; nf < 4; nf++) {
            const int c0 = n0 + wn * 32 + nf * 8 + 2 * tid4;
            const float b0 = bias[c0], b1 = bias[c0 + 1];
            float v0 = acc[mf][nf][0] + b0, v1 = acc[mf][nf][1] + b1;
            float v2 = acc[mf][nf][2] + b0, v3 = acc[mf][nf][3] + b1;
            if (MODE == 0) {
                *(float2*)(C + (size_t)r0 * Dmod + c0)       = make_float2(v0, v1);
                *(float2*)(C + (size_t)(r0 + 8) * Dmod + c0) = make_float2(v2, v3);
            } else if (MODE == 1 || MODE == 3) {
                const int bb = r0 >> 11, s2 = r0 & 2047, hh = c0 >> 7;
                const int j = (c0 & 127) >> 1;
                const int p = (j & ~7) | (2 * tid4 + (nf & 1));
                const size_t base = ((size_t)(bb * Hh + hh) * Sseq + s2) * 64 + p;
                if (MODE == 1) {
                    P1[base]       = packh(v0, v1);
                    P1[base + 512] = packh(v2, v3);
                } else {
                    const float qs = 0.088388347648318447f * 1.4426950408889634f;
                    P1[base]       = packh(v0 * qs, v1 * qs);
                    P1[base + 512] = packh(v2 * qs, v3 * qs);
                }
            } else {
                float u0 = __shfl_xor_sync(0xFFFFFFFFu, v0, 4);
                float u1 = __shfl_xor_sync(0xFFFFFFFFu, v1, 4);
                float u2 = __shfl_xor_sync(0xFFFFFFFFu, v2, 4);
                float u3 = __shfl_xor_sync(0xFFFFFFFFu, v3, 4);
                if ((g & 1) == 0) {
                    const int bb = r0 >> 11, s2 = r0 & 2047, hh = c0 >> 7;
                    const int d = c0 & 127;
                    const size_t base0 =
                        ((size_t)(bb * Hh + hh) * DKk + d) * 1024 + ((s2 & ~15) >> 1);
                    P1[base0 + g]            = packh(v0, u0);
                    P1[base0 + g + 1]        = packh(v2, u2);
                    P1[base0 + 1024 + g]     = packh(v1, u1);
                    P1[base0 + 1024 + g + 1] = packh(v3, u3);
                }
            }
        }
    }
}

// Merged Q/K/V projection (grid.z selects input/weight/epilogue)
__global__ __launch_bounds__(128, 4) void qkv_gemm_kernel(
    const uint32_t* __restrict__ Xh,
    const uint32_t* __restrict__ WqTh, const uint32_t* __restrict__ WkTh,
    const uint32_t* __restrict__ WvTh,
    const float* __restrict__ bq, const float* __restrict__ bk,
    const float* __restrict__ bv,
    uint32_t* __restrict__ Qh, uint32_t* __restrict__ Kh,
    uint32_t* __restrict__ Vh)
{
    extern __shared__ uint32_t smw[];
    const uint32_t smem_base = smem_u32(smw);
    const int m0 = blockIdx.y * 128;
    const int n0 = blockIdx.x * 64;
    const int z = blockIdx.z;
    const uint32_t* Ah = Xh + (size_t)z * Mrows * 1024;
    if (z == 0)
        gemm_body<3>(smw, smem_base, Ah, WqTh, bq, nullptr, Qh, m0, n0);
    else if (z == 1)
        gemm_body<1>(smw, smem_base, Ah, WkTh, bk, nullptr, Kh, m0, n0);
    else
        gemm_body<2>(smw, smem_base, Ah, WvTh, bv, nullptr, Vh, m0, n0);
}

__global__ __launch_bounds__(128, 4) void o_gemm_kernel(
    const uint32_t* __restrict__ Ah, const uint32_t* __restrict__ WTh,
    const float* __restrict__ bias, float* __restrict__ C)
{
    extern __shared__ uint32_t smw[];
    const uint32_t smem_base = smem_u32(smw);
    gemm_body<0>(smw, smem_base, Ah, WTh, bias, C, nullptr,
                 blockIdx.y * 128, blockIdx.x * 64);
}

// ---------------------------------------------------------------------------
// Tensor-core causal FA: kv-tile 128 (softmax passes halved).
// Q single fp16 plane (pre-scaled); QK = q*k (1 MMA); PV = p*v (1 MMA).
// ---------------------------------------------------------------------------
#define KROWW 72   // K row stride in words (64 used), 128 kv rows
#define VROWW 72   // V row stride in words (64 used = 128 kv), 128 d rows
#define FA_STAGE_WORDS (128 * KROWW + 128 * VROWW)   // 18432
#define FA_SMEM_BYTES (2 * FA_STAGE_WORDS * 4)       // 147456

__global__ __launch_bounds__(256, 1) void fa_tc_kernel(
    const uint32_t* __restrict__ QhG,
    const uint32_t* __restrict__ KhG, const uint32_t* __restrict__ VhG,
    uint32_t* __restrict__ OhG)
{
    extern __shared__ uint32_t su[];
    const uint32_t smem_base = smem_u32(su);

    const int qb = (int)gridDim.x - 1 - (int)blockIdx.x;
    const int h  = blockIdx.y;
    const int b  = blockIdx.z;
    const int t  = threadIdx.x;
    const int w  = t >> 5;
    const int lane = t & 31;
    const int g  = lane >> 2;
    const int t4 = lane & 3;
    const int q0 = qb * 128;

    const size_t bhS = (size_t)(b * Hh + h) * Sseq;
    const size_t bhD = (size_t)(b * Hh + h) * DKk;

    // Preload Q fragments (single plane, pre-scaled)
    uint32_t qh[8][4];
    {
        const size_t rg  = (bhS + q0 + w * 16 + g) * 64;
        const size_t rg8 = rg + 8 * 64;
        #pragma unroll
        for (int ks = 0; ks < 8; ks++) {
            const int wk = 8 * ks + 2 * t4;
            uint2 h0 = *(const uint2*)&QhG[rg + wk];
            uint2 h1 = *(const uint2*)&QhG[rg8 + wk];
            qh[ks][0] = h0.x; qh[ks][1] = h1.x; qh[ks][2] = h0.y; qh[ks][3] = h1.y;
        }
    }

    auto load_tile = [&](int stage, int kt) {
        const int kv0 = kt * 128;
        const uint32_t sb = smem_base + (uint32_t)stage * FA_STAGE_WORDS * 4;
        const uint32_t kB = sb;
        const uint32_t vB = sb + 128 * KROWW * 4;
        #pragma unroll
        for (int i = 0; i < 8; i++) {
            int u = t + i * 256;                 // 2048 chunks K (128 rows x 16)
            int row = u >> 4, w4 = (u & 15) * 4;
            CP_ASYNC16(kB + (uint32_t)(row * KROWW + w4) * 4,
                       KhG + (bhS + kv0 + row) * 64 + w4);
        }
        #pragma unroll
        for (int i = 0; i < 8; i++) {
            int u = t + i * 256;                 // 2048 chunks V (128 rows x 16)
            int row = u >> 4, w4 = (u & 15) * 4;
            CP_ASYNC16(vB + (uint32_t)(row * VROWW + w4) * 4,
                       VhG + (bhD + row) * 1024 + (kv0 >> 1) + w4);
        }
    };

    float oacc[16][4];
    #pragma unroll
    for (int nf = 0; nf < 16; nf++)
        #pragma unroll
        for (int r = 0; r < 4; r++) oacc[nf][r] = 0.f;

    float m0 = -1e30f, m1 = -1e30f, l0 = 0.f, l1 = 0.f;
    const int row0 = q0 + w * 16 + g;
    const int row1 = row0 + 8;

    const int ntiles = qb + 1;
    load_tile(0, 0);
    CP_COMMIT();

    for (int kt = 0; kt < ntiles; kt++) {
        const int st = kt & 1;
        const int kv0 = kt * 128;
        if (kt + 1 < ntiles) {
            load_tile(st ^ 1, kt + 1);
            CP_COMMIT();
            CP_WAIT(1);
        } else {
            CP_WAIT(0);
        }
        __syncthreads();

        const uint32_t* Ks = su + (size_t)st * FA_STAGE_WORDS;
        const uint32_t* Vs = Ks + 128 * KROWW;

        float acc[16][4];
        #pragma unroll
        for (int nf = 0; nf < 16; nf++)
            #pragma unroll
            for (int r = 0; r < 4; r++) acc[nf][r] = 0.f;

        #pragma unroll
        for (int ks = 0; ks < 8; ks++) {
            #pragma unroll
            for (int nf = 0; nf < 16; nf++) {
                const int r = (nf * 8 + g) * KROWW + 8 * ks + 2 * t4;
                uint2 kw = *(const uint2*)&Ks[r];
                mma_f16(acc[nf], qh[ks], kw.x, kw.y);
            }
        }

        // causal mask: only the diagonal tile (kt == qb)
        if (kt == qb) {
            #pragma unroll
            for (int nf = 0; nf < 16; nf++) {
                const int c = kv0 + nf * 8 + 2 * t4;
                if (c     > row0) acc[nf][0] = -1e30f;
                if (c + 1 > row0) acc[nf][1] = -1e30f;
                if (c     > row1) acc[nf][2] = -1e30f;
                if (c + 1 > row1) acc[nf][3] = -1e30f;
            }
        }

        float mx0 = -1e30f, mx1 = -1e30f;
        #pragma unroll
        for (int nf = 0; nf < 16; nf++) {
            mx0 = fmaxf(mx0, fmaxf(acc[nf][0], acc[nf][1]));
            mx1 = fmaxf(mx1, fmaxf(acc[nf][2], acc[nf][3]));
        }
        mx0 = fmaxf(mx0, __shfl_xor_sync(0xFFFFFFFFu, mx0, 1));
        mx0 = fmaxf(mx0, __shfl_xor_sync(0xFFFFFFFFu, mx0, 2));
        mx1 = fmaxf(mx1, __shfl_xor_sync(0xFFFFFFFFu, mx1, 1));
        mx1 = fmaxf(mx1, __shfl_xor_sync(0xFFFFFFFFu, mx1, 2));

        const float mn0 = fmaxf(m0, mx0);
        const float mn1 = fmaxf(m1, mx1);
        const float cr0 = ex2(m0 - mn0);
        const float cr1 = ex2(m1 - mn1);

        float ps0 = 0.f, ps1 = 0.f;
        #pragma unroll
        for (int nf = 0; nf < 16; nf++) {
            acc[nf][0] = ex2(acc[nf][0] - mn0);
            acc[nf][1] = ex2(acc[nf][1] - mn0);
            acc[nf][2] = ex2(acc[nf][2] - mn1);
            acc[nf][3] = ex2(acc[nf][3] - mn1);
            ps0 += acc[nf][0] + acc[nf][1];
            ps1 += acc[nf][2] + acc[nf][3];
        }
        ps0 += __shfl_xor_sync(0xFFFFFFFFu, ps0, 1);
        ps0 += __shfl_xor_sync(0xFFFFFFFFu, ps0, 2);
        ps1 += __shfl_xor_sync(0xFFFFFFFFu, ps1, 1);
        ps1 += __shfl_xor_sync(0xFFFFFFFFu, ps1, 2);

        l0 = l0 * cr0 + ps0;
        l1 = l1 * cr1 + ps1;
        m0 = mn0;
        m1 = mn1;

        #pragma unroll
        for (int nf = 0; nf < 16; nf++) {
            oacc[nf][0] *= cr0;
            oacc[nf][1] *= cr0;
            oacc[nf][2] *= cr1;
            oacc[nf][3] *= cr1;
        }

        // ---- P @ V over 128 kv (8 k16 chunks), P single fp16 ----
        #pragma unroll
        for (int ks2 = 0; ks2 < 8; ks2++) {
            uint32_t ph[4];
            ph[0] = packh(acc[2 * ks2][0],     acc[2 * ks2][1]);
            ph[1] = packh(acc[2 * ks2][2],     acc[2 * ks2][3]);
            ph[2] = packh(acc[2 * ks2 + 1][0], acc[2 * ks2 + 1][1]);
            ph[3] = packh(acc[2 * ks2 + 1][2], acc[2 * ks2 + 1][3]);
            #pragma unroll
            for (int nf = 0; nf < 16; nf++) {
                const int r = (nf * 8 + g) * VROWW + 8 * ks2 + 2 * t4;
                uint2 vw = *(const uint2*)&Vs[r];
                mma_f16(oacc[nf], ph, vw.x, vw.y);
            }
        }
        __syncthreads();
    }

    // epilogue: normalize, emit fp16 O plane (pair-permuted words)
    const float inv0 = 1.0f / l0;
    const float inv1 = 1.0f / l1;
    const size_t rowg  = (size_t)(b * Sseq + q0 + w * 16 + g) * 1024 + h * 64;
    const size_t rowg8 = rowg + 8 * 1024;
    #pragma unroll
    for (int nf = 0; nf < 16; nf++) {
        const int w_log = nf * 4 + t4;
        const int phys  = (w_log & ~7) + 2 * t4 + (nf & 1);
        OhG[rowg + phys]  = packh(oacc[nf][0] * inv0, oacc[nf][1] * inv0);
        OhG[rowg8 + phys] = packh(oacc[nf][2] * inv1, oacc[nf][3] * inv1);
    }
}

// ---------------------------------------------------------------------------
// kernel_launch
// ---------------------------------------------------------------------------
extern "C" void kernel_launch(void* const* d_in, const int* in_sizes, int n_in,
                              void* d_out, int out_size)
{
    const float* queries = (const float*)d_in[0];
    const float* keys    = (const float*)d_in[1];
    const float* values  = (const float*)d_in[2];
    const float* Wq      = (const float*)d_in[3];
    const float* bq      = (const float*)d_in[4];
    const float* Wlk     = (const float*)d_in[5];
    const float* blk     = (const float*)d_in[6];
    const float* Wlv     = (const float*)d_in[7];
    const float* blv     = (const float*)d_in[8];
    const float* Wkr     = (const float*)d_in[9];
    const float* bkr     = (const float*)d_in[10];
    const float* Wvr     = (const float*)d_in[11];
    const float* bvr     = (const float*)d_in[12];
    const float* Wo      = (const float*)d_in[13];
    const float* bo      = (const float*)d_in[14];
    float* out = (float*)d_out;

    float *bk, *bv;
    uint32_t *Xh, *Qh, *Kh, *Vh, *Oh;
    uint32_t *WqTh, *WkTh, *WvTh, *WoTh;
    cudaGetSymbolAddress((void**)&Xh,   g_Xh);
    cudaGetSymbolAddress((void**)&Qh,   g_Qh);
    cudaGetSymbolAddress((void**)&Kh,   g_Kh);
    cudaGetSymbolAddress((void**)&Vh,   g_Vh);
    cudaGetSymbolAddress((void**)&Oh,   g_Oh);
    cudaGetSymbolAddress((void**)&WqTh, g_WqTh);
    cudaGetSymbolAddress((void**)&WkTh, g_WkTh);
    cudaGetSymbolAddress((void**)&WvTh, g_WvTh);
    cudaGetSymbolAddress((void**)&WoTh, g_WoTh);
    cudaGetSymbolAddress((void**)&bk,   g_bk);
    cudaGetSymbolAddress((void**)&bv,   g_bv);

    cudaFuncSetAttribute(prep_kernel,
                         cudaFuncAttributeMaxDynamicSharedMemorySize, PREP_SMEM_BYTES);
    cudaFuncSetAttribute(qkv_gemm_kernel,
                         cudaFuncAttributeMaxDynamicSharedMemorySize, G_SMEM_BYTES);
    cudaFuncSetAttribute(o_gemm_kernel,
                         cudaFuncAttributeMaxDynamicSharedMemorySize, G_SMEM_BYTES);
    cudaFuncSetAttribute(fa_tc_kernel,
                         cudaFuncAttributeMaxDynamicSharedMemorySize, FA_SMEM_BYTES);

    // Unified preparation: cvt + transposeW + foldT + fold_b in one launch
    prep_kernel<<<PREP_BLOCKS, 256, PREP_SMEM_BYTES>>>(
        queries, keys, values, Xh,
        Wq, WqTh, Wo, WoTh,
        Wlk, Wkr, WkTh, Wlv, Wvr, WvTh,
        blk, bkr, bk, blv, bvr, bv);

    // Merged Q/K/V projections (CTA 128x64, 4 CTAs/SM)
    qkv_gemm_kernel<<<dim3(Dmod / 64, Mrows / 128, 3), 128, G_SMEM_BYTES>>>(
        Xh, WqTh, WkTh, WvTh, bq, bk, bv, Qh, Kh, Vh);

    // Fused causal attention (kv-tile 128)
    fa_tc_kernel<<<dim3(Sseq / 128, Hh, Bsz), 256, FA_SMEM_BYTES>>>(
        Qh, Kh, Vh, Oh);

    // Output projection
    o_gemm_kernel<<<dim3(Dmod / 64, Mrows / 128), 128, G_SMEM_BYTES>>>(
        Oh, WoTh, bo, out);
}